// round 13
// baseline (speedup 1.0000x reference)
#include <cuda_runtime.h>
#include <cuda_bf16.h>
#include <math.h>
#include <stdint.h>

#define D_    1024
#define DEPTH 8
#define H_    16
#define DH_   64
#define INNER 1024
#define NQ_   8
#define ED_   768
#define FF_   4096
#define TD_   320
#define BS_   32
#define N1_   1024
#define SCALE_ 0.125f
#define ADAW  32768

#define ACT_NONE 0
#define ACT_SILU 1
#define CM_STORE 0
#define CM_ATOM  1
#define CM_SPLIT 2

typedef __nv_bfloat16 bf;

// ---- fp32 scratch ----
__device__ float g_xp[BS_*N1_*D_];
__device__ float g_temb0[BS_*TD_];
__device__ float g_temb1[BS_*D_];
__device__ float g_temb[BS_*D_];
__device__ float g_stemb[BS_*D_];
__device__ float g_ada[BS_*ADAW];
__device__ float g_lat[BS_*NQ_*D_];
__device__ float g_att[BS_*NQ_*H_*N1_];
__device__ float g_hff[BS_*NQ_*D_];
__device__ float g_zacc[BS_*NQ_*(2*D_+FF_)];

// ---- bf16 hi/lo pairs ----
__device__ bf s_inxH[BS_*N1_*ED_],  s_inxL[BS_*N1_*ED_];
__device__ bf s_pinH[D_*ED_],       s_pinL[D_*ED_];
__device__ bf s_xnH[BS_*N1_*D_],    s_xnL[BS_*N1_*D_];
__device__ bf s_xnTH[BS_*D_*N1_],   s_xnTL[BS_*D_*N1_];
__device__ bf s_latnH[BS_*NQ_*D_],  s_latnL[BS_*NQ_*D_];
__device__ bf s_qH[BS_*NQ_*D_],     s_qL[BS_*NQ_*D_];
__device__ bf s_qpH[BS_*NQ_*H_*D_], s_qpL[BS_*NQ_*H_*D_];
__device__ bf s_attH[BS_*NQ_*H_*N1_], s_attL[BS_*NQ_*H_*N1_];
__device__ bf s_ovH[BS_*NQ_*H_*D_], s_ovL[BS_*NQ_*H_*D_];
__device__ bf s_voH[BS_*NQ_*D_],    s_voL[BS_*NQ_*D_];
__device__ bf s_hffH[BS_*NQ_*D_],   s_hffL[BS_*NQ_*D_];
__device__ bf s_h1H[BS_*NQ_*FF_],   s_h1L[BS_*NQ_*FF_];
__device__ bf s_latH[BS_*NQ_*D_],   s_latL[BS_*NQ_*D_];
__device__ bf s_stH[BS_*D_],        s_stL[BS_*D_];
__device__ bf s_wqH[DEPTH*INNER*D_],  s_wqL[DEPTH*INNER*D_];
__device__ bf s_kvH[DEPTH*D_*2*INNER],s_kvL[DEPTH*D_*2*INNER];
__device__ bf s_kvTH[DEPTH*2*INNER*D_],s_kvTL[DEPTH*2*INNER*D_];
__device__ bf s_woH[DEPTH*D_*INNER],  s_woL[DEPTH*D_*INNER];
__device__ bf s_f1H[DEPTH*FF_*D_],    s_f1L[DEPTH*FF_*D_];
__device__ bf s_f2H[DEPTH*D_*FF_],    s_f2L[DEPTH*D_*FF_];
__device__ bf s_awH[DEPTH*4*D_*D_],   s_awL[DEPTH*4*D_*D_];
__device__ bf s_poH[D_*D_],           s_poL[D_*D_];

// ---- helpers ----
__device__ __forceinline__ uint32_t smem_u32(const void* p){
    uint32_t a;
    asm("{ .reg .u64 t; cvta.to.shared.u64 t, %1; cvt.u32.u64 %0, t; }":"=r"(a):"l"(p));
    return a;
}
__device__ __forceinline__ void sp2(float v, bf& h, bf& l){
    h = __float2bfloat16_rn(v);
    l = __float2bfloat16_rn(v - __bfloat162float(h));
}
#define CPA(d,s) asm volatile("cp.async.cg.shared.global [%0],[%1],16;"::"r"(d),"l"(s):"memory")
#define CPC()    asm volatile("cp.async.commit_group;":::"memory")
#define CPW(n)   asm volatile("cp.async.wait_group %0;"::"n"(n):"memory")
#define LDSM4(r,a) asm volatile("ldmatrix.sync.aligned.m8n8.x4.shared.b16 {%0,%1,%2,%3},[%4];" \
    :"=r"((r)[0]),"=r"((r)[1]),"=r"((r)[2]),"=r"((r)[3]):"r"(a))
#define MMA(d,a,b) asm volatile("mma.sync.aligned.m16n8k16.row.col.f32.bf16.bf16.f32 " \
    "{%0,%1,%2,%3},{%4,%5,%6,%7},{%8,%9},{%0,%1,%2,%3};" \
    :"+f"((d)[0]),"+f"((d)[1]),"+f"((d)[2]),"+f"((d)[3]) \
    :"r"((a)[0]),"r"((a)[1]),"r"((a)[2]),"r"((a)[3]),"r"((b)[0]),"r"((b)[1]))

// ---- standard bf16 GEMM: BM=128 BN=128, 2 CTAs/SM (from R12, unchanged) ----
#define SMB 81920
template<int CMODE>
__global__ void __launch_bounds__(256,2) mgemm(
    int M,int N,int K,int ksplit,
    const bf* __restrict__ Ah,const bf* __restrict__ Al,int lda,long sAz,
    const bf* __restrict__ Bh,const bf* __restrict__ Bl,int ldb,long sBz,
    float* __restrict__ C, bf* __restrict__ CH, bf* __restrict__ CL, int ldc, long sCz,
    const float* __restrict__ bias, const float* __restrict__ cscale, float alpha)
{
    extern __shared__ bf sh[];
    const int t=threadIdx.x, lane=t&31, wid=t>>5;
    const int zz=blockIdx.z, batch=zz/ksplit, kp=zz-batch*ksplit;
    const int Kl=K/ksplit, koff=kp*Kl, NC=Kl>>5;
    const int bm=blockIdx.y*128, bn=blockIdx.x*128;
    const uint32_t sb = smem_u32(sh);
    const int mw=(wid>>2)*64, nw=(wid&3)*32;

    const bf* pAh[2]; const bf* pAl[2]; const bf* pBh[2]; const bf* pBl[2];
    uint32_t dst[2];
#pragma unroll
    for(int i=0;i<2;i++){
        int f=t+i*256, row=f>>2, ch=(f&3)*8;
        long ao=(long)batch*sAz + (long)(bm+row)*lda + koff + ch;
        pAh[i]=Ah+ao; pAl[i]=Al+ao;
        int rn=bn+row; if(rn>=N) rn=N-1;
        long bo=(long)batch*sBz + (long)rn*ldb + koff + ch;
        pBh[i]=Bh+bo; pBl[i]=Bl+bo;
        dst[i]=sb+(uint32_t)(row*40+ch)*2u;
    }

    float acc[4][4][4];
#pragma unroll
    for(int a=0;a<4;a++)
#pragma unroll
    for(int b=0;b<4;b++)
#pragma unroll
    for(int c=0;c<4;c++) acc[a][b][c]=0.f;

    auto fill=[&](int st){
        uint32_t so=(uint32_t)st*40960u;
#pragma unroll
        for(int i=0;i<2;i++){
            uint32_t d0=dst[i]+so;
            CPA(d0,       pAh[i]);
            CPA(d0+10240, pAl[i]);
            CPA(d0+20480, pBh[i]);
            CPA(d0+30720, pBl[i]);
            pAh[i]+=32; pAl[i]+=32; pBh[i]+=32; pBl[i]+=32;
        }
        CPC();
    };

    fill(0);
    for(int c=0;c<NC;c++){
        int st=c&1;
        CPW(0);
        __syncthreads();
        if(c+1<NC) fill(st^1);
        uint32_t base = sb + st*40960u;
#pragma unroll
        for(int ks=0;ks<2;ks++){
            uint32_t kadd = (uint32_t)(ks*32 + (lane>>4)*16);
            uint32_t Af[4][4], Bh2[4][2], Bl2[4][2];
#pragma unroll
            for(int mt=0;mt<4;mt++)
                LDSM4(Af[mt], base + (uint32_t)(mw+mt*16+(lane&15))*80u + kadd);
#pragma unroll
            for(int np=0;np<2;np++){
                uint32_t qq[4];
                LDSM4(qq, base+20480u + (uint32_t)(nw+np*16+(lane&15))*80u + kadd);
                Bh2[np*2][0]=qq[0]; Bh2[np*2][1]=qq[2];
                Bh2[np*2+1][0]=qq[1]; Bh2[np*2+1][1]=qq[3];
            }
#pragma unroll
            for(int mt=0;mt<4;mt++)
#pragma unroll
            for(int nt=0;nt<4;nt++) MMA(acc[mt][nt],Af[mt],Bh2[nt]);
#pragma unroll
            for(int np=0;np<2;np++){
                uint32_t qq[4];
                LDSM4(qq, base+30720u + (uint32_t)(nw+np*16+(lane&15))*80u + kadd);
                Bl2[np*2][0]=qq[0]; Bl2[np*2][1]=qq[2];
                Bl2[np*2+1][0]=qq[1]; Bl2[np*2+1][1]=qq[3];
            }
#pragma unroll
            for(int mt=0;mt<4;mt++)
#pragma unroll
            for(int nt=0;nt<4;nt++) MMA(acc[mt][nt],Af[mt],Bl2[nt]);
#pragma unroll
            for(int mt=0;mt<4;mt++)
                LDSM4(Af[mt], base+10240u + (uint32_t)(mw+mt*16+(lane&15))*80u + kadd);
#pragma unroll
            for(int mt=0;mt<4;mt++)
#pragma unroll
            for(int nt=0;nt<4;nt++) MMA(acc[mt][nt],Af[mt],Bh2[nt]);
        }
    }

    const bool dob = bias && (CMODE!=CM_ATOM || kp==0);
#pragma unroll
    for(int mt=0;mt<4;mt++)
#pragma unroll
    for(int nt=0;nt<4;nt++){
        int gc = bn+nw+nt*8+(lane&3)*2;
#pragma unroll
        for(int rr=0;rr<2;rr++){
            int gr = bm+mw+mt*16+(lane>>2)+rr*8;
            if(gr>=M) continue;
#pragma unroll
            for(int cc=0;cc<2;cc++){
                int c2=gc+cc;
                if(c2>=N) continue;
                float v = acc[mt][nt][rr*2+cc]*alpha;
                if(cscale) v *= cscale[c2];
                if(dob) v += bias[c2];
                long off=(long)batch*sCz + (long)gr*ldc + c2;
                if(CMODE==CM_ATOM) atomicAdd(&C[off],v);
                else if(CMODE==CM_STORE) C[off]=v;
                else { bf h,l; sp2(v,h,l); CH[off]=h; CL[off]=l; }
            }
        }
    }
}

// ---- WIDE bf16 GEMM: BM=128 BN=256, warp tile 64x64, 1 CTA/SM. M%128==0, N%256==0, no ksplit ----
#define WST 61440
#define WSMB (2*WST)
template<int CMODE>
__global__ void __launch_bounds__(256,1) mgemmB(
    int K,
    const bf* __restrict__ Ah,const bf* __restrict__ Al,int lda,long sAz,
    const bf* __restrict__ Bh,const bf* __restrict__ Bl,int ldb,long sBz,
    float* __restrict__ C, bf* __restrict__ CH, bf* __restrict__ CL, int ldc, long sCz,
    const float* __restrict__ bias, const float* __restrict__ cscale, float alpha)
{
    extern __shared__ bf sh[];
    const int t=threadIdx.x, lane=t&31, wid=t>>5;
    const int batch=blockIdx.z;
    const int bm=blockIdx.y*128, bn=blockIdx.x*256;
    const uint32_t sb = smem_u32(sh);
    const int mw=(wid>>2)*64, nw=(wid&3)*64;
    const int NC=K>>5;

    const bf* pAh[2]; const bf* pAl[2]; const bf* pBh[4]; const bf* pBl[4];
    uint32_t dA[2], dB[4];
#pragma unroll
    for(int i=0;i<2;i++){
        int f=t+i*256, row=f>>2, ch=(f&3)*8;
        long ao=(long)batch*sAz + (long)(bm+row)*lda + ch;
        pAh[i]=Ah+ao; pAl[i]=Al+ao;
        dA[i]=sb+(uint32_t)(row*80+(f&3)*16);
    }
#pragma unroll
    for(int i=0;i<4;i++){
        int f=t+i*256, row=f>>2, ch=(f&3)*8;
        long bo=(long)batch*sBz + (long)(bn+row)*ldb + ch;
        pBh[i]=Bh+bo; pBl[i]=Bl+bo;
        dB[i]=sb+(uint32_t)(row*80+(f&3)*16);
    }

    float acc[4][8][4];
#pragma unroll
    for(int a=0;a<4;a++)
#pragma unroll
    for(int b=0;b<8;b++)
#pragma unroll
    for(int c=0;c<4;c++) acc[a][b][c]=0.f;

    auto fill=[&](int st){
        uint32_t so=(uint32_t)st*(uint32_t)WST;
#pragma unroll
        for(int i=0;i<2;i++){
            CPA(dA[i]+so,        pAh[i]);
            CPA(dA[i]+so+10240u, pAl[i]);
            pAh[i]+=32; pAl[i]+=32;
        }
#pragma unroll
        for(int i=0;i<4;i++){
            CPA(dB[i]+so+20480u, pBh[i]);
            CPA(dB[i]+so+40960u, pBl[i]);
            pBh[i]+=32; pBl[i]+=32;
        }
        CPC();
    };

    fill(0);
    for(int c=0;c<NC;c++){
        int st=c&1;
        CPW(0);
        __syncthreads();
        if(c+1<NC) fill(st^1);
        uint32_t base = sb + st*(uint32_t)WST;
#pragma unroll
        for(int ks=0;ks<2;ks++){
            uint32_t kadd = (uint32_t)(ks*32 + (lane>>4)*16);
            uint32_t Af[4][4], Bh2[8][2], Bl2[8][2];
#pragma unroll
            for(int mt=0;mt<4;mt++)
                LDSM4(Af[mt], base + (uint32_t)(mw+mt*16+(lane&15))*80u + kadd);
#pragma unroll
            for(int np=0;np<4;np++){
                uint32_t qq[4];
                LDSM4(qq, base+20480u + (uint32_t)(nw+np*16+(lane&15))*80u + kadd);
                Bh2[np*2][0]=qq[0]; Bh2[np*2][1]=qq[2];
                Bh2[np*2+1][0]=qq[1]; Bh2[np*2+1][1]=qq[3];
            }
#pragma unroll
            for(int mt=0;mt<4;mt++)
#pragma unroll
            for(int nt=0;nt<8;nt++) MMA(acc[mt][nt],Af[mt],Bh2[nt]);
#pragma unroll
            for(int np=0;np<4;np++){
                uint32_t qq[4];
                LDSM4(qq, base+40960u + (uint32_t)(nw+np*16+(lane&15))*80u + kadd);
                Bl2[np*2][0]=qq[0]; Bl2[np*2][1]=qq[2];
                Bl2[np*2+1][0]=qq[1]; Bl2[np*2+1][1]=qq[3];
            }
#pragma unroll
            for(int mt=0;mt<4;mt++)
#pragma unroll
            for(int nt=0;nt<8;nt++) MMA(acc[mt][nt],Af[mt],Bl2[nt]);
#pragma unroll
            for(int mt=0;mt<4;mt++)
                LDSM4(Af[mt], base+10240u + (uint32_t)(mw+mt*16+(lane&15))*80u + kadd);
#pragma unroll
            for(int mt=0;mt<4;mt++)
#pragma unroll
            for(int nt=0;nt<8;nt++) MMA(acc[mt][nt],Af[mt],Bh2[nt]);
        }
    }

#pragma unroll
    for(int mt=0;mt<4;mt++)
#pragma unroll
    for(int nt=0;nt<8;nt++){
        int gc = bn+nw+nt*8+(lane&3)*2;
#pragma unroll
        for(int rr=0;rr<2;rr++){
            int gr = bm+mw+mt*16+(lane>>2)+rr*8;
#pragma unroll
            for(int cc=0;cc<2;cc++){
                int c2=gc+cc;
                float v = acc[mt][nt][rr*2+cc]*alpha;
                if(cscale) v *= cscale[c2];
                if(bias) v += bias[c2];
                long off=(long)batch*sCz + (long)gr*ldc + c2;
                if(CMODE==CM_STORE) C[off]=v;
                else { bf h,l; sp2(v,h,l); CH[off]=h; CL[off]=l; }
            }
        }
    }
}

// ---- BM=32 bf16 GEMM (M==32) ----
#define SM32S 25600
__global__ void __launch_bounds__(256,2) mgemm32(
    int N,int K,
    const bf* __restrict__ Ah,const bf* __restrict__ Al,int lda,
    const bf* __restrict__ Bh,const bf* __restrict__ Bl,int ldb,
    float* __restrict__ C,int ldc,const float* __restrict__ bias)
{
    extern __shared__ bf sh[];
    const int t=threadIdx.x, lane=t&31, wid=t>>5;
    const int bn=blockIdx.x*128;
    const uint32_t sb=smem_u32(sh);
    const int NC=K>>5;
    float acc[2][2][4];
#pragma unroll
    for(int a=0;a<2;a++)
#pragma unroll
    for(int b=0;b<2;b++)
#pragma unroll
    for(int c=0;c<4;c++) acc[a][b][c]=0.f;

    auto fill=[&](int st,int c){
        uint32_t bs=sb+(uint32_t)st*SM32S;
        {
            int row=(t&127)>>2, ch=(t&3)*8;
            const bf* Ap=(t<128)?Ah:Al;
            uint32_t off=(t<128)?0u:2560u;
            CPA(bs+off+(uint32_t)(row*80+ch*2), Ap+(long)row*lda+c*32+ch);
        }
#pragma unroll
        for(int i=0;i<2;i++){
            int f=t+i*256, row=f>>2, ch=(f&3)*8;
            int rn=bn+row; if(rn>=N) rn=N-1;
            long bo=(long)rn*ldb+c*32+ch;
            CPA(bs+5120u+(uint32_t)(row*80+ch*2), Bh+bo);
            CPA(bs+15360u+(uint32_t)(row*80+ch*2), Bl+bo);
        }
        CPC();
    };

    fill(0,0);
    for(int c=0;c<NC;c++){
        int st=c&1;
        CPW(0);
        __syncthreads();
        if(c+1<NC) fill(st^1,c+1);
        uint32_t base=sb+(uint32_t)st*SM32S;
#pragma unroll
        for(int ks=0;ks<2;ks++){
            uint32_t kadd=(uint32_t)(ks*32+(lane>>4)*16);
            uint32_t Af[2][4], Bf[2][2], Bl2[2][2];
#pragma unroll
            for(int mt=0;mt<2;mt++)
                LDSM4(Af[mt], base + (uint32_t)((mt*16+(lane&15))*80) + kadd);
            {
                uint32_t qq[4];
                LDSM4(qq, base+5120u + (uint32_t)((wid*16+(lane&15))*80) + kadd);
                Bf[0][0]=qq[0];Bf[0][1]=qq[2];Bf[1][0]=qq[1];Bf[1][1]=qq[3];
            }
#pragma unroll
            for(int mt=0;mt<2;mt++)
#pragma unroll
            for(int nt=0;nt<2;nt++) MMA(acc[mt][nt],Af[mt],Bf[nt]);
            {
                uint32_t qq[4];
                LDSM4(qq, base+15360u + (uint32_t)((wid*16+(lane&15))*80) + kadd);
                Bl2[0][0]=qq[0];Bl2[0][1]=qq[2];Bl2[1][0]=qq[1];Bl2[1][1]=qq[3];
            }
#pragma unroll
            for(int mt=0;mt<2;mt++)
#pragma unroll
            for(int nt=0;nt<2;nt++) MMA(acc[mt][nt],Af[mt],Bl2[nt]);
#pragma unroll
            for(int mt=0;mt<2;mt++)
                LDSM4(Af[mt], base+2560u + (uint32_t)((mt*16+(lane&15))*80) + kadd);
#pragma unroll
            for(int mt=0;mt<2;mt++)
#pragma unroll
            for(int nt=0;nt<2;nt++) MMA(acc[mt][nt],Af[mt],Bf[nt]);
        }
    }
#pragma unroll
    for(int mt=0;mt<2;mt++)
#pragma unroll
    for(int nt=0;nt<2;nt++){
        int gc=bn+wid*16+nt*8+(lane&3)*2;
#pragma unroll
        for(int rr=0;rr<2;rr++){
            int gr=mt*16+(lane>>2)+rr*8;
#pragma unroll
            for(int cc=0;cc<2;cc++){
                int c2=gc+cc;
                if(c2>=N) continue;
                float v=acc[mt][nt][rr*2+cc];
                if(bias) v+=bias[c2];
                C[(long)gr*ldc+c2]=v;
            }
        }
    }
}

// ---- unified prep ----
#define NSEG 10
struct Segs {
    const float* src[NSEG]; bf* dh[NSEG]; bf* dl[NSEG];
    int K[NSEG], N[NSEG], mode[NSEG];
    int bstart[NSEG+1]; int nseg;
};
__global__ void prep_all(Segs S)
{
    __shared__ float tile[32][33];
    int b=blockIdx.x;
    int si=0;
    while(si+1<S.nseg && b>=S.bstart[si+1]) si++;
    int lb=b-S.bstart[si];
    int tx=threadIdx.x, ty=threadIdx.y;
    if(S.mode[si]==0){
        int K=S.K[si], N=S.N[si];
        int tpz=(N/32)*(K/32);
        int z=lb/tpz, rem=lb-z*tpz;
        int n0=(rem%(N/32))*32, k0=(rem/(N/32))*32;
        long zo=(long)z*K*N;
        const float* Sp=S.src[si]+zo; bf* TH=S.dh[si]+zo; bf* TL=S.dl[si]+zo;
#pragma unroll
        for(int j=0;j<4;j++)
            tile[ty+j*8][tx]=Sp[(long)(k0+ty+j*8)*N+n0+tx];
        __syncthreads();
#pragma unroll
        for(int j=0;j<4;j++){
            int n=n0+ty+j*8, k=k0+tx;
            bf h,l; sp2(tile[tx][ty+j*8],h,l);
            TH[(long)n*K+k]=h; TL[(long)n*K+k]=l;
        }
    } else {
        long n=(long)S.K[si]*2048;
        long i0=(long)lb*2048 + ty*32+tx;
#pragma unroll
        for(int j=0;j<8;j++){
            long i=i0+j*256;
            if(i<n){ bf h,l; sp2(S.src[si][i],h,l); S.dh[si][i]=h; S.dl[si][i]=l; }
        }
    }
}

// ---- SIMT fp32 GEMM (temb only) ----
template<int ACT>
__global__ void __launch_bounds__(256) gemm_s(
    int M,int N,int K,
    const float* __restrict__ A,int lda,
    const float* __restrict__ B,int ldb,
    float* __restrict__ C,int ldc,
    const float* __restrict__ bias)
{
    __shared__ float As[16][68], Bs[16][68];
    int bm=blockIdx.y*64, bn=blockIdx.x*64, t=threadIdx.x;
    int tx=t&15, ty=t>>4;
    float acc[4][4];
#pragma unroll
    for(int i=0;i<4;i++)
#pragma unroll
    for(int j=0;j<4;j++) acc[i][j]=0.f;
    for(int k0=0;k0<K;k0+=16){
#pragma unroll
        for(int i=0;i<4;i++){
            int idx=t+i*256, r=idx>>4, kk=idx&15;
            As[kk][r] = (bm+r<M)? A[(long)(bm+r)*lda+k0+kk] : 0.f;
        }
#pragma unroll
        for(int i=0;i<4;i++){
            int idx=t+i*256, kk=idx>>6, cc=idx&63;
            Bs[kk][cc] = (bn+cc<N)? B[(long)(k0+kk)*ldb+bn+cc] : 0.f;
        }
        __syncthreads();
#pragma unroll
        for(int kk=0;kk<16;kk++){
            float ra[4],rb[4];
#pragma unroll
            for(int i=0;i<4;i++) ra[i]=As[kk][ty*4+i];
#pragma unroll
            for(int j=0;j<4;j++) rb[j]=Bs[kk][tx*4+j];
#pragma unroll
            for(int i=0;i<4;i++)
#pragma unroll
            for(int j=0;j<4;j++) acc[i][j]+=ra[i]*rb[j];
        }
        __syncthreads();
    }
#pragma unroll
    for(int i=0;i<4;i++){
        int gr=bm+ty*4+i; if(gr>=M) continue;
#pragma unroll
        for(int j=0;j<4;j++){
            int gc=bn+tx*4+j; if(gc>=N) continue;
            float v=acc[i][j];
            if(bias) v+=bias[gc];
            if(ACT==ACT_SILU) v=v/(1.f+expf(-v));
            C[(long)gr*ldc+gc]=v;
        }
    }
}

// ---- LayerNorm D=1024 -> split or fp32 ----
template<bool AFFINE,bool SPLIT>
__global__ void __launch_bounds__(256) ln_k(const float* __restrict__ x,
    float* __restrict__ y, bf* __restrict__ yH, bf* __restrict__ yL,
    const float* __restrict__ g, const float* __restrict__ b)
{
    long row=blockIdx.x; const float* xr=x+row*D_; int t=threadIdx.x;
    float v[4], s=0.f;
#pragma unroll
    for(int i=0;i<4;i++){ v[i]=xr[t+i*256]; s+=v[i]; }
    __shared__ float red[256];
    red[t]=s; __syncthreads();
    for(int o=128;o>0;o>>=1){ if(t<o) red[t]+=red[t+o]; __syncthreads(); }
    float m=red[0]*(1.f/D_); __syncthreads();
    float vs=0.f;
#pragma unroll
    for(int i=0;i<4;i++){ float d=v[i]-m; vs+=d*d; }
    red[t]=vs; __syncthreads();
    for(int o=128;o>0;o>>=1){ if(t<o) red[t]+=red[t+o]; __syncthreads(); }
    float rs=1.f/sqrtf(red[0]*(1.f/D_)+1e-5f);
#pragma unroll
    for(int i=0;i<4;i++){
        int c=t+i*256; float o=(v[i]-m)*rs;
        if(AFFINE) o=o*g[c]+b[c];
        if(SPLIT){ bf h,l; sp2(o,h,l); yH[row*D_+c]=h; yL[row*D_+c]=l; }
        else y[row*D_+c]=o;
    }
}

// ---- softmax 1024 -> split ----
__global__ void __launch_bounds__(256) softmax_k(const float* __restrict__ x,
    bf* __restrict__ pH, bf* __restrict__ pL)
{
    long row=blockIdx.x; const float* p=x+row*N1_; int t=threadIdx.x;
    float v[4], mx=-1e30f;
#pragma unroll
    for(int i=0;i<4;i++){ v[i]=p[t+i*256]; mx=fmaxf(mx,v[i]); }
    __shared__ float red[256];
    red[t]=mx; __syncthreads();
    for(int o=128;o>0;o>>=1){ if(t<o) red[t]=fmaxf(red[t],red[t+o]); __syncthreads(); }
    mx=red[0]; __syncthreads();
    float s=0.f;
#pragma unroll
    for(int i=0;i<4;i++){ v[i]=expf(v[i]-mx); s+=v[i]; }
    red[t]=s; __syncthreads();
    for(int o=128;o>0;o>>=1){ if(t<o) red[t]+=red[t+o]; __syncthreads(); }
    float inv=1.f/red[0];
#pragma unroll
    for(int i=0;i<4;i++){
        int c=t+i*256; bf h,l; sp2(v[i]*inv,h,l);
        pH[row*N1_+c]=h; pL[row*N1_+c]=l;
    }
}

// ---- split / gelu-split ----
__global__ void split_k(const float* __restrict__ s, bf* __restrict__ h, bf* __restrict__ l, int n)
{
    int i=blockIdx.x*blockDim.x+threadIdx.x;
    if(i>=n) return;
    bf hh,ll; sp2(s[i],hh,ll); h[i]=hh; l[i]=ll;
}
__global__ void gsplit_k(const float* __restrict__ s, bf* __restrict__ h, bf* __restrict__ l, int n)
{
    int i=blockIdx.x*blockDim.x+threadIdx.x;
    if(i>=n) return;
    float v=s[i];
    v = 0.5f*v*(1.f+erff(v*0.70710678118654752f));
    bf hh,ll; sp2(v,hh,ll); h[i]=hh; l[i]=ll;
}

// ---- transpose bf16 pairs [R][C] -> [C][R], z-batched ----
__global__ void btransp(const bf* __restrict__ ih,const bf* __restrict__ il,
                        bf* __restrict__ oh, bf* __restrict__ ol,int R,int C)
{
    __shared__ bf th[32][33], tl[32][33];
    long zo=(long)blockIdx.z*R*C;
    int c0=blockIdx.x*32, r0=blockIdx.y*32;
    int tx=threadIdx.x, ty=threadIdx.y;
#pragma unroll
    for(int j=0;j<4;j++){
        int r=r0+ty+j*8;
        th[ty+j*8][tx]=ih[zo+(long)r*C+c0+tx];
        tl[ty+j*8][tx]=il[zo+(long)r*C+c0+tx];
    }
    __syncthreads();
#pragma unroll
    for(int j=0;j<4;j++){
        int c=c0+ty+j*8, r=r0+tx;
        oh[zo+(long)c*R+r]=th[tx][ty+j*8];
        ol[zo+(long)c*R+r]=tl[tx][ty+j*8];
    }
}

// ---- misc ----
__global__ void timestep_k(const float* __restrict__ ts, float* __restrict__ out){
    int b=blockIdx.x,i=threadIdx.x;
    int j=(i<160)?i:(i-160);
    float f=expf(-logf(10000.f)*(float)j/160.f);
    double a=(double)(ts[b]*f);
    out[b*TD_+i]=(i<160)?(float)cos(a):(float)sin(a);
}
__global__ void silu_split_k(const float* __restrict__ x,float* __restrict__ y,
                             bf* __restrict__ yH,bf* __restrict__ yL,int n){
    int i=blockIdx.x*blockDim.x+threadIdx.x;
    if(i<n){ float v=x[i]; v=v/(1.f+expf(-v)); y[i]=v;
        bf h,l; sp2(v,h,l); yH[i]=h; yL[i]=l; }
}
__global__ void bcast_k(const float* __restrict__ s,float* __restrict__ d,int n,int per){
    int i=blockIdx.x*blockDim.x+threadIdx.x;
    if(i<n) d[i]=s[i%per];
}
__global__ void modulate_k(const float* __restrict__ q,const float* __restrict__ ada,int loff,
                           bf* __restrict__ qH,bf* __restrict__ qL){
    int i=blockIdx.x*blockDim.x+threadIdx.x;
    if(i>=BS_*NQ_*D_) return;
    int b=i/(NQ_*D_), c=i&(D_-1);
    const float* ap=ada+(long)b*ADAW+loff;
    float v=q[i]*(1.f+ap[2*D_+c])+ap[c];
    bf h,l; sp2(v,h,l); qH[i]=h; qL[i]=l;
}

// ---- host ----
#define GSA(p,s) cudaGetSymbolAddress((void**)&p,s)
static inline dim3 tg(int M,int N,int z){ return dim3((unsigned)((N+127)/128),(unsigned)((M+127)/128),(unsigned)z); }
static bf* NB_=nullptr;

extern "C" void kernel_launch(void* const* d_in, const int* in_sizes, int n_in,
                              void* d_out, int out_size)
{
    const float *in_x=(const float*)d_in[0], *in_ts=(const float*)d_in[1], *in_lat=(const float*)d_in[2];
    const float *te_w1=(const float*)d_in[3], *te_b1=(const float*)d_in[4];
    const float *te_w2=(const float*)d_in[5], *te_b2=(const float*)d_in[6];
    const float *pin_w=(const float*)d_in[7], *pin_b=(const float*)d_in[8];
    const float *ln1_g=(const float*)d_in[9], *ln1_b=(const float*)d_in[10];
    const float *ln2_g=(const float*)d_in[11], *ln2_b=(const float*)d_in[12];
    const float *wq=(const float*)d_in[13], *wkv=(const float*)d_in[14], *wo=(const float*)d_in[15];
    const float *flg=(const float*)d_in[16], *flb=(const float*)d_in[17];
    const float *fw1=(const float*)d_in[18], *fw2=(const float*)d_in[19];
    const float *aw=(const float*)d_in[20], *ab=(const float*)d_in[21];
    const float *pout_w=(const float*)d_in[22], *pout_b=(const float*)d_in[23];
    const float *ng=(const float*)d_in[24], *nb=(const float*)d_in[25];
    float* out=(float*)d_out;

    cudaFuncSetAttribute(mgemm<CM_STORE>,cudaFuncAttributeMaxDynamicSharedMemorySize,SMB);
    cudaFuncSetAttribute(mgemm<CM_ATOM>, cudaFuncAttributeMaxDynamicSharedMemorySize,SMB);
    cudaFuncSetAttribute(mgemm<CM_SPLIT>,cudaFuncAttributeMaxDynamicSharedMemorySize,SMB);
    cudaFuncSetAttribute(mgemmB<CM_STORE>,cudaFuncAttributeMaxDynamicSharedMemorySize,WSMB);
    cudaFuncSetAttribute(mgemmB<CM_SPLIT>,cudaFuncAttributeMaxDynamicSharedMemorySize,WSMB);
    cudaFuncSetAttribute(mgemm32,cudaFuncAttributeMaxDynamicSharedMemorySize,2*SM32S);

    float *xp,*temb0,*temb1,*temb,*stemb,*ada,*lat,*att,*hff,*zacc;
    GSA(xp,g_xp); GSA(temb0,g_temb0); GSA(temb1,g_temb1); GSA(temb,g_temb);
    GSA(stemb,g_stemb); GSA(ada,g_ada); GSA(lat,g_lat);
    GSA(att,g_att); GSA(hff,g_hff); GSA(zacc,g_zacc);
    float* q    = zacc;
    float* vout = zacc + (long)BS_*NQ_*D_;
    float* h1   = zacc + (long)2*BS_*NQ_*D_;
    bf *inxH,*inxL,*pinH,*pinL,*xnH,*xnL,*xnTH,*xnTL,*latnH,*latnL,*qH,*qL,*qpH,*qpL;
    bf *attH,*attL,*ovH,*ovL,*voH,*voL,*hffH,*hffL,*h1H,*h1L,*latH,*latL,*stH,*stL;
    bf *wqH,*wqL,*kvH,*kvL,*kvTH,*kvTL,*woH,*woL,*f1H,*f1L,*f2H,*f2L,*awH,*awL,*poH,*poL;
    GSA(inxH,s_inxH); GSA(inxL,s_inxL); GSA(pinH,s_pinH); GSA(pinL,s_pinL);
    GSA(xnH,s_xnH); GSA(xnL,s_xnL); GSA(xnTH,s_xnTH); GSA(xnTL,s_xnTL);
    GSA(latnH,s_latnH); GSA(latnL,s_latnL); GSA(qH,s_qH); GSA(qL,s_qL);
    GSA(qpH,s_qpH); GSA(qpL,s_qpL); GSA(attH,s_attH); GSA(attL,s_attL);
    GSA(ovH,s_ovH); GSA(ovL,s_ovL); GSA(voH,s_voH); GSA(voL,s_voL);
    GSA(hffH,s_hffH); GSA(hffL,s_hffL); GSA(h1H,s_h1H); GSA(h1L,s_h1L);
    GSA(latH,s_latH); GSA(latL,s_latL); GSA(stH,s_stH); GSA(stL,s_stL);
    GSA(wqH,s_wqH); GSA(wqL,s_wqL); GSA(kvH,s_kvH); GSA(kvL,s_kvL);
    GSA(kvTH,s_kvTH); GSA(kvTL,s_kvTL); GSA(woH,s_woH); GSA(woL,s_woL);
    GSA(f1H,s_f1H); GSA(f1L,s_f1L); GSA(f2H,s_f2H); GSA(f2L,s_f2L);
    GSA(awH,s_awH); GSA(awL,s_awL); GSA(poH,s_poH); GSA(poL,s_poL);

    // launch 0: ALL prep in one kernel
    Segs S; int nbk=0; int si=0;
    auto addT=[&](const float* s, bf* h, bf* l, int K,int N,int z){
        S.src[si]=s;S.dh[si]=h;S.dl[si]=l;S.K[si]=K;S.N[si]=N;S.mode[si]=0;
        S.bstart[si]=nbk; nbk+=(N/32)*(K/32)*z; si++;
    };
    auto addS2=[&](const float* s, bf* h, bf* l, long n){
        S.src[si]=s;S.dh[si]=h;S.dl[si]=l;S.K[si]=(int)(n/2048);S.N[si]=1;S.mode[si]=1;
        S.bstart[si]=nbk; nbk+=(int)(n/2048); si++;
    };
    addT(pin_w,pinH,pinL,ED_,D_,1);
    addT(wq,wqH,wqL,D_,INNER,DEPTH);
    addT(wkv,kvTH,kvTL,D_,2*INNER,DEPTH);
    addT(wo,woH,woL,INNER,D_,DEPTH);
    addT(fw1,f1H,f1L,D_,FF_,DEPTH);
    addT(fw2,f2H,f2L,FF_,D_,DEPTH);
    addT(aw,awH,awL,D_,4*D_,DEPTH);
    addT(pout_w,poH,poL,D_,D_,1);
    addS2(wkv,kvH,kvL,(long)DEPTH*D_*2*INNER);
    addS2(in_x,inxH,inxL,(long)BS_*N1_*ED_);
    S.nseg=si; S.bstart[si]=nbk;
    prep_all<<<nbk,dim3(32,8)>>>(S);

    // launches 1,2: timestep chain start
    timestep_k<<<BS_,TD_>>>(in_ts,temb0);
    gemm_s<ACT_SILU><<<dim3(16,1),256>>>(BS_,D_,TD_,temb0,TD_,te_w1,D_,temb1,D_,te_b1);

    // launch 3: proj_in via WIDE kernel (process idx 5 -> ncu profiles mgemmB)
    mgemmB<CM_STORE><<<dim3(D_/256,(BS_*N1_)/128,1),256,WSMB>>>(
        ED_, inxH,inxL,ED_,0, pinH,pinL,ED_,0,
        xp,NB_,NB_,D_,0, pin_b,nullptr,1.f);

    gemm_s<ACT_NONE><<<dim3(16,1),256>>>(BS_,D_,D_,temb1,D_,te_w2,D_,temb,D_,te_b2);
    silu_split_k<<<(BS_*D_+255)/256,256>>>(temb,stemb,stH,stL,BS_*D_);

    // batched adaLN for ALL layers (BM=32)
    mgemm32<<<ADAW/128,256,2*SM32S>>>(ADAW,D_, stH,stL,D_, awH,awL,D_, ada,ADAW, ab);

    ln_k<false,true><<<BS_*N1_,256>>>(xp,nullptr,xnH,xnL,nullptr,nullptr);
    btransp<<<dim3(D_/32,N1_/32,BS_),dim3(32,8)>>>(xnH,xnL,xnTH,xnTL,N1_,D_);
    bcast_k<<<(BS_*NQ_*D_+255)/256,256>>>(in_lat,lat,BS_*NQ_*D_,NQ_*D_);

    for(int l=0;l<DEPTH;l++){
        const float *g1=ln1_g+l*D_, *b1=ln1_b+l*D_, *g2=ln2_g+l*D_, *b2=ln2_b+l*D_;
        const float *fg=flg+l*D_, *fb=flb+l*D_;
        const bf *wqh=wqH+(long)l*INNER*D_, *wql=wqL+(long)l*INNER*D_;
        const bf *kvh=kvH+(long)l*D_*2*INNER, *kvl=kvL+(long)l*D_*2*INNER;
        const bf *kvth=kvTH+(long)l*2*INNER*D_, *kvtl=kvTL+(long)l*2*INNER*D_;
        const bf *woh=woH+(long)l*D_*INNER, *wol=woL+(long)l*D_*INNER;
        const bf *f1h=f1H+(long)l*FF_*D_, *f1l=f1L+(long)l*FF_*D_;
        const bf *f2h=f2H+(long)l*D_*FF_, *f2l=f2L+(long)l*D_*FF_;

        cudaMemsetAsync(zacc,0,(size_t)BS_*NQ_*(2*D_+FF_)*sizeof(float),0);

        // latn -> q (split-K=16) -> modulate+split
        ln_k<true,true><<<BS_*NQ_,256>>>(lat,nullptr,latnH,latnL,g2,b2);
        mgemm<CM_ATOM><<<tg(BS_*NQ_,INNER,16),256,SMB>>>(
            BS_*NQ_,INNER,D_,16, latnH,latnL,D_,0, wqh,wql,D_,0,
            q,NB_,NB_,INNER,0, nullptr,nullptr,1.f);
        modulate_k<<<(BS_*NQ_*D_+255)/256,256>>>(q,ada,l*4*D_,qH,qL);

        // qp(split out, ⊙g1) = SCALE * qmod_h @ wk_h^T (z=heads)
        mgemm<CM_SPLIT><<<tg(BS_*NQ_,D_,H_),256,SMB>>>(
            BS_*NQ_,D_,DH_,1, qH,qL,INNER,64, kvh,kvl,2*INNER,64,
            nullptr,qpH,qpL,H_*D_,(long)D_, nullptr,g1,SCALE_);

        // logits = qp' @ xn^T (WIDE kernel, z=batch)
        mgemmB<CM_STORE><<<dim3(N1_/256,1,BS_),256,WSMB>>>(
            D_, qpH,qpL,D_,(long)NQ_*H_*D_, xnH,xnL,D_,(long)N1_*D_,
            att,NB_,NB_,N1_,(long)NQ_*H_*N1_, nullptr,nullptr,1.f);
        softmax_k<<<BS_*NQ_*H_,256>>>(att,attH,attL);

        // ov(split out, g1*x+b1) = attn @ xn (WIDE kernel, z=batch, via xnT)
        mgemmB<CM_SPLIT><<<dim3(D_/256,1,BS_),256,WSMB>>>(
            N1_, attH,attL,N1_,(long)NQ_*H_*N1_, xnTH,xnTL,N1_,(long)D_*N1_,
            nullptr,ovH,ovL,D_,(long)NQ_*H_*D_, b1,g1,1.f);

        // vout = ovm_h @ wv_h (z=heads, split-K=8)
        mgemm<CM_ATOM><<<tg(BS_*NQ_,DH_,H_*8),256,SMB>>>(
            BS_*NQ_,DH_,D_,8, ovH,ovL,H_*D_,(long)D_, kvth+(long)INNER*D_,kvtl+(long)INNER*D_,D_,(long)64*D_,
            vout,NB_,NB_,D_,64, nullptr,nullptr,1.f);
        split_k<<<(BS_*NQ_*D_+255)/256,256>>>(vout,voH,voL,BS_*NQ_*D_);

        // lat += vout @ wo (split-K=16)
        mgemm<CM_ATOM><<<tg(BS_*NQ_,D_,16),256,SMB>>>(
            BS_*NQ_,D_,INNER,16, voH,voL,INNER,0, woh,wol,INNER,0,
            lat,NB_,NB_,D_,0, nullptr,nullptr,1.f);

        // FF: h1 raw (split-K=4) -> GELU+split -> ff2 (split-K=16)
        ln_k<true,true><<<BS_*NQ_,256>>>(lat,nullptr,hffH,hffL,fg,fb);
        mgemm<CM_ATOM><<<tg(BS_*NQ_,FF_,4),256,SMB>>>(
            BS_*NQ_,FF_,D_,4, hffH,hffL,D_,0, f1h,f1l,D_,0,
            h1,NB_,NB_,FF_,0, nullptr,nullptr,1.f);
        gsplit_k<<<(BS_*NQ_*FF_+255)/256,256>>>(h1,h1H,h1L,BS_*NQ_*FF_);
        mgemm<CM_ATOM><<<tg(BS_*NQ_,D_,16),256,SMB>>>(
            BS_*NQ_,D_,FF_,16, h1H,h1L,FF_,0, f2h,f2l,FF_,0,
            lat,NB_,NB_,D_,0, nullptr,nullptr,1.f);
    }

    // ---- proj_out (split-K=16) + final LN ----
    split_k<<<(BS_*NQ_*D_+255)/256,256>>>(lat,latH,latL,BS_*NQ_*D_);
    cudaMemsetAsync(hff,0,(size_t)BS_*NQ_*D_*sizeof(float),0);
    mgemm<CM_ATOM><<<tg(BS_*NQ_,D_,16),256,SMB>>>(
        BS_*NQ_,D_,D_,16, latH,latL,D_,0, poH,poL,D_,0,
        hff,NB_,NB_,D_,0, pout_b,nullptr,1.f);
    ln_k<true,false><<<BS_*NQ_,256>>>(hff,out,nullptr,nullptr,ng,nb);
}

// round 14
// speedup vs baseline: 1.0984x; 1.0984x over previous
#include <cuda_runtime.h>
#include <cuda_bf16.h>
#include <math.h>
#include <stdint.h>

#define D_    1024
#define DEPTH 8
#define H_    16
#define DH_   64
#define INNER 1024
#define NQ_   8
#define ED_   768
#define FF_   4096
#define TD_   320
#define BS_   32
#define N1_   1024
#define SCALE_ 0.125f
#define ADAW  32768

#define ACT_NONE 0
#define ACT_SILU 1
#define CM_STORE 0
#define CM_ATOM  1
#define CM_SPLIT 2

typedef __nv_bfloat16 bf;

// ---- fp32 scratch ----
__device__ float g_xp[BS_*N1_*D_];
__device__ float g_temb0[BS_*TD_];
__device__ float g_temb1[BS_*D_];
__device__ float g_temb[BS_*D_];
__device__ float g_stemb[BS_*D_];
__device__ float g_ada[BS_*ADAW];
__device__ float g_lat[BS_*NQ_*D_];
__device__ float g_att[BS_*NQ_*H_*N1_];
__device__ float g_hff[BS_*NQ_*D_];
__device__ float g_zacc[BS_*NQ_*(2*D_+FF_)];

// ---- bf16 hi/lo pairs ----
__device__ bf s_inxH[BS_*N1_*ED_],  s_inxL[BS_*N1_*ED_];
__device__ bf s_pinH[D_*ED_],       s_pinL[D_*ED_];
__device__ bf s_xnH[BS_*N1_*D_],    s_xnL[BS_*N1_*D_];
__device__ bf s_xnTH[BS_*D_*N1_],   s_xnTL[BS_*D_*N1_];
__device__ bf s_latnH[BS_*NQ_*D_],  s_latnL[BS_*NQ_*D_];
__device__ bf s_qH[BS_*NQ_*D_],     s_qL[BS_*NQ_*D_];
__device__ bf s_qpH[BS_*NQ_*H_*D_], s_qpL[BS_*NQ_*H_*D_];
__device__ bf s_attH[BS_*NQ_*H_*N1_], s_attL[BS_*NQ_*H_*N1_];
__device__ bf s_ovH[BS_*NQ_*H_*D_], s_ovL[BS_*NQ_*H_*D_];
__device__ bf s_voH[BS_*NQ_*D_],    s_voL[BS_*NQ_*D_];
__device__ bf s_hffH[BS_*NQ_*D_],   s_hffL[BS_*NQ_*D_];
__device__ bf s_h1H[BS_*NQ_*FF_],   s_h1L[BS_*NQ_*FF_];
__device__ bf s_latH[BS_*NQ_*D_],   s_latL[BS_*NQ_*D_];
__device__ bf s_stH[BS_*D_],        s_stL[BS_*D_];
__device__ bf s_wqH[DEPTH*INNER*D_],  s_wqL[DEPTH*INNER*D_];
__device__ bf s_kvH[DEPTH*D_*2*INNER],s_kvL[DEPTH*D_*2*INNER];
__device__ bf s_kvTH[DEPTH*2*INNER*D_],s_kvTL[DEPTH*2*INNER*D_];
__device__ bf s_woH[DEPTH*D_*INNER],  s_woL[DEPTH*D_*INNER];
__device__ bf s_f1H[DEPTH*FF_*D_],    s_f1L[DEPTH*FF_*D_];
__device__ bf s_f2H[DEPTH*D_*FF_],    s_f2L[DEPTH*D_*FF_];
__device__ bf s_awH[DEPTH*4*D_*D_],   s_awL[DEPTH*4*D_*D_];
__device__ bf s_poH[D_*D_],           s_poL[D_*D_];

// ---- helpers ----
__device__ __forceinline__ uint32_t smem_u32(const void* p){
    uint32_t a;
    asm("{ .reg .u64 t; cvta.to.shared.u64 t, %1; cvt.u32.u64 %0, t; }":"=r"(a):"l"(p));
    return a;
}
__device__ __forceinline__ void sp2(float v, bf& h, bf& l){
    h = __float2bfloat16_rn(v);
    l = __float2bfloat16_rn(v - __bfloat162float(h));
}
#define CPA(d,s) asm volatile("cp.async.cg.shared.global [%0],[%1],16;"::"r"(d),"l"(s):"memory")
#define CPC()    asm volatile("cp.async.commit_group;":::"memory")
#define CPW(n)   asm volatile("cp.async.wait_group %0;"::"n"(n):"memory")
#define LDSM4(r,a) asm volatile("ldmatrix.sync.aligned.m8n8.x4.shared.b16 {%0,%1,%2,%3},[%4];" \
    :"=r"((r)[0]),"=r"((r)[1]),"=r"((r)[2]),"=r"((r)[3]):"r"(a))
#define MMA(d,a,b) asm volatile("mma.sync.aligned.m16n8k16.row.col.f32.bf16.bf16.f32 " \
    "{%0,%1,%2,%3},{%4,%5,%6,%7},{%8,%9},{%0,%1,%2,%3};" \
    :"+f"((d)[0]),"+f"((d)[1]),"+f"((d)[2]),"+f"((d)[3]) \
    :"r"((a)[0]),"r"((a)[1]),"r"((a)[2]),"r"((a)[3]),"r"((b)[0]),"r"((b)[1]))

// ---- bf16 tensor GEMM: C = A@B^T; NPASS=3: AhBh+AhBl+AlBh, NPASS=2: AhBh+AlBh (B rounded) ----
#define SMB 81920
template<int CMODE,int NPASS>
__global__ void __launch_bounds__(256,2) mgemm(
    int M,int N,int K,int ksplit,
    const bf* __restrict__ Ah,const bf* __restrict__ Al,int lda,long sAz,
    const bf* __restrict__ Bh,const bf* __restrict__ Bl,int ldb,long sBz,
    float* __restrict__ C, bf* __restrict__ CH, bf* __restrict__ CL, int ldc, long sCz,
    const float* __restrict__ bias, const float* __restrict__ cscale, float alpha)
{
    extern __shared__ bf sh[];
    const int t=threadIdx.x, lane=t&31, wid=t>>5;
    const int zz=blockIdx.z, batch=zz/ksplit, kp=zz-batch*ksplit;
    const int Kl=K/ksplit, koff=kp*Kl, NC=Kl>>5;
    const int bm=blockIdx.y*128, bn=blockIdx.x*128;
    const uint32_t sb = smem_u32(sh);
    const int mw=(wid>>2)*64, nw=(wid&3)*32;

    const bf* pAh[2]; const bf* pAl[2]; const bf* pBh[2]; const bf* pBl[2];
    uint32_t dst[2];
#pragma unroll
    for(int i=0;i<2;i++){
        int f=t+i*256, row=f>>2, ch=(f&3)*8;
        long ao=(long)batch*sAz + (long)(bm+row)*lda + koff + ch;
        pAh[i]=Ah+ao; pAl[i]=Al+ao;
        int rn=bn+row; if(rn>=N) rn=N-1;
        long bo=(long)batch*sBz + (long)rn*ldb + koff + ch;
        pBh[i]=Bh+bo; pBl[i]=Bl+bo;
        dst[i]=sb+(uint32_t)(row*40+ch)*2u;
    }

    float acc[4][4][4];
#pragma unroll
    for(int a=0;a<4;a++)
#pragma unroll
    for(int b=0;b<4;b++)
#pragma unroll
    for(int c=0;c<4;c++) acc[a][b][c]=0.f;

    auto fill=[&](int st){
        uint32_t so=(uint32_t)st*40960u;
#pragma unroll
        for(int i=0;i<2;i++){
            uint32_t d0=dst[i]+so;
            CPA(d0,       pAh[i]);
            CPA(d0+10240, pAl[i]);
            CPA(d0+20480, pBh[i]);
            if(NPASS==3) CPA(d0+30720, pBl[i]);
            pAh[i]+=32; pAl[i]+=32; pBh[i]+=32;
            if(NPASS==3) pBl[i]+=32;
        }
        CPC();
    };

    fill(0);
    for(int c=0;c<NC;c++){
        int st=c&1;
        CPW(0);
        __syncthreads();
        if(c+1<NC) fill(st^1);
        uint32_t base = sb + st*40960u;
#pragma unroll
        for(int ks=0;ks<2;ks++){
            uint32_t kadd = (uint32_t)(ks*32 + (lane>>4)*16);
            uint32_t Af[4][4], Bh2[4][2];
#pragma unroll
            for(int mt=0;mt<4;mt++)
                LDSM4(Af[mt], base + (uint32_t)(mw+mt*16+(lane&15))*80u + kadd);
#pragma unroll
            for(int np=0;np<2;np++){
                uint32_t qq[4];
                LDSM4(qq, base+20480u + (uint32_t)(nw+np*16+(lane&15))*80u + kadd);
                Bh2[np*2][0]=qq[0]; Bh2[np*2][1]=qq[2];
                Bh2[np*2+1][0]=qq[1]; Bh2[np*2+1][1]=qq[3];
            }
#pragma unroll
            for(int mt=0;mt<4;mt++)
#pragma unroll
            for(int nt=0;nt<4;nt++) MMA(acc[mt][nt],Af[mt],Bh2[nt]);
            if(NPASS==3){
                uint32_t Bl2[4][2];
#pragma unroll
                for(int np=0;np<2;np++){
                    uint32_t qq[4];
                    LDSM4(qq, base+30720u + (uint32_t)(nw+np*16+(lane&15))*80u + kadd);
                    Bl2[np*2][0]=qq[0]; Bl2[np*2][1]=qq[2];
                    Bl2[np*2+1][0]=qq[1]; Bl2[np*2+1][1]=qq[3];
                }
#pragma unroll
                for(int mt=0;mt<4;mt++)
#pragma unroll
                for(int nt=0;nt<4;nt++) MMA(acc[mt][nt],Af[mt],Bl2[nt]);
            }
#pragma unroll
            for(int mt=0;mt<4;mt++)
                LDSM4(Af[mt], base+10240u + (uint32_t)(mw+mt*16+(lane&15))*80u + kadd);
#pragma unroll
            for(int mt=0;mt<4;mt++)
#pragma unroll
            for(int nt=0;nt<4;nt++) MMA(acc[mt][nt],Af[mt],Bh2[nt]);
        }
    }

    const bool dob = bias && (CMODE!=CM_ATOM || kp==0);
#pragma unroll
    for(int mt=0;mt<4;mt++)
#pragma unroll
    for(int nt=0;nt<4;nt++){
        int gc = bn+nw+nt*8+(lane&3)*2;
#pragma unroll
        for(int rr=0;rr<2;rr++){
            int gr = bm+mw+mt*16+(lane>>2)+rr*8;
            if(gr>=M) continue;
#pragma unroll
            for(int cc=0;cc<2;cc++){
                int c2=gc+cc;
                if(c2>=N) continue;
                float v = acc[mt][nt][rr*2+cc]*alpha;
                if(cscale) v *= cscale[c2];
                if(dob) v += bias[c2];
                long off=(long)batch*sCz + (long)gr*ldc + c2;
                if(CMODE==CM_ATOM) atomicAdd(&C[off],v);
                else if(CMODE==CM_STORE) C[off]=v;
                else { bf h,l; sp2(v,h,l); CH[off]=h; CL[off]=l; }
            }
        }
    }
}

// ---- BM=32 bf16 GEMM (M==32) ----
#define SM32S 25600
__global__ void __launch_bounds__(256,2) mgemm32(
    int N,int K,
    const bf* __restrict__ Ah,const bf* __restrict__ Al,int lda,
    const bf* __restrict__ Bh,const bf* __restrict__ Bl,int ldb,
    float* __restrict__ C,int ldc,const float* __restrict__ bias)
{
    extern __shared__ bf sh[];
    const int t=threadIdx.x, lane=t&31, wid=t>>5;
    const int bn=blockIdx.x*128;
    const uint32_t sb=smem_u32(sh);
    const int NC=K>>5;
    float acc[2][2][4];
#pragma unroll
    for(int a=0;a<2;a++)
#pragma unroll
    for(int b=0;b<2;b++)
#pragma unroll
    for(int c=0;c<4;c++) acc[a][b][c]=0.f;

    auto fill=[&](int st,int c){
        uint32_t bs=sb+(uint32_t)st*SM32S;
        {
            int row=(t&127)>>2, ch=(t&3)*8;
            const bf* Ap=(t<128)?Ah:Al;
            uint32_t off=(t<128)?0u:2560u;
            CPA(bs+off+(uint32_t)(row*80+ch*2), Ap+(long)row*lda+c*32+ch);
        }
#pragma unroll
        for(int i=0;i<2;i++){
            int f=t+i*256, row=f>>2, ch=(f&3)*8;
            int rn=bn+row; if(rn>=N) rn=N-1;
            long bo=(long)rn*ldb+c*32+ch;
            CPA(bs+5120u+(uint32_t)(row*80+ch*2), Bh+bo);
            CPA(bs+15360u+(uint32_t)(row*80+ch*2), Bl+bo);
        }
        CPC();
    };

    fill(0,0);
    for(int c=0;c<NC;c++){
        int st=c&1;
        CPW(0);
        __syncthreads();
        if(c+1<NC) fill(st^1,c+1);
        uint32_t base=sb+(uint32_t)st*SM32S;
#pragma unroll
        for(int ks=0;ks<2;ks++){
            uint32_t kadd=(uint32_t)(ks*32+(lane>>4)*16);
            uint32_t Af[2][4], Bf[2][2], Bl2[2][2];
#pragma unroll
            for(int mt=0;mt<2;mt++)
                LDSM4(Af[mt], base + (uint32_t)((mt*16+(lane&15))*80) + kadd);
            {
                uint32_t qq[4];
                LDSM4(qq, base+5120u + (uint32_t)((wid*16+(lane&15))*80) + kadd);
                Bf[0][0]=qq[0];Bf[0][1]=qq[2];Bf[1][0]=qq[1];Bf[1][1]=qq[3];
            }
#pragma unroll
            for(int mt=0;mt<2;mt++)
#pragma unroll
            for(int nt=0;nt<2;nt++) MMA(acc[mt][nt],Af[mt],Bf[nt]);
            {
                uint32_t qq[4];
                LDSM4(qq, base+15360u + (uint32_t)((wid*16+(lane&15))*80) + kadd);
                Bl2[0][0]=qq[0];Bl2[0][1]=qq[2];Bl2[1][0]=qq[1];Bl2[1][1]=qq[3];
            }
#pragma unroll
            for(int mt=0;mt<2;mt++)
#pragma unroll
            for(int nt=0;nt<2;nt++) MMA(acc[mt][nt],Af[mt],Bl2[nt]);
#pragma unroll
            for(int mt=0;mt<2;mt++)
                LDSM4(Af[mt], base+2560u + (uint32_t)((mt*16+(lane&15))*80) + kadd);
#pragma unroll
            for(int mt=0;mt<2;mt++)
#pragma unroll
            for(int nt=0;nt<2;nt++) MMA(acc[mt][nt],Af[mt],Bf[nt]);
        }
    }
#pragma unroll
    for(int mt=0;mt<2;mt++)
#pragma unroll
    for(int nt=0;nt<2;nt++){
        int gc=bn+wid*16+nt*8+(lane&3)*2;
#pragma unroll
        for(int rr=0;rr<2;rr++){
            int gr=mt*16+(lane>>2)+rr*8;
#pragma unroll
            for(int cc=0;cc<2;cc++){
                int c2=gc+cc;
                if(c2>=N) continue;
                float v=acc[mt][nt][rr*2+cc];
                if(bias) v+=bias[c2];
                C[(long)gr*ldc+c2]=v;
            }
        }
    }
}

// ---- unified prep ----
#define NSEG 10
struct Segs {
    const float* src[NSEG]; bf* dh[NSEG]; bf* dl[NSEG];
    int K[NSEG], N[NSEG], mode[NSEG];
    int bstart[NSEG+1]; int nseg;
};
__global__ void prep_all(Segs S)
{
    __shared__ float tile[32][33];
    int b=blockIdx.x;
    int si=0;
    while(si+1<S.nseg && b>=S.bstart[si+1]) si++;
    int lb=b-S.bstart[si];
    int tx=threadIdx.x, ty=threadIdx.y;
    if(S.mode[si]==0){
        int K=S.K[si], N=S.N[si];
        int tpz=(N/32)*(K/32);
        int z=lb/tpz, rem=lb-z*tpz;
        int n0=(rem%(N/32))*32, k0=(rem/(N/32))*32;
        long zo=(long)z*K*N;
        const float* Sp=S.src[si]+zo; bf* TH=S.dh[si]+zo; bf* TL=S.dl[si]+zo;
#pragma unroll
        for(int j=0;j<4;j++)
            tile[ty+j*8][tx]=Sp[(long)(k0+ty+j*8)*N+n0+tx];
        __syncthreads();
#pragma unroll
        for(int j=0;j<4;j++){
            int n=n0+ty+j*8, k=k0+tx;
            bf h,l; sp2(tile[tx][ty+j*8],h,l);
            TH[(long)n*K+k]=h; TL[(long)n*K+k]=l;
        }
    } else {
        long n=(long)S.K[si]*2048;
        long i0=(long)lb*2048 + ty*32+tx;
#pragma unroll
        for(int j=0;j<8;j++){
            long i=i0+j*256;
            if(i<n){ bf h,l; sp2(S.src[si][i],h,l); S.dh[si][i]=h; S.dl[si][i]=l; }
        }
    }
}

// ---- SIMT fp32 GEMM (temb only) ----
template<int ACT>
__global__ void __launch_bounds__(256) gemm_s(
    int M,int N,int K,
    const float* __restrict__ A,int lda,
    const float* __restrict__ B,int ldb,
    float* __restrict__ C,int ldc,
    const float* __restrict__ bias)
{
    __shared__ float As[16][68], Bs[16][68];
    int bm=blockIdx.y*64, bn=blockIdx.x*64, t=threadIdx.x;
    int tx=t&15, ty=t>>4;
    float acc[4][4];
#pragma unroll
    for(int i=0;i<4;i++)
#pragma unroll
    for(int j=0;j<4;j++) acc[i][j]=0.f;
    for(int k0=0;k0<K;k0+=16){
#pragma unroll
        for(int i=0;i<4;i++){
            int idx=t+i*256, r=idx>>4, kk=idx&15;
            As[kk][r] = (bm+r<M)? A[(long)(bm+r)*lda+k0+kk] : 0.f;
        }
#pragma unroll
        for(int i=0;i<4;i++){
            int idx=t+i*256, kk=idx>>6, cc=idx&63;
            Bs[kk][cc] = (bn+cc<N)? B[(long)(k0+kk)*ldb+bn+cc] : 0.f;
        }
        __syncthreads();
#pragma unroll
        for(int kk=0;kk<16;kk++){
            float ra[4],rb[4];
#pragma unroll
            for(int i=0;i<4;i++) ra[i]=As[kk][ty*4+i];
#pragma unroll
            for(int j=0;j<4;j++) rb[j]=Bs[kk][tx*4+j];
#pragma unroll
            for(int i=0;i<4;i++)
#pragma unroll
            for(int j=0;j<4;j++) acc[i][j]+=ra[i]*rb[j];
        }
        __syncthreads();
    }
#pragma unroll
    for(int i=0;i<4;i++){
        int gr=bm+ty*4+i; if(gr>=M) continue;
#pragma unroll
        for(int j=0;j<4;j++){
            int gc=bn+tx*4+j; if(gc>=N) continue;
            float v=acc[i][j];
            if(bias) v+=bias[gc];
            if(ACT==ACT_SILU) v=v/(1.f+expf(-v));
            C[(long)gr*ldc+gc]=v;
        }
    }
}

// ---- LayerNorm D=1024 -> split or fp32 ----
template<bool AFFINE,bool SPLIT>
__global__ void __launch_bounds__(256) ln_k(const float* __restrict__ x,
    float* __restrict__ y, bf* __restrict__ yH, bf* __restrict__ yL,
    const float* __restrict__ g, const float* __restrict__ b)
{
    long row=blockIdx.x; const float* xr=x+row*D_; int t=threadIdx.x;
    float v[4], s=0.f;
#pragma unroll
    for(int i=0;i<4;i++){ v[i]=xr[t+i*256]; s+=v[i]; }
    __shared__ float red[256];
    red[t]=s; __syncthreads();
    for(int o=128;o>0;o>>=1){ if(t<o) red[t]+=red[t+o]; __syncthreads(); }
    float m=red[0]*(1.f/D_); __syncthreads();
    float vs=0.f;
#pragma unroll
    for(int i=0;i<4;i++){ float d=v[i]-m; vs+=d*d; }
    red[t]=vs; __syncthreads();
    for(int o=128;o>0;o>>=1){ if(t<o) red[t]+=red[t+o]; __syncthreads(); }
    float rs=1.f/sqrtf(red[0]*(1.f/D_)+1e-5f);
#pragma unroll
    for(int i=0;i<4;i++){
        int c=t+i*256; float o=(v[i]-m)*rs;
        if(AFFINE) o=o*g[c]+b[c];
        if(SPLIT){ bf h,l; sp2(o,h,l); yH[row*D_+c]=h; yL[row*D_+c]=l; }
        else y[row*D_+c]=o;
    }
}

// ---- softmax 1024 -> split ----
__global__ void __launch_bounds__(256) softmax_k(const float* __restrict__ x,
    bf* __restrict__ pH, bf* __restrict__ pL)
{
    long row=blockIdx.x; const float* p=x+row*N1_; int t=threadIdx.x;
    float v[4], mx=-1e30f;
#pragma unroll
    for(int i=0;i<4;i++){ v[i]=p[t+i*256]; mx=fmaxf(mx,v[i]); }
    __shared__ float red[256];
    red[t]=mx; __syncthreads();
    for(int o=128;o>0;o>>=1){ if(t<o) red[t]=fmaxf(red[t],red[t+o]); __syncthreads(); }
    mx=red[0]; __syncthreads();
    float s=0.f;
#pragma unroll
    for(int i=0;i<4;i++){ v[i]=expf(v[i]-mx); s+=v[i]; }
    red[t]=s; __syncthreads();
    for(int o=128;o>0;o>>=1){ if(t<o) red[t]+=red[t+o]; __syncthreads(); }
    float inv=1.f/red[0];
#pragma unroll
    for(int i=0;i<4;i++){
        int c=t+i*256; bf h,l; sp2(v[i]*inv,h,l);
        pH[row*N1_+c]=h; pL[row*N1_+c]=l;
    }
}

// ---- split / gelu-split ----
__global__ void split_k(const float* __restrict__ s, bf* __restrict__ h, bf* __restrict__ l, int n)
{
    int i=blockIdx.x*blockDim.x+threadIdx.x;
    if(i>=n) return;
    bf hh,ll; sp2(s[i],hh,ll); h[i]=hh; l[i]=ll;
}
__global__ void gsplit_k(const float* __restrict__ s, bf* __restrict__ h, bf* __restrict__ l, int n)
{
    int i=blockIdx.x*blockDim.x+threadIdx.x;
    if(i>=n) return;
    float v=s[i];
    v = 0.5f*v*(1.f+erff(v*0.70710678118654752f));
    bf hh,ll; sp2(v,hh,ll); h[i]=hh; l[i]=ll;
}

// ---- transpose bf16 pairs [R][C] -> [C][R], z-batched ----
__global__ void btransp(const bf* __restrict__ ih,const bf* __restrict__ il,
                        bf* __restrict__ oh, bf* __restrict__ ol,int R,int C)
{
    __shared__ bf th[32][33], tl[32][33];
    long zo=(long)blockIdx.z*R*C;
    int c0=blockIdx.x*32, r0=blockIdx.y*32;
    int tx=threadIdx.x, ty=threadIdx.y;
#pragma unroll
    for(int j=0;j<4;j++){
        int r=r0+ty+j*8;
        th[ty+j*8][tx]=ih[zo+(long)r*C+c0+tx];
        tl[ty+j*8][tx]=il[zo+(long)r*C+c0+tx];
    }
    __syncthreads();
#pragma unroll
    for(int j=0;j<4;j++){
        int c=c0+ty+j*8, r=r0+tx;
        oh[zo+(long)c*R+r]=th[tx][ty+j*8];
        ol[zo+(long)c*R+r]=tl[tx][ty+j*8];
    }
}

// ---- misc ----
__global__ void timestep_k(const float* __restrict__ ts, float* __restrict__ out){
    int b=blockIdx.x,i=threadIdx.x;
    int j=(i<160)?i:(i-160);
    float f=expf(-logf(10000.f)*(float)j/160.f);
    double a=(double)(ts[b]*f);
    out[b*TD_+i]=(i<160)?(float)cos(a):(float)sin(a);
}
__global__ void silu_split_k(const float* __restrict__ x,float* __restrict__ y,
                             bf* __restrict__ yH,bf* __restrict__ yL,int n){
    int i=blockIdx.x*blockDim.x+threadIdx.x;
    if(i<n){ float v=x[i]; v=v/(1.f+expf(-v)); y[i]=v;
        bf h,l; sp2(v,h,l); yH[i]=h; yL[i]=l; }
}
__global__ void bcast_k(const float* __restrict__ s,float* __restrict__ d,int n,int per){
    int i=blockIdx.x*blockDim.x+threadIdx.x;
    if(i<n) d[i]=s[i%per];
}
__global__ void modulate_k(const float* __restrict__ q,const float* __restrict__ ada,int loff,
                           bf* __restrict__ qH,bf* __restrict__ qL){
    int i=blockIdx.x*blockDim.x+threadIdx.x;
    if(i>=BS_*NQ_*D_) return;
    int b=i/(NQ_*D_), c=i&(D_-1);
    const float* ap=ada+(long)b*ADAW+loff;
    float v=q[i]*(1.f+ap[2*D_+c])+ap[c];
    bf h,l; sp2(v,h,l); qH[i]=h; qL[i]=l;
}

// ---- host ----
#define GSA(p,s) cudaGetSymbolAddress((void**)&p,s)
static inline dim3 tg(int M,int N,int z){ return dim3((unsigned)((N+127)/128),(unsigned)((M+127)/128),(unsigned)z); }
static bf* NB_=nullptr;

extern "C" void kernel_launch(void* const* d_in, const int* in_sizes, int n_in,
                              void* d_out, int out_size)
{
    const float *in_x=(const float*)d_in[0], *in_ts=(const float*)d_in[1], *in_lat=(const float*)d_in[2];
    const float *te_w1=(const float*)d_in[3], *te_b1=(const float*)d_in[4];
    const float *te_w2=(const float*)d_in[5], *te_b2=(const float*)d_in[6];
    const float *pin_w=(const float*)d_in[7], *pin_b=(const float*)d_in[8];
    const float *ln1_g=(const float*)d_in[9], *ln1_b=(const float*)d_in[10];
    const float *ln2_g=(const float*)d_in[11], *ln2_b=(const float*)d_in[12];
    const float *wq=(const float*)d_in[13], *wkv=(const float*)d_in[14], *wo=(const float*)d_in[15];
    const float *flg=(const float*)d_in[16], *flb=(const float*)d_in[17];
    const float *fw1=(const float*)d_in[18], *fw2=(const float*)d_in[19];
    const float *aw=(const float*)d_in[20], *ab=(const float*)d_in[21];
    const float *pout_w=(const float*)d_in[22], *pout_b=(const float*)d_in[23];
    const float *ng=(const float*)d_in[24], *nb=(const float*)d_in[25];
    float* out=(float*)d_out;

    cudaFuncSetAttribute(mgemm<CM_STORE,3>,cudaFuncAttributeMaxDynamicSharedMemorySize,SMB);
    cudaFuncSetAttribute(mgemm<CM_ATOM,3>, cudaFuncAttributeMaxDynamicSharedMemorySize,SMB);
    cudaFuncSetAttribute(mgemm<CM_SPLIT,3>,cudaFuncAttributeMaxDynamicSharedMemorySize,SMB);
    cudaFuncSetAttribute(mgemm<CM_STORE,2>,cudaFuncAttributeMaxDynamicSharedMemorySize,SMB);
    cudaFuncSetAttribute(mgemm<CM_SPLIT,2>,cudaFuncAttributeMaxDynamicSharedMemorySize,SMB);
    cudaFuncSetAttribute(mgemm32,cudaFuncAttributeMaxDynamicSharedMemorySize,2*SM32S);

    float *xp,*temb0,*temb1,*temb,*stemb,*ada,*lat,*att,*hff,*zacc;
    GSA(xp,g_xp); GSA(temb0,g_temb0); GSA(temb1,g_temb1); GSA(temb,g_temb);
    GSA(stemb,g_stemb); GSA(ada,g_ada); GSA(lat,g_lat);
    GSA(att,g_att); GSA(hff,g_hff); GSA(zacc,g_zacc);
    float* q    = zacc;
    float* vout = zacc + (long)BS_*NQ_*D_;
    float* h1   = zacc + (long)2*BS_*NQ_*D_;
    bf *inxH,*inxL,*pinH,*pinL,*xnH,*xnL,*xnTH,*xnTL,*latnH,*latnL,*qH,*qL,*qpH,*qpL;
    bf *attH,*attL,*ovH,*ovL,*voH,*voL,*hffH,*hffL,*h1H,*h1L,*latH,*latL,*stH,*stL;
    bf *wqH,*wqL,*kvH,*kvL,*kvTH,*kvTL,*woH,*woL,*f1H,*f1L,*f2H,*f2L,*awH,*awL,*poH,*poL;
    GSA(inxH,s_inxH); GSA(inxL,s_inxL); GSA(pinH,s_pinH); GSA(pinL,s_pinL);
    GSA(xnH,s_xnH); GSA(xnL,s_xnL); GSA(xnTH,s_xnTH); GSA(xnTL,s_xnTL);
    GSA(latnH,s_latnH); GSA(latnL,s_latnL); GSA(qH,s_qH); GSA(qL,s_qL);
    GSA(qpH,s_qpH); GSA(qpL,s_qpL); GSA(attH,s_attH); GSA(attL,s_attL);
    GSA(ovH,s_ovH); GSA(ovL,s_ovL); GSA(voH,s_voH); GSA(voL,s_voL);
    GSA(hffH,s_hffH); GSA(hffL,s_hffL); GSA(h1H,s_h1H); GSA(h1L,s_h1L);
    GSA(latH,s_latH); GSA(latL,s_latL); GSA(stH,s_stH); GSA(stL,s_stL);
    GSA(wqH,s_wqH); GSA(wqL,s_wqL); GSA(kvH,s_kvH); GSA(kvL,s_kvL);
    GSA(kvTH,s_kvTH); GSA(kvTL,s_kvTL); GSA(woH,s_woH); GSA(woL,s_woL);
    GSA(f1H,s_f1H); GSA(f1L,s_f1L); GSA(f2H,s_f2H); GSA(f2L,s_f2L);
    GSA(awH,s_awH); GSA(awL,s_awL); GSA(poH,s_poH); GSA(poL,s_poL);

    // launch 0: ALL prep in one kernel
    Segs S; int nbk=0; int si=0;
    auto addT=[&](const float* s, bf* h, bf* l, int K,int N,int z){
        S.src[si]=s;S.dh[si]=h;S.dl[si]=l;S.K[si]=K;S.N[si]=N;S.mode[si]=0;
        S.bstart[si]=nbk; nbk+=(N/32)*(K/32)*z; si++;
    };
    auto addS2=[&](const float* s, bf* h, bf* l, long n){
        S.src[si]=s;S.dh[si]=h;S.dl[si]=l;S.K[si]=(int)(n/2048);S.N[si]=1;S.mode[si]=1;
        S.bstart[si]=nbk; nbk+=(int)(n/2048); si++;
    };
    addT(pin_w,pinH,pinL,ED_,D_,1);
    addT(wq,wqH,wqL,D_,INNER,DEPTH);
    addT(wkv,kvTH,kvTL,D_,2*INNER,DEPTH);
    addT(wo,woH,woL,INNER,D_,DEPTH);
    addT(fw1,f1H,f1L,D_,FF_,DEPTH);
    addT(fw2,f2H,f2L,FF_,D_,DEPTH);
    addT(aw,awH,awL,D_,4*D_,DEPTH);
    addT(pout_w,poH,poL,D_,D_,1);
    addS2(wkv,kvH,kvL,(long)DEPTH*D_*2*INNER);
    addS2(in_x,inxH,inxL,(long)BS_*N1_*ED_);
    S.nseg=si; S.bstart[si]=nbk;
    prep_all<<<nbk,dim3(32,8)>>>(S);

    // launches 1,2
    timestep_k<<<BS_,TD_>>>(in_ts,temb0);
    gemm_s<ACT_SILU><<<dim3(16,1),256>>>(BS_,D_,TD_,temb0,TD_,te_w1,D_,temb1,D_,te_b1);

    // launch 3: proj_in (standard mgemm, profiled at idx 5)
    mgemm<CM_STORE,3><<<tg(BS_*N1_,D_,1),256,SMB>>>(
        BS_*N1_,D_,ED_,1, inxH,inxL,ED_,0, pinH,pinL,ED_,0,
        xp,NB_,NB_,D_,0, pin_b,nullptr,1.f);

    gemm_s<ACT_NONE><<<dim3(16,1),256>>>(BS_,D_,D_,temb1,D_,te_w2,D_,temb,D_,te_b2);
    silu_split_k<<<(BS_*D_+255)/256,256>>>(temb,stemb,stH,stL,BS_*D_);

    // batched adaLN for ALL layers (BM=32)
    mgemm32<<<ADAW/128,256,2*SM32S>>>(ADAW,D_, stH,stL,D_, awH,awL,D_, ada,ADAW, ab);

    ln_k<false,true><<<BS_*N1_,256>>>(xp,nullptr,xnH,xnL,nullptr,nullptr);
    btransp<<<dim3(D_/32,N1_/32,BS_),dim3(32,8)>>>(xnH,xnL,xnTH,xnTL,N1_,D_);
    bcast_k<<<(BS_*NQ_*D_+255)/256,256>>>(in_lat,lat,BS_*NQ_*D_,NQ_*D_);

    for(int l=0;l<DEPTH;l++){
        const float *g1=ln1_g+l*D_, *b1=ln1_b+l*D_, *g2=ln2_g+l*D_, *b2=ln2_b+l*D_;
        const float *fg=flg+l*D_, *fb=flb+l*D_;
        const bf *wqh=wqH+(long)l*INNER*D_, *wql=wqL+(long)l*INNER*D_;
        const bf *kvh=kvH+(long)l*D_*2*INNER, *kvl=kvL+(long)l*D_*2*INNER;
        const bf *kvth=kvTH+(long)l*2*INNER*D_, *kvtl=kvTL+(long)l*2*INNER*D_;
        const bf *woh=woH+(long)l*D_*INNER, *wol=woL+(long)l*D_*INNER;
        const bf *f1h=f1H+(long)l*FF_*D_, *f1l=f1L+(long)l*FF_*D_;
        const bf *f2h=f2H+(long)l*D_*FF_, *f2l=f2L+(long)l*D_*FF_;

        cudaMemsetAsync(zacc,0,(size_t)BS_*NQ_*(2*D_+FF_)*sizeof(float),0);

        // latn -> q (split-K=16) -> modulate+split
        ln_k<true,true><<<BS_*NQ_,256>>>(lat,nullptr,latnH,latnL,g2,b2);
        mgemm<CM_ATOM,3><<<tg(BS_*NQ_,INNER,16),256,SMB>>>(
            BS_*NQ_,INNER,D_,16, latnH,latnL,D_,0, wqh,wql,D_,0,
            q,NB_,NB_,INNER,0, nullptr,nullptr,1.f);
        modulate_k<<<(BS_*NQ_*D_+255)/256,256>>>(q,ada,l*4*D_,qH,qL);

        // qp(split out, ⊙g1) = SCALE * qmod_h @ wk_h^T (z=heads)
        mgemm<CM_SPLIT,3><<<tg(BS_*NQ_,D_,H_),256,SMB>>>(
            BS_*NQ_,D_,DH_,1, qH,qL,INNER,64, kvh,kvl,2*INNER,64,
            nullptr,qpH,qpL,H_*D_,(long)D_, nullptr,g1,SCALE_);

        // logits = qp' @ xn^T (2-PASS: xn rounded to bf16; qp stays split)
        mgemm<CM_STORE,2><<<tg(NQ_*H_,N1_,BS_),256,SMB>>>(
            NQ_*H_,N1_,D_,1, qpH,qpL,D_,(long)NQ_*H_*D_, xnH,xnH,D_,(long)N1_*D_,
            att,NB_,NB_,N1_,(long)NQ_*H_*N1_, nullptr,nullptr,1.f);
        softmax_k<<<BS_*NQ_*H_,256>>>(att,attH,attL);

        // ov(split out, g1*x+b1) = attn @ xn (2-PASS: xnT rounded; attn stays split)
        mgemm<CM_SPLIT,2><<<tg(NQ_*H_,D_,BS_),256,SMB>>>(
            NQ_*H_,D_,N1_,1, attH,attL,N1_,(long)NQ_*H_*N1_, xnTH,xnTH,N1_,(long)D_*N1_,
            nullptr,ovH,ovL,D_,(long)NQ_*H_*D_, b1,g1,1.f);

        // vout = ovm_h @ wv_h (z=heads, split-K=8)
        mgemm<CM_ATOM,3><<<tg(BS_*NQ_,DH_,H_*8),256,SMB>>>(
            BS_*NQ_,DH_,D_,8, ovH,ovL,H_*D_,(long)D_, kvth+(long)INNER*D_,kvtl+(long)INNER*D_,D_,(long)64*D_,
            vout,NB_,NB_,D_,64, nullptr,nullptr,1.f);
        split_k<<<(BS_*NQ_*D_+255)/256,256>>>(vout,voH,voL,BS_*NQ_*D_);

        // lat += vout @ wo (split-K=16)
        mgemm<CM_ATOM,3><<<tg(BS_*NQ_,D_,16),256,SMB>>>(
            BS_*NQ_,D_,INNER,16, voH,voL,INNER,0, woh,wol,INNER,0,
            lat,NB_,NB_,D_,0, nullptr,nullptr,1.f);

        // FF: h1 raw (split-K=4) -> GELU+split -> ff2 (split-K=16)
        ln_k<true,true><<<BS_*NQ_,256>>>(lat,nullptr,hffH,hffL,fg,fb);
        mgemm<CM_ATOM,3><<<tg(BS_*NQ_,FF_,4),256,SMB>>>(
            BS_*NQ_,FF_,D_,4, hffH,hffL,D_,0, f1h,f1l,D_,0,
            h1,NB_,NB_,FF_,0, nullptr,nullptr,1.f);
        gsplit_k<<<(BS_*NQ_*FF_+255)/256,256>>>(h1,h1H,h1L,BS_*NQ_*FF_);
        mgemm<CM_ATOM,3><<<tg(BS_*NQ_,D_,16),256,SMB>>>(
            BS_*NQ_,D_,FF_,16, h1H,h1L,FF_,0, f2h,f2l,FF_,0,
            lat,NB_,NB_,D_,0, nullptr,nullptr,1.f);
    }

    // ---- proj_out (split-K=16) + final LN ----
    split_k<<<(BS_*NQ_*D_+255)/256,256>>>(lat,latH,latL,BS_*NQ_*D_);
    cudaMemsetAsync(hff,0,(size_t)BS_*NQ_*D_*sizeof(float),0);
    mgemm<CM_ATOM,3><<<tg(BS_*NQ_,D_,16),256,SMB>>>(
        BS_*NQ_,D_,D_,16, latH,latL,D_,0, poH,poL,D_,0,
        hff,NB_,NB_,D_,0, pout_b,nullptr,1.f);
    ln_k<true,false><<<BS_*NQ_,256>>>(hff,out,nullptr,nullptr,ng,nb);
}

// round 15
// speedup vs baseline: 1.1519x; 1.0487x over previous
#include <cuda_runtime.h>
#include <cuda_bf16.h>
#include <math.h>
#include <stdint.h>

#define D_    1024
#define DEPTH 8
#define H_    16
#define DH_   64
#define INNER 1024
#define NQ_   8
#define ED_   768
#define FF_   4096
#define TD_   320
#define BS_   32
#define N1_   1024
#define SCALE_ 0.125f
#define ADAW  32768

#define ACT_NONE 0
#define ACT_SILU 1
#define CM_STORE 0
#define CM_ATOM  1
#define CM_SPLIT 2

typedef __nv_bfloat16 bf;

// ---- fp32 scratch ----
__device__ float g_xp[BS_*N1_*D_];
__device__ float g_temb0[BS_*TD_];
__device__ float g_temb1[BS_*D_];
__device__ float g_temb[BS_*D_];
__device__ float g_stemb[BS_*D_];
__device__ float g_ada[BS_*ADAW];
__device__ float g_lat[BS_*NQ_*D_];
__device__ float g_att[BS_*NQ_*H_*N1_];
__device__ float g_hff[BS_*NQ_*D_];
__device__ float g_zacc[BS_*NQ_*(2*D_+FF_)];

// ---- bf16 hi/lo pairs ----
__device__ bf s_inxH[BS_*N1_*ED_],  s_inxL[BS_*N1_*ED_];
__device__ bf s_pinH[D_*ED_],       s_pinL[D_*ED_];
__device__ bf s_xnH[BS_*N1_*D_],    s_xnL[BS_*N1_*D_];
__device__ bf s_xnTH[BS_*D_*N1_],   s_xnTL[BS_*D_*N1_];
__device__ bf s_latnH[BS_*NQ_*D_],  s_latnL[BS_*NQ_*D_];
__device__ bf s_qH[BS_*NQ_*D_],     s_qL[BS_*NQ_*D_];
__device__ bf s_qpH[BS_*NQ_*H_*D_], s_qpL[BS_*NQ_*H_*D_];
__device__ bf s_attH[BS_*NQ_*H_*N1_], s_attL[BS_*NQ_*H_*N1_];
__device__ bf s_ovH[BS_*NQ_*H_*D_], s_ovL[BS_*NQ_*H_*D_];
__device__ bf s_voH[BS_*NQ_*D_],    s_voL[BS_*NQ_*D_];
__device__ bf s_hffH[BS_*NQ_*D_],   s_hffL[BS_*NQ_*D_];
__device__ bf s_h1H[BS_*NQ_*FF_],   s_h1L[BS_*NQ_*FF_];
__device__ bf s_latH[BS_*NQ_*D_],   s_latL[BS_*NQ_*D_];
__device__ bf s_stH[BS_*D_],        s_stL[BS_*D_];
__device__ bf s_wqH[DEPTH*INNER*D_],  s_wqL[DEPTH*INNER*D_];
__device__ bf s_kvH[DEPTH*D_*2*INNER],s_kvL[DEPTH*D_*2*INNER];
__device__ bf s_kvTH[DEPTH*2*INNER*D_],s_kvTL[DEPTH*2*INNER*D_];
__device__ bf s_woH[DEPTH*D_*INNER],  s_woL[DEPTH*D_*INNER];
__device__ bf s_f1H[DEPTH*FF_*D_],    s_f1L[DEPTH*FF_*D_];
__device__ bf s_f2H[DEPTH*D_*FF_],    s_f2L[DEPTH*D_*FF_];
__device__ bf s_awH[DEPTH*4*D_*D_],   s_awL[DEPTH*4*D_*D_];
__device__ bf s_poH[D_*D_],           s_poL[D_*D_];

// ---- helpers ----
__device__ __forceinline__ uint32_t smem_u32(const void* p){
    uint32_t a;
    asm("{ .reg .u64 t; cvta.to.shared.u64 t, %1; cvt.u32.u64 %0, t; }":"=r"(a):"l"(p));
    return a;
}
__device__ __forceinline__ void sp2(float v, bf& h, bf& l){
    h = __float2bfloat16_rn(v);
    l = __float2bfloat16_rn(v - __bfloat162float(h));
}
#define CPA(d,s) asm volatile("cp.async.cg.shared.global [%0],[%1],16;"::"r"(d),"l"(s):"memory")
#define CPC()    asm volatile("cp.async.commit_group;":::"memory")
#define CPW(n)   asm volatile("cp.async.wait_group %0;"::"n"(n):"memory")
#define LDSM4(r,a) asm volatile("ldmatrix.sync.aligned.m8n8.x4.shared.b16 {%0,%1,%2,%3},[%4];" \
    :"=r"((r)[0]),"=r"((r)[1]),"=r"((r)[2]),"=r"((r)[3]):"r"(a))
#define MMA(d,a,b) asm volatile("mma.sync.aligned.m16n8k16.row.col.f32.bf16.bf16.f32 " \
    "{%0,%1,%2,%3},{%4,%5,%6,%7},{%8,%9},{%0,%1,%2,%3};" \
    :"+f"((d)[0]),"+f"((d)[1]),"+f"((d)[2]),"+f"((d)[3]) \
    :"r"((a)[0]),"r"((a)[1]),"r"((a)[2]),"r"((a)[3]),"r"((b)[0]),"r"((b)[1]))

// ---- bf16 tensor GEMM: BK=32; NPASS=3: AhBh+AhBl+AlBh, NPASS=2: AhBh+AlBh ----
#define SMB 81920
template<int CMODE,int NPASS>
__global__ void __launch_bounds__(256,2) mgemm(
    int M,int N,int K,int ksplit,
    const bf* __restrict__ Ah,const bf* __restrict__ Al,int lda,long sAz,
    const bf* __restrict__ Bh,const bf* __restrict__ Bl,int ldb,long sBz,
    float* __restrict__ C, bf* __restrict__ CH, bf* __restrict__ CL, int ldc, long sCz,
    const float* __restrict__ bias, const float* __restrict__ cscale, float alpha)
{
    extern __shared__ bf sh[];
    const int t=threadIdx.x, lane=t&31, wid=t>>5;
    const int zz=blockIdx.z, batch=zz/ksplit, kp=zz-batch*ksplit;
    const int Kl=K/ksplit, koff=kp*Kl, NC=Kl>>5;
    const int bm=blockIdx.y*128, bn=blockIdx.x*128;
    const uint32_t sb = smem_u32(sh);
    const int mw=(wid>>2)*64, nw=(wid&3)*32;

    const bf* pAh[2]; const bf* pAl[2]; const bf* pBh[2]; const bf* pBl[2];
    uint32_t dst[2];
#pragma unroll
    for(int i=0;i<2;i++){
        int f=t+i*256, row=f>>2, ch=(f&3)*8;
        long ao=(long)batch*sAz + (long)(bm+row)*lda + koff + ch;
        pAh[i]=Ah+ao; pAl[i]=Al+ao;
        int rn=bn+row; if(rn>=N) rn=N-1;
        long bo=(long)batch*sBz + (long)rn*ldb + koff + ch;
        pBh[i]=Bh+bo; pBl[i]=Bl+bo;
        dst[i]=sb+(uint32_t)(row*40+ch)*2u;
    }

    float acc[4][4][4];
#pragma unroll
    for(int a=0;a<4;a++)
#pragma unroll
    for(int b=0;b<4;b++)
#pragma unroll
    for(int c=0;c<4;c++) acc[a][b][c]=0.f;

    auto fill=[&](int st){
        uint32_t so=(uint32_t)st*40960u;
#pragma unroll
        for(int i=0;i<2;i++){
            uint32_t d0=dst[i]+so;
            CPA(d0,       pAh[i]);
            CPA(d0+10240, pAl[i]);
            CPA(d0+20480, pBh[i]);
            if(NPASS==3) CPA(d0+30720, pBl[i]);
            pAh[i]+=32; pAl[i]+=32; pBh[i]+=32;
            if(NPASS==3) pBl[i]+=32;
        }
        CPC();
    };

    fill(0);
    for(int c=0;c<NC;c++){
        int st=c&1;
        CPW(0);
        __syncthreads();
        if(c+1<NC) fill(st^1);
        uint32_t base = sb + st*40960u;
#pragma unroll
        for(int ks=0;ks<2;ks++){
            uint32_t kadd = (uint32_t)(ks*32 + (lane>>4)*16);
            uint32_t Af[4][4], Bh2[4][2];
#pragma unroll
            for(int mt=0;mt<4;mt++)
                LDSM4(Af[mt], base + (uint32_t)(mw+mt*16+(lane&15))*80u + kadd);
#pragma unroll
            for(int np=0;np<2;np++){
                uint32_t qq[4];
                LDSM4(qq, base+20480u + (uint32_t)(nw+np*16+(lane&15))*80u + kadd);
                Bh2[np*2][0]=qq[0]; Bh2[np*2][1]=qq[2];
                Bh2[np*2+1][0]=qq[1]; Bh2[np*2+1][1]=qq[3];
            }
#pragma unroll
            for(int mt=0;mt<4;mt++)
#pragma unroll
            for(int nt=0;nt<4;nt++) MMA(acc[mt][nt],Af[mt],Bh2[nt]);
            if(NPASS==3){
                uint32_t Bl2[4][2];
#pragma unroll
                for(int np=0;np<2;np++){
                    uint32_t qq[4];
                    LDSM4(qq, base+30720u + (uint32_t)(nw+np*16+(lane&15))*80u + kadd);
                    Bl2[np*2][0]=qq[0]; Bl2[np*2][1]=qq[2];
                    Bl2[np*2+1][0]=qq[1]; Bl2[np*2+1][1]=qq[3];
                }
#pragma unroll
                for(int mt=0;mt<4;mt++)
#pragma unroll
                for(int nt=0;nt<4;nt++) MMA(acc[mt][nt],Af[mt],Bl2[nt]);
            }
#pragma unroll
            for(int mt=0;mt<4;mt++)
                LDSM4(Af[mt], base+10240u + (uint32_t)(mw+mt*16+(lane&15))*80u + kadd);
#pragma unroll
            for(int mt=0;mt<4;mt++)
#pragma unroll
            for(int nt=0;nt<4;nt++) MMA(acc[mt][nt],Af[mt],Bh2[nt]);
        }
    }

    const bool dob = bias && (CMODE!=CM_ATOM || kp==0);
#pragma unroll
    for(int mt=0;mt<4;mt++)
#pragma unroll
    for(int nt=0;nt<4;nt++){
        int gc = bn+nw+nt*8+(lane&3)*2;
#pragma unroll
        for(int rr=0;rr<2;rr++){
            int gr = bm+mw+mt*16+(lane>>2)+rr*8;
            if(gr>=M) continue;
#pragma unroll
            for(int cc=0;cc<2;cc++){
                int c2=gc+cc;
                if(c2>=N) continue;
                float v = acc[mt][nt][rr*2+cc]*alpha;
                if(cscale) v *= cscale[c2];
                if(dob) v += bias[c2];
                long off=(long)batch*sCz + (long)gr*ldc + c2;
                if(CMODE==CM_ATOM) atomicAdd(&C[off],v);
                else if(CMODE==CM_STORE) C[off]=v;
                else { bf h,l; sp2(v,h,l); CH[off]=h; CL[off]=l; }
            }
        }
    }
}

// ---- BK=64 2-pass GEMM (logits/ov): M%128==0, N%128==0, K%64==0, no ksplit ----
// stage: Ah(18432)+Al(18432)+Bh(18432)=55296B; 2 stages=110592B; row stride 144B (9x16: conflict-free)
#define S64  55296
#define SMB64 (2*S64)
template<int CMODE>
__global__ void __launch_bounds__(256,2) mgemm64(
    int K,
    const bf* __restrict__ Ah,const bf* __restrict__ Al,int lda,long sAz,
    const bf* __restrict__ Bh,int ldb,long sBz,
    float* __restrict__ C, bf* __restrict__ CH, bf* __restrict__ CL, int ldc, long sCz,
    const float* __restrict__ bias, const float* __restrict__ cscale, float alpha)
{
    extern __shared__ bf sh[];
    const int t=threadIdx.x, lane=t&31, wid=t>>5;
    const int batch=blockIdx.z;
    const int bm=blockIdx.y*128, bn=blockIdx.x*128;
    const uint32_t sb = smem_u32(sh);
    const int mw=(wid>>2)*64, nw=(wid&3)*32;
    const int NC=K>>6;

    const bf* pAh[4]; const bf* pAl[4]; const bf* pBh[4];
    uint32_t dst[4];
#pragma unroll
    for(int i=0;i<4;i++){
        int f=t+i*256, row=f>>3, ch=(f&7)*8;
        long ao=(long)batch*sAz + (long)(bm+row)*lda + ch;
        pAh[i]=Ah+ao; pAl[i]=Al+ao;
        long bo=(long)batch*sBz + (long)(bn+row)*ldb + ch;
        pBh[i]=Bh+bo;
        dst[i]=sb+(uint32_t)(row*144+ch*2);
    }

    float acc[4][4][4];
#pragma unroll
    for(int a=0;a<4;a++)
#pragma unroll
    for(int b=0;b<4;b++)
#pragma unroll
    for(int c=0;c<4;c++) acc[a][b][c]=0.f;

    auto fill=[&](int st){
        uint32_t so=(uint32_t)st*(uint32_t)S64;
#pragma unroll
        for(int i=0;i<4;i++){
            uint32_t d0=dst[i]+so;
            CPA(d0,        pAh[i]);
            CPA(d0+18432u, pAl[i]);
            CPA(d0+36864u, pBh[i]);
            pAh[i]+=64; pAl[i]+=64; pBh[i]+=64;
        }
        CPC();
    };

    fill(0);
    for(int c=0;c<NC;c++){
        int st=c&1;
        CPW(0);
        __syncthreads();
        if(c+1<NC) fill(st^1);
        uint32_t base = sb + st*(uint32_t)S64;
#pragma unroll
        for(int ks=0;ks<4;ks++){
            uint32_t kadd = (uint32_t)(ks*32 + (lane>>4)*16);
            uint32_t Af[4][4], Bh2[4][2];
#pragma unroll
            for(int mt=0;mt<4;mt++)
                LDSM4(Af[mt], base + (uint32_t)(mw+mt*16+(lane&15))*144u + kadd);
#pragma unroll
            for(int np=0;np<2;np++){
                uint32_t qq[4];
                LDSM4(qq, base+36864u + (uint32_t)(nw+np*16+(lane&15))*144u + kadd);
                Bh2[np*2][0]=qq[0]; Bh2[np*2][1]=qq[2];
                Bh2[np*2+1][0]=qq[1]; Bh2[np*2+1][1]=qq[3];
            }
#pragma unroll
            for(int mt=0;mt<4;mt++)
#pragma unroll
            for(int nt=0;nt<4;nt++) MMA(acc[mt][nt],Af[mt],Bh2[nt]);
#pragma unroll
            for(int mt=0;mt<4;mt++)
                LDSM4(Af[mt], base+18432u + (uint32_t)(mw+mt*16+(lane&15))*144u + kadd);
#pragma unroll
            for(int mt=0;mt<4;mt++)
#pragma unroll
            for(int nt=0;nt<4;nt++) MMA(acc[mt][nt],Af[mt],Bh2[nt]);
        }
    }

#pragma unroll
    for(int mt=0;mt<4;mt++)
#pragma unroll
    for(int nt=0;nt<4;nt++){
        int gc = bn+nw+nt*8+(lane&3)*2;
#pragma unroll
        for(int rr=0;rr<2;rr++){
            int gr = bm+mw+mt*16+(lane>>2)+rr*8;
#pragma unroll
            for(int cc=0;cc<2;cc++){
                int c2=gc+cc;
                float v = acc[mt][nt][rr*2+cc]*alpha;
                if(cscale) v *= cscale[c2];
                if(bias) v += bias[c2];
                long off=(long)batch*sCz + (long)gr*ldc + c2;
                if(CMODE==CM_STORE) C[off]=v;
                else { bf h,l; sp2(v,h,l); CH[off]=h; CL[off]=l; }
            }
        }
    }
}

// ---- BM=32 bf16 GEMM (M==32) ----
#define SM32S 25600
__global__ void __launch_bounds__(256,2) mgemm32(
    int N,int K,
    const bf* __restrict__ Ah,const bf* __restrict__ Al,int lda,
    const bf* __restrict__ Bh,const bf* __restrict__ Bl,int ldb,
    float* __restrict__ C,int ldc,const float* __restrict__ bias)
{
    extern __shared__ bf sh[];
    const int t=threadIdx.x, lane=t&31, wid=t>>5;
    const int bn=blockIdx.x*128;
    const uint32_t sb=smem_u32(sh);
    const int NC=K>>5;
    float acc[2][2][4];
#pragma unroll
    for(int a=0;a<2;a++)
#pragma unroll
    for(int b=0;b<2;b++)
#pragma unroll
    for(int c=0;c<4;c++) acc[a][b][c]=0.f;

    auto fill=[&](int st,int c){
        uint32_t bs=sb+(uint32_t)st*SM32S;
        {
            int row=(t&127)>>2, ch=(t&3)*8;
            const bf* Ap=(t<128)?Ah:Al;
            uint32_t off=(t<128)?0u:2560u;
            CPA(bs+off+(uint32_t)(row*80+ch*2), Ap+(long)row*lda+c*32+ch);
        }
#pragma unroll
        for(int i=0;i<2;i++){
            int f=t+i*256, row=f>>2, ch=(f&3)*8;
            int rn=bn+row; if(rn>=N) rn=N-1;
            long bo=(long)rn*ldb+c*32+ch;
            CPA(bs+5120u+(uint32_t)(row*80+ch*2), Bh+bo);
            CPA(bs+15360u+(uint32_t)(row*80+ch*2), Bl+bo);
        }
        CPC();
    };

    fill(0,0);
    for(int c=0;c<NC;c++){
        int st=c&1;
        CPW(0);
        __syncthreads();
        if(c+1<NC) fill(st^1,c+1);
        uint32_t base=sb+(uint32_t)st*SM32S;
#pragma unroll
        for(int ks=0;ks<2;ks++){
            uint32_t kadd=(uint32_t)(ks*32+(lane>>4)*16);
            uint32_t Af[2][4], Bf[2][2], Bl2[2][2];
#pragma unroll
            for(int mt=0;mt<2;mt++)
                LDSM4(Af[mt], base + (uint32_t)((mt*16+(lane&15))*80) + kadd);
            {
                uint32_t qq[4];
                LDSM4(qq, base+5120u + (uint32_t)((wid*16+(lane&15))*80) + kadd);
                Bf[0][0]=qq[0];Bf[0][1]=qq[2];Bf[1][0]=qq[1];Bf[1][1]=qq[3];
            }
#pragma unroll
            for(int mt=0;mt<2;mt++)
#pragma unroll
            for(int nt=0;nt<2;nt++) MMA(acc[mt][nt],Af[mt],Bf[nt]);
            {
                uint32_t qq[4];
                LDSM4(qq, base+15360u + (uint32_t)((wid*16+(lane&15))*80) + kadd);
                Bl2[0][0]=qq[0];Bl2[0][1]=qq[2];Bl2[1][0]=qq[1];Bl2[1][1]=qq[3];
            }
#pragma unroll
            for(int mt=0;mt<2;mt++)
#pragma unroll
            for(int nt=0;nt<2;nt++) MMA(acc[mt][nt],Af[mt],Bl2[nt]);
#pragma unroll
            for(int mt=0;mt<2;mt++)
                LDSM4(Af[mt], base+2560u + (uint32_t)((mt*16+(lane&15))*80) + kadd);
#pragma unroll
            for(int mt=0;mt<2;mt++)
#pragma unroll
            for(int nt=0;nt<2;nt++) MMA(acc[mt][nt],Af[mt],Bf[nt]);
        }
    }
#pragma unroll
    for(int mt=0;mt<2;mt++)
#pragma unroll
    for(int nt=0;nt<2;nt++){
        int gc=bn+wid*16+nt*8+(lane&3)*2;
#pragma unroll
        for(int rr=0;rr<2;rr++){
            int gr=mt*16+(lane>>2)+rr*8;
#pragma unroll
            for(int cc=0;cc<2;cc++){
                int c2=gc+cc;
                if(c2>=N) continue;
                float v=acc[mt][nt][rr*2+cc];
                if(bias) v+=bias[c2];
                C[(long)gr*ldc+c2]=v;
            }
        }
    }
}

// ---- unified prep ----
#define NSEG 10
struct Segs {
    const float* src[NSEG]; bf* dh[NSEG]; bf* dl[NSEG];
    int K[NSEG], N[NSEG], mode[NSEG];
    int bstart[NSEG+1]; int nseg;
};
__global__ void prep_all(Segs S)
{
    __shared__ float tile[32][33];
    int b=blockIdx.x;
    int si=0;
    while(si+1<S.nseg && b>=S.bstart[si+1]) si++;
    int lb=b-S.bstart[si];
    int tx=threadIdx.x, ty=threadIdx.y;
    if(S.mode[si]==0){
        int K=S.K[si], N=S.N[si];
        int tpz=(N/32)*(K/32);
        int z=lb/tpz, rem=lb-z*tpz;
        int n0=(rem%(N/32))*32, k0=(rem/(N/32))*32;
        long zo=(long)z*K*N;
        const float* Sp=S.src[si]+zo; bf* TH=S.dh[si]+zo; bf* TL=S.dl[si]+zo;
#pragma unroll
        for(int j=0;j<4;j++)
            tile[ty+j*8][tx]=Sp[(long)(k0+ty+j*8)*N+n0+tx];
        __syncthreads();
#pragma unroll
        for(int j=0;j<4;j++){
            int n=n0+ty+j*8, k=k0+tx;
            bf h,l; sp2(tile[tx][ty+j*8],h,l);
            TH[(long)n*K+k]=h; TL[(long)n*K+k]=l;
        }
    } else {
        long n=(long)S.K[si]*2048;
        long i0=(long)lb*2048 + ty*32+tx;
#pragma unroll
        for(int j=0;j<8;j++){
            long i=i0+j*256;
            if(i<n){ bf h,l; sp2(S.src[si][i],h,l); S.dh[si][i]=h; S.dl[si][i]=l; }
        }
    }
}

// ---- SIMT fp32 GEMM (temb only) ----
template<int ACT>
__global__ void __launch_bounds__(256) gemm_s(
    int M,int N,int K,
    const float* __restrict__ A,int lda,
    const float* __restrict__ B,int ldb,
    float* __restrict__ C,int ldc,
    const float* __restrict__ bias)
{
    __shared__ float As[16][68], Bs[16][68];
    int bm=blockIdx.y*64, bn=blockIdx.x*64, t=threadIdx.x;
    int tx=t&15, ty=t>>4;
    float acc[4][4];
#pragma unroll
    for(int i=0;i<4;i++)
#pragma unroll
    for(int j=0;j<4;j++) acc[i][j]=0.f;
    for(int k0=0;k0<K;k0+=16){
#pragma unroll
        for(int i=0;i<4;i++){
            int idx=t+i*256, r=idx>>4, kk=idx&15;
            As[kk][r] = (bm+r<M)? A[(long)(bm+r)*lda+k0+kk] : 0.f;
        }
#pragma unroll
        for(int i=0;i<4;i++){
            int idx=t+i*256, kk=idx>>6, cc=idx&63;
            Bs[kk][cc] = (bn+cc<N)? B[(long)(k0+kk)*ldb+bn+cc] : 0.f;
        }
        __syncthreads();
#pragma unroll
        for(int kk=0;kk<16;kk++){
            float ra[4],rb[4];
#pragma unroll
            for(int i=0;i<4;i++) ra[i]=As[kk][ty*4+i];
#pragma unroll
            for(int j=0;j<4;j++) rb[j]=Bs[kk][tx*4+j];
#pragma unroll
            for(int i=0;i<4;i++)
#pragma unroll
            for(int j=0;j<4;j++) acc[i][j]+=ra[i]*rb[j];
        }
        __syncthreads();
    }
#pragma unroll
    for(int i=0;i<4;i++){
        int gr=bm+ty*4+i; if(gr>=M) continue;
#pragma unroll
        for(int j=0;j<4;j++){
            int gc=bn+tx*4+j; if(gc>=N) continue;
            float v=acc[i][j];
            if(bias) v+=bias[gc];
            if(ACT==ACT_SILU) v=v/(1.f+expf(-v));
            C[(long)gr*ldc+gc]=v;
        }
    }
}

// ---- LayerNorm D=1024 -> split or fp32 ----
template<bool AFFINE,bool SPLIT>
__global__ void __launch_bounds__(256) ln_k(const float* __restrict__ x,
    float* __restrict__ y, bf* __restrict__ yH, bf* __restrict__ yL,
    const float* __restrict__ g, const float* __restrict__ b)
{
    long row=blockIdx.x; const float* xr=x+row*D_; int t=threadIdx.x;
    float v[4], s=0.f;
#pragma unroll
    for(int i=0;i<4;i++){ v[i]=xr[t+i*256]; s+=v[i]; }
    __shared__ float red[256];
    red[t]=s; __syncthreads();
    for(int o=128;o>0;o>>=1){ if(t<o) red[t]+=red[t+o]; __syncthreads(); }
    float m=red[0]*(1.f/D_); __syncthreads();
    float vs=0.f;
#pragma unroll
    for(int i=0;i<4;i++){ float d=v[i]-m; vs+=d*d; }
    red[t]=vs; __syncthreads();
    for(int o=128;o>0;o>>=1){ if(t<o) red[t]+=red[t+o]; __syncthreads(); }
    float rs=1.f/sqrtf(red[0]*(1.f/D_)+1e-5f);
#pragma unroll
    for(int i=0;i<4;i++){
        int c=t+i*256; float o=(v[i]-m)*rs;
        if(AFFINE) o=o*g[c]+b[c];
        if(SPLIT){ bf h,l; sp2(o,h,l); yH[row*D_+c]=h; yL[row*D_+c]=l; }
        else y[row*D_+c]=o;
    }
}

// ---- softmax 1024 -> split ----
__global__ void __launch_bounds__(256) softmax_k(const float* __restrict__ x,
    bf* __restrict__ pH, bf* __restrict__ pL)
{
    long row=blockIdx.x; const float* p=x+row*N1_; int t=threadIdx.x;
    float v[4], mx=-1e30f;
#pragma unroll
    for(int i=0;i<4;i++){ v[i]=p[t+i*256]; mx=fmaxf(mx,v[i]); }
    __shared__ float red[256];
    red[t]=mx; __syncthreads();
    for(int o=128;o>0;o>>=1){ if(t<o) red[t]=fmaxf(red[t],red[t+o]); __syncthreads(); }
    mx=red[0]; __syncthreads();
    float s=0.f;
#pragma unroll
    for(int i=0;i<4;i++){ v[i]=expf(v[i]-mx); s+=v[i]; }
    red[t]=s; __syncthreads();
    for(int o=128;o>0;o>>=1){ if(t<o) red[t]+=red[t+o]; __syncthreads(); }
    float inv=1.f/red[0];
#pragma unroll
    for(int i=0;i<4;i++){
        int c=t+i*256; bf h,l; sp2(v[i]*inv,h,l);
        pH[row*N1_+c]=h; pL[row*N1_+c]=l;
    }
}

// ---- split / gelu-split ----
__global__ void split_k(const float* __restrict__ s, bf* __restrict__ h, bf* __restrict__ l, int n)
{
    int i=blockIdx.x*blockDim.x+threadIdx.x;
    if(i>=n) return;
    bf hh,ll; sp2(s[i],hh,ll); h[i]=hh; l[i]=ll;
}
__global__ void gsplit_k(const float* __restrict__ s, bf* __restrict__ h, bf* __restrict__ l, int n)
{
    int i=blockIdx.x*blockDim.x+threadIdx.x;
    if(i>=n) return;
    float v=s[i];
    v = 0.5f*v*(1.f+erff(v*0.70710678118654752f));
    bf hh,ll; sp2(v,hh,ll); h[i]=hh; l[i]=ll;
}

// ---- transpose bf16 pairs [R][C] -> [C][R], z-batched ----
__global__ void btransp(const bf* __restrict__ ih,const bf* __restrict__ il,
                        bf* __restrict__ oh, bf* __restrict__ ol,int R,int C)
{
    __shared__ bf th[32][33], tl[32][33];
    long zo=(long)blockIdx.z*R*C;
    int c0=blockIdx.x*32, r0=blockIdx.y*32;
    int tx=threadIdx.x, ty=threadIdx.y;
#pragma unroll
    for(int j=0;j<4;j++){
        int r=r0+ty+j*8;
        th[ty+j*8][tx]=ih[zo+(long)r*C+c0+tx];
        tl[ty+j*8][tx]=il[zo+(long)r*C+c0+tx];
    }
    __syncthreads();
#pragma unroll
    for(int j=0;j<4;j++){
        int c=c0+ty+j*8, r=r0+tx;
        oh[zo+(long)c*R+r]=th[tx][ty+j*8];
        ol[zo+(long)c*R+r]=tl[tx][ty+j*8];
    }
}

// ---- misc ----
__global__ void timestep_k(const float* __restrict__ ts, float* __restrict__ out){
    int b=blockIdx.x,i=threadIdx.x;
    int j=(i<160)?i:(i-160);
    float f=expf(-logf(10000.f)*(float)j/160.f);
    double a=(double)(ts[b]*f);
    out[b*TD_+i]=(i<160)?(float)cos(a):(float)sin(a);
}
__global__ void silu_split_k(const float* __restrict__ x,float* __restrict__ y,
                             bf* __restrict__ yH,bf* __restrict__ yL,int n){
    int i=blockIdx.x*blockDim.x+threadIdx.x;
    if(i<n){ float v=x[i]; v=v/(1.f+expf(-v)); y[i]=v;
        bf h,l; sp2(v,h,l); yH[i]=h; yL[i]=l; }
}
__global__ void bcast_k(const float* __restrict__ s,float* __restrict__ d,int n,int per){
    int i=blockIdx.x*blockDim.x+threadIdx.x;
    if(i<n) d[i]=s[i%per];
}
__global__ void modulate_k(const float* __restrict__ q,const float* __restrict__ ada,int loff,
                           bf* __restrict__ qH,bf* __restrict__ qL){
    int i=blockIdx.x*blockDim.x+threadIdx.x;
    if(i>=BS_*NQ_*D_) return;
    int b=i/(NQ_*D_), c=i&(D_-1);
    const float* ap=ada+(long)b*ADAW+loff;
    float v=q[i]*(1.f+ap[2*D_+c])+ap[c];
    bf h,l; sp2(v,h,l); qH[i]=h; qL[i]=l;
}

// ---- host ----
#define GSA(p,s) cudaGetSymbolAddress((void**)&p,s)
static inline dim3 tg(int M,int N,int z){ return dim3((unsigned)((N+127)/128),(unsigned)((M+127)/128),(unsigned)z); }
static bf* NB_=nullptr;

extern "C" void kernel_launch(void* const* d_in, const int* in_sizes, int n_in,
                              void* d_out, int out_size)
{
    const float *in_x=(const float*)d_in[0], *in_ts=(const float*)d_in[1], *in_lat=(const float*)d_in[2];
    const float *te_w1=(const float*)d_in[3], *te_b1=(const float*)d_in[4];
    const float *te_w2=(const float*)d_in[5], *te_b2=(const float*)d_in[6];
    const float *pin_w=(const float*)d_in[7], *pin_b=(const float*)d_in[8];
    const float *ln1_g=(const float*)d_in[9], *ln1_b=(const float*)d_in[10];
    const float *ln2_g=(const float*)d_in[11], *ln2_b=(const float*)d_in[12];
    const float *wq=(const float*)d_in[13], *wkv=(const float*)d_in[14], *wo=(const float*)d_in[15];
    const float *flg=(const float*)d_in[16], *flb=(const float*)d_in[17];
    const float *fw1=(const float*)d_in[18], *fw2=(const float*)d_in[19];
    const float *aw=(const float*)d_in[20], *ab=(const float*)d_in[21];
    const float *pout_w=(const float*)d_in[22], *pout_b=(const float*)d_in[23];
    const float *ng=(const float*)d_in[24], *nb=(const float*)d_in[25];
    float* out=(float*)d_out;

    cudaFuncSetAttribute(mgemm<CM_STORE,3>,cudaFuncAttributeMaxDynamicSharedMemorySize,SMB);
    cudaFuncSetAttribute(mgemm<CM_ATOM,3>, cudaFuncAttributeMaxDynamicSharedMemorySize,SMB);
    cudaFuncSetAttribute(mgemm<CM_SPLIT,3>,cudaFuncAttributeMaxDynamicSharedMemorySize,SMB);
    cudaFuncSetAttribute(mgemm64<CM_STORE>,cudaFuncAttributeMaxDynamicSharedMemorySize,SMB64);
    cudaFuncSetAttribute(mgemm64<CM_SPLIT>,cudaFuncAttributeMaxDynamicSharedMemorySize,SMB64);
    cudaFuncSetAttribute(mgemm32,cudaFuncAttributeMaxDynamicSharedMemorySize,2*SM32S);

    float *xp,*temb0,*temb1,*temb,*stemb,*ada,*lat,*att,*hff,*zacc;
    GSA(xp,g_xp); GSA(temb0,g_temb0); GSA(temb1,g_temb1); GSA(temb,g_temb);
    GSA(stemb,g_stemb); GSA(ada,g_ada); GSA(lat,g_lat);
    GSA(att,g_att); GSA(hff,g_hff); GSA(zacc,g_zacc);
    float* q    = zacc;
    float* vout = zacc + (long)BS_*NQ_*D_;
    float* h1   = zacc + (long)2*BS_*NQ_*D_;
    bf *inxH,*inxL,*pinH,*pinL,*xnH,*xnL,*xnTH,*xnTL,*latnH,*latnL,*qH,*qL,*qpH,*qpL;
    bf *attH,*attL,*ovH,*ovL,*voH,*voL,*hffH,*hffL,*h1H,*h1L,*latH,*latL,*stH,*stL;
    bf *wqH,*wqL,*kvH,*kvL,*kvTH,*kvTL,*woH,*woL,*f1H,*f1L,*f2H,*f2L,*awH,*awL,*poH,*poL;
    GSA(inxH,s_inxH); GSA(inxL,s_inxL); GSA(pinH,s_pinH); GSA(pinL,s_pinL);
    GSA(xnH,s_xnH); GSA(xnL,s_xnL); GSA(xnTH,s_xnTH); GSA(xnTL,s_xnTL);
    GSA(latnH,s_latnH); GSA(latnL,s_latnL); GSA(qH,s_qH); GSA(qL,s_qL);
    GSA(qpH,s_qpH); GSA(qpL,s_qpL); GSA(attH,s_attH); GSA(attL,s_attL);
    GSA(ovH,s_ovH); GSA(ovL,s_ovL); GSA(voH,s_voH); GSA(voL,s_voL);
    GSA(hffH,s_hffH); GSA(hffL,s_hffL); GSA(h1H,s_h1H); GSA(h1L,s_h1L);
    GSA(latH,s_latH); GSA(latL,s_latL); GSA(stH,s_stH); GSA(stL,s_stL);
    GSA(wqH,s_wqH); GSA(wqL,s_wqL); GSA(kvH,s_kvH); GSA(kvL,s_kvL);
    GSA(kvTH,s_kvTH); GSA(kvTL,s_kvTL); GSA(woH,s_woH); GSA(woL,s_woL);
    GSA(f1H,s_f1H); GSA(f1L,s_f1L); GSA(f2H,s_f2H); GSA(f2L,s_f2L);
    GSA(awH,s_awH); GSA(awL,s_awL); GSA(poH,s_poH); GSA(poL,s_poL);

    // launch 0: ALL prep in one kernel
    Segs S; int nbk=0; int si=0;
    auto addT=[&](const float* s, bf* h, bf* l, int K,int N,int z){
        S.src[si]=s;S.dh[si]=h;S.dl[si]=l;S.K[si]=K;S.N[si]=N;S.mode[si]=0;
        S.bstart[si]=nbk; nbk+=(N/32)*(K/32)*z; si++;
    };
    auto addS2=[&](const float* s, bf* h, bf* l, long n){
        S.src[si]=s;S.dh[si]=h;S.dl[si]=l;S.K[si]=(int)(n/2048);S.N[si]=1;S.mode[si]=1;
        S.bstart[si]=nbk; nbk+=(int)(n/2048); si++;
    };
    addT(pin_w,pinH,pinL,ED_,D_,1);
    addT(wq,wqH,wqL,D_,INNER,DEPTH);
    addT(wkv,kvTH,kvTL,D_,2*INNER,DEPTH);
    addT(wo,woH,woL,INNER,D_,DEPTH);
    addT(fw1,f1H,f1L,D_,FF_,DEPTH);
    addT(fw2,f2H,f2L,FF_,D_,DEPTH);
    addT(aw,awH,awL,D_,4*D_,DEPTH);
    addT(pout_w,poH,poL,D_,D_,1);
    addS2(wkv,kvH,kvL,(long)DEPTH*D_*2*INNER);
    addS2(in_x,inxH,inxL,(long)BS_*N1_*ED_);
    S.nseg=si; S.bstart[si]=nbk;
    prep_all<<<nbk,dim3(32,8)>>>(S);

    // launches 1,2
    timestep_k<<<BS_,TD_>>>(in_ts,temb0);
    gemm_s<ACT_SILU><<<dim3(16,1),256>>>(BS_,D_,TD_,temb0,TD_,te_w1,D_,temb1,D_,te_b1);

    // launch 3: proj_in (profiled at idx 5)
    mgemm<CM_STORE,3><<<tg(BS_*N1_,D_,1),256,SMB>>>(
        BS_*N1_,D_,ED_,1, inxH,inxL,ED_,0, pinH,pinL,ED_,0,
        xp,NB_,NB_,D_,0, pin_b,nullptr,1.f);

    gemm_s<ACT_NONE><<<dim3(16,1),256>>>(BS_,D_,D_,temb1,D_,te_w2,D_,temb,D_,te_b2);
    silu_split_k<<<(BS_*D_+255)/256,256>>>(temb,stemb,stH,stL,BS_*D_);

    // batched adaLN for ALL layers (BM=32)
    mgemm32<<<ADAW/128,256,2*SM32S>>>(ADAW,D_, stH,stL,D_, awH,awL,D_, ada,ADAW, ab);

    ln_k<false,true><<<BS_*N1_,256>>>(xp,nullptr,xnH,xnL,nullptr,nullptr);
    btransp<<<dim3(D_/32,N1_/32,BS_),dim3(32,8)>>>(xnH,xnL,xnTH,xnTL,N1_,D_);
    bcast_k<<<(BS_*NQ_*D_+255)/256,256>>>(in_lat,lat,BS_*NQ_*D_,NQ_*D_);

    for(int l=0;l<DEPTH;l++){
        const float *g1=ln1_g+l*D_, *b1=ln1_b+l*D_, *g2=ln2_g+l*D_, *b2=ln2_b+l*D_;
        const float *fg=flg+l*D_, *fb=flb+l*D_;
        const bf *wqh=wqH+(long)l*INNER*D_, *wql=wqL+(long)l*INNER*D_;
        const bf *kvh=kvH+(long)l*D_*2*INNER, *kvl=kvL+(long)l*D_*2*INNER;
        const bf *kvth=kvTH+(long)l*2*INNER*D_, *kvtl=kvTL+(long)l*2*INNER*D_;
        const bf *woh=woH+(long)l*D_*INNER, *wol=woL+(long)l*D_*INNER;
        const bf *f1h=f1H+(long)l*FF_*D_, *f1l=f1L+(long)l*FF_*D_;
        const bf *f2h=f2H+(long)l*D_*FF_, *f2l=f2L+(long)l*D_*FF_;

        cudaMemsetAsync(zacc,0,(size_t)BS_*NQ_*(2*D_+FF_)*sizeof(float),0);

        // latn -> q (split-K=16) -> modulate+split
        ln_k<true,true><<<BS_*NQ_,256>>>(lat,nullptr,latnH,latnL,g2,b2);
        mgemm<CM_ATOM,3><<<tg(BS_*NQ_,INNER,16),256,SMB>>>(
            BS_*NQ_,INNER,D_,16, latnH,latnL,D_,0, wqh,wql,D_,0,
            q,NB_,NB_,INNER,0, nullptr,nullptr,1.f);
        modulate_k<<<(BS_*NQ_*D_+255)/256,256>>>(q,ada,l*4*D_,qH,qL);

        // qp(split out, ⊙g1) = SCALE * qmod_h @ wk_h^T (z=heads)
        mgemm<CM_SPLIT,3><<<tg(BS_*NQ_,D_,H_),256,SMB>>>(
            BS_*NQ_,D_,DH_,1, qH,qL,INNER,64, kvh,kvl,2*INNER,64,
            nullptr,qpH,qpL,H_*D_,(long)D_, nullptr,g1,SCALE_);

        // logits = qp' @ xn^T (2-pass, BK=64)
        mgemm64<CM_STORE><<<dim3(N1_/128,1,BS_),256,SMB64>>>(
            D_, qpH,qpL,D_,(long)NQ_*H_*D_, xnH,D_,(long)N1_*D_,
            att,NB_,NB_,N1_,(long)NQ_*H_*N1_, nullptr,nullptr,1.f);
        softmax_k<<<BS_*NQ_*H_,256>>>(att,attH,attL);

        // ov(split out, g1*x+b1) = attn @ xn (2-pass, BK=64, via xnT)
        mgemm64<CM_SPLIT><<<dim3(D_/128,1,BS_),256,SMB64>>>(
            N1_, attH,attL,N1_,(long)NQ_*H_*N1_, xnTH,N1_,(long)D_*N1_,
            nullptr,ovH,ovL,D_,(long)NQ_*H_*D_, b1,g1,1.f);

        // vout = ovm_h @ wv_h (z=heads, split-K=8)
        mgemm<CM_ATOM,3><<<tg(BS_*NQ_,DH_,H_*8),256,SMB>>>(
            BS_*NQ_,DH_,D_,8, ovH,ovL,H_*D_,(long)D_, kvth+(long)INNER*D_,kvtl+(long)INNER*D_,D_,(long)64*D_,
            vout,NB_,NB_,D_,64, nullptr,nullptr,1.f);
        split_k<<<(BS_*NQ_*D_+255)/256,256>>>(vout,voH,voL,BS_*NQ_*D_);

        // lat += vout @ wo (split-K=16)
        mgemm<CM_ATOM,3><<<tg(BS_*NQ_,D_,16),256,SMB>>>(
            BS_*NQ_,D_,INNER,16, voH,voL,INNER,0, woh,wol,INNER,0,
            lat,NB_,NB_,D_,0, nullptr,nullptr,1.f);

        // FF: h1 raw (split-K=4) -> GELU+split -> ff2 (split-K=16)
        ln_k<true,true><<<BS_*NQ_,256>>>(lat,nullptr,hffH,hffL,fg,fb);
        mgemm<CM_ATOM,3><<<tg(BS_*NQ_,FF_,4),256,SMB>>>(
            BS_*NQ_,FF_,D_,4, hffH,hffL,D_,0, f1h,f1l,D_,0,
            h1,NB_,NB_,FF_,0, nullptr,nullptr,1.f);
        gsplit_k<<<(BS_*NQ_*FF_+255)/256,256>>>(h1,h1H,h1L,BS_*NQ_*FF_);
        mgemm<CM_ATOM,3><<<tg(BS_*NQ_,D_,16),256,SMB>>>(
            BS_*NQ_,D_,FF_,16, h1H,h1L,FF_,0, f2h,f2l,FF_,0,
            lat,NB_,NB_,D_,0, nullptr,nullptr,1.f);
    }

    // ---- proj_out (split-K=16) + final LN ----
    split_k<<<(BS_*NQ_*D_+255)/256,256>>>(lat,latH,latL,BS_*NQ_*D_);
    cudaMemsetAsync(hff,0,(size_t)BS_*NQ_*D_*sizeof(float),0);
    mgemm<CM_ATOM,3><<<tg(BS_*NQ_,D_,16),256,SMB>>>(
        BS_*NQ_,D_,D_,16, latH,latL,D_,0, poH,poL,D_,0,
        hff,NB_,NB_,D_,0, pout_b,nullptr,1.f);
    ln_k<true,false><<<BS_*NQ_,256>>>(hff,out,nullptr,nullptr,ng,nb);
}

// round 16
// speedup vs baseline: 1.1757x; 1.0207x over previous
#include <cuda_runtime.h>
#include <cuda_bf16.h>
#include <math.h>
#include <stdint.h>

#define D_    1024
#define DEPTH 8
#define H_    16
#define DH_   64
#define INNER 1024
#define NQ_   8
#define ED_   768
#define FF_   4096
#define TD_   320
#define BS_   32
#define N1_   1024
#define SCALE_ 0.125f
#define ADAW  32768

#define ACT_NONE 0
#define ACT_SILU 1
#define CM_STORE 0
#define CM_ATOM  1
#define CM_SPLIT 2

typedef __nv_bfloat16 bf;

// ---- fp32 scratch ----
__device__ float g_xp[BS_*N1_*D_];
__device__ float g_temb0[BS_*TD_];
__device__ float g_temb1[BS_*D_];
__device__ float g_temb[BS_*D_];
__device__ float g_stemb[BS_*D_];
__device__ float g_ada[BS_*ADAW];
__device__ float g_lat[BS_*NQ_*D_];
__device__ float g_att[BS_*NQ_*H_*N1_];
__device__ float g_hff[BS_*NQ_*D_];
__device__ float g_zacc[BS_*NQ_*(2*D_+FF_)];

// ---- bf16 hi/lo pairs ----
__device__ bf s_inxH[BS_*N1_*ED_],  s_inxL[BS_*N1_*ED_];
__device__ bf s_pinH[D_*ED_],       s_pinL[D_*ED_];
__device__ bf s_xnH[BS_*N1_*D_],    s_xnL[BS_*N1_*D_];
__device__ bf s_xnTH[BS_*D_*N1_],   s_xnTL[BS_*D_*N1_];
__device__ bf s_latnH[BS_*NQ_*D_],  s_latnL[BS_*NQ_*D_];
__device__ bf s_qH[BS_*NQ_*D_],     s_qL[BS_*NQ_*D_];
__device__ bf s_qpH[BS_*NQ_*H_*D_], s_qpL[BS_*NQ_*H_*D_];
__device__ bf s_attH[BS_*NQ_*H_*N1_], s_attL[BS_*NQ_*H_*N1_];
__device__ bf s_ovH[BS_*NQ_*H_*D_], s_ovL[BS_*NQ_*H_*D_];
__device__ bf s_voH[BS_*NQ_*D_],    s_voL[BS_*NQ_*D_];
__device__ bf s_hffH[BS_*NQ_*D_],   s_hffL[BS_*NQ_*D_];
__device__ bf s_h1H[BS_*NQ_*FF_],   s_h1L[BS_*NQ_*FF_];
__device__ bf s_latH[BS_*NQ_*D_],   s_latL[BS_*NQ_*D_];
__device__ bf s_stH[BS_*D_],        s_stL[BS_*D_];
__device__ bf s_wqH[DEPTH*INNER*D_],  s_wqL[DEPTH*INNER*D_];
__device__ bf s_kvH[DEPTH*D_*2*INNER],s_kvL[DEPTH*D_*2*INNER];
__device__ bf s_kvTH[DEPTH*2*INNER*D_],s_kvTL[DEPTH*2*INNER*D_];
__device__ bf s_woH[DEPTH*D_*INNER],  s_woL[DEPTH*D_*INNER];
__device__ bf s_f1H[DEPTH*FF_*D_],    s_f1L[DEPTH*FF_*D_];
__device__ bf s_f2H[DEPTH*D_*FF_],    s_f2L[DEPTH*D_*FF_];
__device__ bf s_awH[DEPTH*4*D_*D_],   s_awL[DEPTH*4*D_*D_];
__device__ bf s_poH[D_*D_],           s_poL[D_*D_];

// ---- helpers ----
__device__ __forceinline__ uint32_t smem_u32(const void* p){
    uint32_t a;
    asm("{ .reg .u64 t; cvta.to.shared.u64 t, %1; cvt.u32.u64 %0, t; }":"=r"(a):"l"(p));
    return a;
}
__device__ __forceinline__ void sp2(float v, bf& h, bf& l){
    h = __float2bfloat16_rn(v);
    l = __float2bfloat16_rn(v - __bfloat162float(h));
}
#define CPA(d,s) asm volatile("cp.async.cg.shared.global [%0],[%1],16;"::"r"(d),"l"(s):"memory")
#define CPC()    asm volatile("cp.async.commit_group;":::"memory")
#define CPW(n)   asm volatile("cp.async.wait_group %0;"::"n"(n):"memory")
#define LDSM4(r,a) asm volatile("ldmatrix.sync.aligned.m8n8.x4.shared.b16 {%0,%1,%2,%3},[%4];" \
    :"=r"((r)[0]),"=r"((r)[1]),"=r"((r)[2]),"=r"((r)[3]):"r"(a))
#define MMA(d,a,b) asm volatile("mma.sync.aligned.m16n8k16.row.col.f32.bf16.bf16.f32 " \
    "{%0,%1,%2,%3},{%4,%5,%6,%7},{%8,%9},{%0,%1,%2,%3};" \
    :"+f"((d)[0]),"+f"((d)[1]),"+f"((d)[2]),"+f"((d)[3]) \
    :"r"((a)[0]),"r"((a)[1]),"r"((a)[2]),"r"((a)[3]),"r"((b)[0]),"r"((b)[1]))

// ---- bf16 tensor GEMM: BK=32; NPASS=3: AhBh+AhBl+AlBh, NPASS=2: AhBh+AlBh ----
#define SMB 81920
template<int CMODE,int NPASS>
__global__ void __launch_bounds__(256,2) mgemm(
    int M,int N,int K,int ksplit,
    const bf* __restrict__ Ah,const bf* __restrict__ Al,int lda,long sAz,
    const bf* __restrict__ Bh,const bf* __restrict__ Bl,int ldb,long sBz,
    float* __restrict__ C, bf* __restrict__ CH, bf* __restrict__ CL, int ldc, long sCz,
    const float* __restrict__ bias, const float* __restrict__ cscale, float alpha)
{
    extern __shared__ bf sh[];
    const int t=threadIdx.x, lane=t&31, wid=t>>5;
    const int zz=blockIdx.z, batch=zz/ksplit, kp=zz-batch*ksplit;
    const int Kl=K/ksplit, koff=kp*Kl, NC=Kl>>5;
    const int bm=blockIdx.y*128, bn=blockIdx.x*128;
    const uint32_t sb = smem_u32(sh);
    const int mw=(wid>>2)*64, nw=(wid&3)*32;

    const bf* pAh[2]; const bf* pAl[2]; const bf* pBh[2]; const bf* pBl[2];
    uint32_t dst[2];
#pragma unroll
    for(int i=0;i<2;i++){
        int f=t+i*256, row=f>>2, ch=(f&3)*8;
        long ao=(long)batch*sAz + (long)(bm+row)*lda + koff + ch;
        pAh[i]=Ah+ao; pAl[i]=Al+ao;
        int rn=bn+row; if(rn>=N) rn=N-1;
        long bo=(long)batch*sBz + (long)rn*ldb + koff + ch;
        pBh[i]=Bh+bo; pBl[i]=Bl+bo;
        dst[i]=sb+(uint32_t)(row*40+ch)*2u;
    }

    float acc[4][4][4];
#pragma unroll
    for(int a=0;a<4;a++)
#pragma unroll
    for(int b=0;b<4;b++)
#pragma unroll
    for(int c=0;c<4;c++) acc[a][b][c]=0.f;

    auto fill=[&](int st){
        uint32_t so=(uint32_t)st*40960u;
#pragma unroll
        for(int i=0;i<2;i++){
            uint32_t d0=dst[i]+so;
            CPA(d0,       pAh[i]);
            CPA(d0+10240, pAl[i]);
            CPA(d0+20480, pBh[i]);
            if(NPASS==3) CPA(d0+30720, pBl[i]);
            pAh[i]+=32; pAl[i]+=32; pBh[i]+=32;
            if(NPASS==3) pBl[i]+=32;
        }
        CPC();
    };

    fill(0);
    for(int c=0;c<NC;c++){
        int st=c&1;
        CPW(0);
        __syncthreads();
        if(c+1<NC) fill(st^1);
        uint32_t base = sb + st*40960u;
#pragma unroll
        for(int ks=0;ks<2;ks++){
            uint32_t kadd = (uint32_t)(ks*32 + (lane>>4)*16);
            uint32_t Af[4][4], Bh2[4][2];
#pragma unroll
            for(int mt=0;mt<4;mt++)
                LDSM4(Af[mt], base + (uint32_t)(mw+mt*16+(lane&15))*80u + kadd);
#pragma unroll
            for(int np=0;np<2;np++){
                uint32_t qq[4];
                LDSM4(qq, base+20480u + (uint32_t)(nw+np*16+(lane&15))*80u + kadd);
                Bh2[np*2][0]=qq[0]; Bh2[np*2][1]=qq[2];
                Bh2[np*2+1][0]=qq[1]; Bh2[np*2+1][1]=qq[3];
            }
#pragma unroll
            for(int mt=0;mt<4;mt++)
#pragma unroll
            for(int nt=0;nt<4;nt++) MMA(acc[mt][nt],Af[mt],Bh2[nt]);
            if(NPASS==3){
                uint32_t Bl2[4][2];
#pragma unroll
                for(int np=0;np<2;np++){
                    uint32_t qq[4];
                    LDSM4(qq, base+30720u + (uint32_t)(nw+np*16+(lane&15))*80u + kadd);
                    Bl2[np*2][0]=qq[0]; Bl2[np*2][1]=qq[2];
                    Bl2[np*2+1][0]=qq[1]; Bl2[np*2+1][1]=qq[3];
                }
#pragma unroll
                for(int mt=0;mt<4;mt++)
#pragma unroll
                for(int nt=0;nt<4;nt++) MMA(acc[mt][nt],Af[mt],Bl2[nt]);
            }
#pragma unroll
            for(int mt=0;mt<4;mt++)
                LDSM4(Af[mt], base+10240u + (uint32_t)(mw+mt*16+(lane&15))*80u + kadd);
#pragma unroll
            for(int mt=0;mt<4;mt++)
#pragma unroll
            for(int nt=0;nt<4;nt++) MMA(acc[mt][nt],Af[mt],Bh2[nt]);
        }
    }

    const bool dob = bias && (CMODE!=CM_ATOM || kp==0);
#pragma unroll
    for(int mt=0;mt<4;mt++)
#pragma unroll
    for(int nt=0;nt<4;nt++){
        int gc = bn+nw+nt*8+(lane&3)*2;
#pragma unroll
        for(int rr=0;rr<2;rr++){
            int gr = bm+mw+mt*16+(lane>>2)+rr*8;
            if(gr>=M) continue;
#pragma unroll
            for(int cc=0;cc<2;cc++){
                int c2=gc+cc;
                if(c2>=N) continue;
                float v = acc[mt][nt][rr*2+cc]*alpha;
                if(cscale) v *= cscale[c2];
                if(dob) v += bias[c2];
                long off=(long)batch*sCz + (long)gr*ldc + c2;
                if(CMODE==CM_ATOM) atomicAdd(&C[off],v);
                else if(CMODE==CM_STORE) C[off]=v;
                else { bf h,l; sp2(v,h,l); CH[off]=h; CL[off]=l; }
            }
        }
    }
}

// ---- BK=64 2-pass GEMM (logits/ov) ----
#define S64  55296
#define SMB64 (2*S64)
template<int CMODE>
__global__ void __launch_bounds__(256,2) mgemm64(
    int K,
    const bf* __restrict__ Ah,const bf* __restrict__ Al,int lda,long sAz,
    const bf* __restrict__ Bh,int ldb,long sBz,
    float* __restrict__ C, bf* __restrict__ CH, bf* __restrict__ CL, int ldc, long sCz,
    const float* __restrict__ bias, const float* __restrict__ cscale, float alpha)
{
    extern __shared__ bf sh[];
    const int t=threadIdx.x, lane=t&31, wid=t>>5;
    const int batch=blockIdx.z;
    const int bm=blockIdx.y*128, bn=blockIdx.x*128;
    const uint32_t sb = smem_u32(sh);
    const int mw=(wid>>2)*64, nw=(wid&3)*32;
    const int NC=K>>6;

    const bf* pAh[4]; const bf* pAl[4]; const bf* pBh[4];
    uint32_t dst[4];
#pragma unroll
    for(int i=0;i<4;i++){
        int f=t+i*256, row=f>>3, ch=(f&7)*8;
        long ao=(long)batch*sAz + (long)(bm+row)*lda + ch;
        pAh[i]=Ah+ao; pAl[i]=Al+ao;
        long bo=(long)batch*sBz + (long)(bn+row)*ldb + ch;
        pBh[i]=Bh+bo;
        dst[i]=sb+(uint32_t)(row*144+ch*2);
    }

    float acc[4][4][4];
#pragma unroll
    for(int a=0;a<4;a++)
#pragma unroll
    for(int b=0;b<4;b++)
#pragma unroll
    for(int c=0;c<4;c++) acc[a][b][c]=0.f;

    auto fill=[&](int st){
        uint32_t so=(uint32_t)st*(uint32_t)S64;
#pragma unroll
        for(int i=0;i<4;i++){
            uint32_t d0=dst[i]+so;
            CPA(d0,        pAh[i]);
            CPA(d0+18432u, pAl[i]);
            CPA(d0+36864u, pBh[i]);
            pAh[i]+=64; pAl[i]+=64; pBh[i]+=64;
        }
        CPC();
    };

    fill(0);
    for(int c=0;c<NC;c++){
        int st=c&1;
        CPW(0);
        __syncthreads();
        if(c+1<NC) fill(st^1);
        uint32_t base = sb + st*(uint32_t)S64;
#pragma unroll
        for(int ks=0;ks<4;ks++){
            uint32_t kadd = (uint32_t)(ks*32 + (lane>>4)*16);
            uint32_t Af[4][4], Bh2[4][2];
#pragma unroll
            for(int mt=0;mt<4;mt++)
                LDSM4(Af[mt], base + (uint32_t)(mw+mt*16+(lane&15))*144u + kadd);
#pragma unroll
            for(int np=0;np<2;np++){
                uint32_t qq[4];
                LDSM4(qq, base+36864u + (uint32_t)(nw+np*16+(lane&15))*144u + kadd);
                Bh2[np*2][0]=qq[0]; Bh2[np*2][1]=qq[2];
                Bh2[np*2+1][0]=qq[1]; Bh2[np*2+1][1]=qq[3];
            }
#pragma unroll
            for(int mt=0;mt<4;mt++)
#pragma unroll
            for(int nt=0;nt<4;nt++) MMA(acc[mt][nt],Af[mt],Bh2[nt]);
#pragma unroll
            for(int mt=0;mt<4;mt++)
                LDSM4(Af[mt], base+18432u + (uint32_t)(mw+mt*16+(lane&15))*144u + kadd);
#pragma unroll
            for(int mt=0;mt<4;mt++)
#pragma unroll
            for(int nt=0;nt<4;nt++) MMA(acc[mt][nt],Af[mt],Bh2[nt]);
        }
    }

#pragma unroll
    for(int mt=0;mt<4;mt++)
#pragma unroll
    for(int nt=0;nt<4;nt++){
        int gc = bn+nw+nt*8+(lane&3)*2;
#pragma unroll
        for(int rr=0;rr<2;rr++){
            int gr = bm+mw+mt*16+(lane>>2)+rr*8;
#pragma unroll
            for(int cc=0;cc<2;cc++){
                int c2=gc+cc;
                float v = acc[mt][nt][rr*2+cc]*alpha;
                if(cscale) v *= cscale[c2];
                if(bias) v += bias[c2];
                long off=(long)batch*sCz + (long)gr*ldc + c2;
                if(CMODE==CM_STORE) C[off]=v;
                else { bf h,l; sp2(v,h,l); CH[off]=h; CL[off]=l; }
            }
        }
    }
}

// ---- BN=64 3-pass GEMM (vout): BM=128, N==64, split-K atomic, warp tile 32x32 ----
#define SV 30720
#define SMBV (2*SV)
__global__ void __launch_bounds__(256,2) mgemmV(
    int K,int ksplit,
    const bf* __restrict__ Ah,const bf* __restrict__ Al,int lda,long sAz,
    const bf* __restrict__ Bh,const bf* __restrict__ Bl,int ldb,long sBz,
    float* __restrict__ C,int ldc,long sCz)
{
    extern __shared__ bf sh[];
    const int t=threadIdx.x, lane=t&31, wid=t>>5;
    const int zz=blockIdx.z, batch=zz/ksplit, kp=zz-batch*ksplit;
    const int Kl=K/ksplit, koff=kp*Kl, NC=Kl>>5;
    const int bm=blockIdx.y*128;
    const uint32_t sb=smem_u32(sh);
    const int mw=(wid&3)*32, nw=(wid>>2)*32;

    const bf* pAh[2]; const bf* pAl[2]; const bf* pBh; const bf* pBl;
    uint32_t dstA[2], dstB;
#pragma unroll
    for(int i=0;i<2;i++){
        int f=t+i*256, row=f>>2, ch=(f&3)*8;
        long ao=(long)batch*sAz + (long)(bm+row)*lda + koff + ch;
        pAh[i]=Ah+ao; pAl[i]=Al+ao;
        dstA[i]=sb+(uint32_t)(row*40+ch)*2u;
    }
    {
        int row=t>>2, ch=(t&3)*8;
        long bo=(long)batch*sBz + (long)row*ldb + koff + ch;
        pBh=Bh+bo; pBl=Bl+bo;
        dstB=sb+(uint32_t)(row*40+ch)*2u;
    }

    float acc[2][4][4];
#pragma unroll
    for(int a=0;a<2;a++)
#pragma unroll
    for(int b=0;b<4;b++)
#pragma unroll
    for(int c=0;c<4;c++) acc[a][b][c]=0.f;

    auto fill=[&](int st){
        uint32_t so=(uint32_t)st*(uint32_t)SV;
#pragma unroll
        for(int i=0;i<2;i++){
            uint32_t d0=dstA[i]+so;
            CPA(d0,       pAh[i]);
            CPA(d0+10240, pAl[i]);
            pAh[i]+=32; pAl[i]+=32;
        }
        CPA(dstB+so+20480u, pBh);
        CPA(dstB+so+25600u, pBl);
        pBh+=32; pBl+=32;
        CPC();
    };

    fill(0);
    for(int c=0;c<NC;c++){
        int st=c&1;
        CPW(0);
        __syncthreads();
        if(c+1<NC) fill(st^1);
        uint32_t base=sb+(uint32_t)st*(uint32_t)SV;
#pragma unroll
        for(int ks=0;ks<2;ks++){
            uint32_t kadd=(uint32_t)(ks*32+(lane>>4)*16);
            uint32_t Af[2][4], Bh2[4][2];
#pragma unroll
            for(int mt=0;mt<2;mt++)
                LDSM4(Af[mt], base + (uint32_t)(mw+mt*16+(lane&15))*80u + kadd);
#pragma unroll
            for(int np=0;np<2;np++){
                uint32_t qq[4];
                LDSM4(qq, base+20480u + (uint32_t)(nw+np*16+(lane&15))*80u + kadd);
                Bh2[np*2][0]=qq[0]; Bh2[np*2][1]=qq[2];
                Bh2[np*2+1][0]=qq[1]; Bh2[np*2+1][1]=qq[3];
            }
#pragma unroll
            for(int mt=0;mt<2;mt++)
#pragma unroll
            for(int nt=0;nt<4;nt++) MMA(acc[mt][nt],Af[mt],Bh2[nt]);
            {
                uint32_t Bl2[4][2];
#pragma unroll
                for(int np=0;np<2;np++){
                    uint32_t qq[4];
                    LDSM4(qq, base+25600u + (uint32_t)(nw+np*16+(lane&15))*80u + kadd);
                    Bl2[np*2][0]=qq[0]; Bl2[np*2][1]=qq[2];
                    Bl2[np*2+1][0]=qq[1]; Bl2[np*2+1][1]=qq[3];
                }
#pragma unroll
                for(int mt=0;mt<2;mt++)
#pragma unroll
                for(int nt=0;nt<4;nt++) MMA(acc[mt][nt],Af[mt],Bl2[nt]);
            }
#pragma unroll
            for(int mt=0;mt<2;mt++)
                LDSM4(Af[mt], base+10240u + (uint32_t)(mw+mt*16+(lane&15))*80u + kadd);
#pragma unroll
            for(int mt=0;mt<2;mt++)
#pragma unroll
            for(int nt=0;nt<4;nt++) MMA(acc[mt][nt],Af[mt],Bh2[nt]);
        }
    }

#pragma unroll
    for(int mt=0;mt<2;mt++)
#pragma unroll
    for(int nt=0;nt<4;nt++){
        int gc = nw+nt*8+(lane&3)*2;
#pragma unroll
        for(int rr=0;rr<2;rr++){
            int gr = bm+mw+mt*16+(lane>>2)+rr*8;
#pragma unroll
            for(int cc=0;cc<2;cc++){
                long off=(long)batch*sCz + (long)gr*ldc + gc+cc;
                atomicAdd(&C[off], acc[mt][nt][rr*2+cc]);
            }
        }
    }
}

// ---- BM=32 bf16 GEMM (M==32) ----
#define SM32S 25600
__global__ void __launch_bounds__(256,2) mgemm32(
    int N,int K,
    const bf* __restrict__ Ah,const bf* __restrict__ Al,int lda,
    const bf* __restrict__ Bh,const bf* __restrict__ Bl,int ldb,
    float* __restrict__ C,int ldc,const float* __restrict__ bias)
{
    extern __shared__ bf sh[];
    const int t=threadIdx.x, lane=t&31, wid=t>>5;
    const int bn=blockIdx.x*128;
    const uint32_t sb=smem_u32(sh);
    const int NC=K>>5;
    float acc[2][2][4];
#pragma unroll
    for(int a=0;a<2;a++)
#pragma unroll
    for(int b=0;b<2;b++)
#pragma unroll
    for(int c=0;c<4;c++) acc[a][b][c]=0.f;

    auto fill=[&](int st,int c){
        uint32_t bs=sb+(uint32_t)st*SM32S;
        {
            int row=(t&127)>>2, ch=(t&3)*8;
            const bf* Ap=(t<128)?Ah:Al;
            uint32_t off=(t<128)?0u:2560u;
            CPA(bs+off+(uint32_t)(row*80+ch*2), Ap+(long)row*lda+c*32+ch);
        }
#pragma unroll
        for(int i=0;i<2;i++){
            int f=t+i*256, row=f>>2, ch=(f&3)*8;
            int rn=bn+row; if(rn>=N) rn=N-1;
            long bo=(long)rn*ldb+c*32+ch;
            CPA(bs+5120u+(uint32_t)(row*80+ch*2), Bh+bo);
            CPA(bs+15360u+(uint32_t)(row*80+ch*2), Bl+bo);
        }
        CPC();
    };

    fill(0,0);
    for(int c=0;c<NC;c++){
        int st=c&1;
        CPW(0);
        __syncthreads();
        if(c+1<NC) fill(st^1,c+1);
        uint32_t base=sb+(uint32_t)st*SM32S;
#pragma unroll
        for(int ks=0;ks<2;ks++){
            uint32_t kadd=(uint32_t)(ks*32+(lane>>4)*16);
            uint32_t Af[2][4], Bf[2][2], Bl2[2][2];
#pragma unroll
            for(int mt=0;mt<2;mt++)
                LDSM4(Af[mt], base + (uint32_t)((mt*16+(lane&15))*80) + kadd);
            {
                uint32_t qq[4];
                LDSM4(qq, base+5120u + (uint32_t)((wid*16+(lane&15))*80) + kadd);
                Bf[0][0]=qq[0];Bf[0][1]=qq[2];Bf[1][0]=qq[1];Bf[1][1]=qq[3];
            }
#pragma unroll
            for(int mt=0;mt<2;mt++)
#pragma unroll
            for(int nt=0;nt<2;nt++) MMA(acc[mt][nt],Af[mt],Bf[nt]);
            {
                uint32_t qq[4];
                LDSM4(qq, base+15360u + (uint32_t)((wid*16+(lane&15))*80) + kadd);
                Bl2[0][0]=qq[0];Bl2[0][1]=qq[2];Bl2[1][0]=qq[1];Bl2[1][1]=qq[3];
            }
#pragma unroll
            for(int mt=0;mt<2;mt++)
#pragma unroll
            for(int nt=0;nt<2;nt++) MMA(acc[mt][nt],Af[mt],Bl2[nt]);
#pragma unroll
            for(int mt=0;mt<2;mt++)
                LDSM4(Af[mt], base+2560u + (uint32_t)((mt*16+(lane&15))*80) + kadd);
#pragma unroll
            for(int mt=0;mt<2;mt++)
#pragma unroll
            for(int nt=0;nt<2;nt++) MMA(acc[mt][nt],Af[mt],Bf[nt]);
        }
    }
#pragma unroll
    for(int mt=0;mt<2;mt++)
#pragma unroll
    for(int nt=0;nt<2;nt++){
        int gc=bn+wid*16+nt*8+(lane&3)*2;
#pragma unroll
        for(int rr=0;rr<2;rr++){
            int gr=mt*16+(lane>>2)+rr*8;
#pragma unroll
            for(int cc=0;cc<2;cc++){
                int c2=gc+cc;
                if(c2>=N) continue;
                float v=acc[mt][nt][rr*2+cc];
                if(bias) v+=bias[c2];
                C[(long)gr*ldc+c2]=v;
            }
        }
    }
}

// ---- unified prep ----
#define NSEG 10
struct Segs {
    const float* src[NSEG]; bf* dh[NSEG]; bf* dl[NSEG];
    int K[NSEG], N[NSEG], mode[NSEG];
    int bstart[NSEG+1]; int nseg;
};
__global__ void prep_all(Segs S)
{
    __shared__ float tile[32][33];
    int b=blockIdx.x;
    int si=0;
    while(si+1<S.nseg && b>=S.bstart[si+1]) si++;
    int lb=b-S.bstart[si];
    int tx=threadIdx.x, ty=threadIdx.y;
    if(S.mode[si]==0){
        int K=S.K[si], N=S.N[si];
        int tpz=(N/32)*(K/32);
        int z=lb/tpz, rem=lb-z*tpz;
        int n0=(rem%(N/32))*32, k0=(rem/(N/32))*32;
        long zo=(long)z*K*N;
        const float* Sp=S.src[si]+zo; bf* TH=S.dh[si]+zo; bf* TL=S.dl[si]+zo;
#pragma unroll
        for(int j=0;j<4;j++)
            tile[ty+j*8][tx]=Sp[(long)(k0+ty+j*8)*N+n0+tx];
        __syncthreads();
#pragma unroll
        for(int j=0;j<4;j++){
            int n=n0+ty+j*8, k=k0+tx;
            bf h,l; sp2(tile[tx][ty+j*8],h,l);
            TH[(long)n*K+k]=h; TL[(long)n*K+k]=l;
        }
    } else {
        long n=(long)S.K[si]*2048;
        long i0=(long)lb*2048 + ty*32+tx;
#pragma unroll
        for(int j=0;j<8;j++){
            long i=i0+j*256;
            if(i<n){ bf h,l; sp2(S.src[si][i],h,l); S.dh[si][i]=h; S.dl[si][i]=l; }
        }
    }
}

// ---- SIMT fp32 GEMM (temb only) ----
template<int ACT>
__global__ void __launch_bounds__(256) gemm_s(
    int M,int N,int K,
    const float* __restrict__ A,int lda,
    const float* __restrict__ B,int ldb,
    float* __restrict__ C,int ldc,
    const float* __restrict__ bias)
{
    __shared__ float As[16][68], Bs[16][68];
    int bm=blockIdx.y*64, bn=blockIdx.x*64, t=threadIdx.x;
    int tx=t&15, ty=t>>4;
    float acc[4][4];
#pragma unroll
    for(int i=0;i<4;i++)
#pragma unroll
    for(int j=0;j<4;j++) acc[i][j]=0.f;
    for(int k0=0;k0<K;k0+=16){
#pragma unroll
        for(int i=0;i<4;i++){
            int idx=t+i*256, r=idx>>4, kk=idx&15;
            As[kk][r] = (bm+r<M)? A[(long)(bm+r)*lda+k0+kk] : 0.f;
        }
#pragma unroll
        for(int i=0;i<4;i++){
            int idx=t+i*256, kk=idx>>6, cc=idx&63;
            Bs[kk][cc] = (bn+cc<N)? B[(long)(k0+kk)*ldb+bn+cc] : 0.f;
        }
        __syncthreads();
#pragma unroll
        for(int kk=0;kk<16;kk++){
            float ra[4],rb[4];
#pragma unroll
            for(int i=0;i<4;i++) ra[i]=As[kk][ty*4+i];
#pragma unroll
            for(int j=0;j<4;j++) rb[j]=Bs[kk][tx*4+j];
#pragma unroll
            for(int i=0;i<4;i++)
#pragma unroll
            for(int j=0;j<4;j++) acc[i][j]+=ra[i]*rb[j];
        }
        __syncthreads();
    }
#pragma unroll
    for(int i=0;i<4;i++){
        int gr=bm+ty*4+i; if(gr>=M) continue;
#pragma unroll
        for(int j=0;j<4;j++){
            int gc=bn+tx*4+j; if(gc>=N) continue;
            float v=acc[i][j];
            if(bias) v+=bias[gc];
            if(ACT==ACT_SILU) v=v/(1.f+expf(-v));
            C[(long)gr*ldc+gc]=v;
        }
    }
}

// ---- LayerNorm D=1024 -> split or fp32 ----
template<bool AFFINE,bool SPLIT>
__global__ void __launch_bounds__(256) ln_k(const float* __restrict__ x,
    float* __restrict__ y, bf* __restrict__ yH, bf* __restrict__ yL,
    const float* __restrict__ g, const float* __restrict__ b)
{
    long row=blockIdx.x; const float* xr=x+row*D_; int t=threadIdx.x;
    float v[4], s=0.f;
#pragma unroll
    for(int i=0;i<4;i++){ v[i]=xr[t+i*256]; s+=v[i]; }
    __shared__ float red[256];
    red[t]=s; __syncthreads();
    for(int o=128;o>0;o>>=1){ if(t<o) red[t]+=red[t+o]; __syncthreads(); }
    float m=red[0]*(1.f/D_); __syncthreads();
    float vs=0.f;
#pragma unroll
    for(int i=0;i<4;i++){ float d=v[i]-m; vs+=d*d; }
    red[t]=vs; __syncthreads();
    for(int o=128;o>0;o>>=1){ if(t<o) red[t]+=red[t+o]; __syncthreads(); }
    float rs=1.f/sqrtf(red[0]*(1.f/D_)+1e-5f);
#pragma unroll
    for(int i=0;i<4;i++){
        int c=t+i*256; float o=(v[i]-m)*rs;
        if(AFFINE) o=o*g[c]+b[c];
        if(SPLIT){ bf h,l; sp2(o,h,l); yH[row*D_+c]=h; yL[row*D_+c]=l; }
        else y[row*D_+c]=o;
    }
}

// ---- softmax 1024 -> split ----
__global__ void __launch_bounds__(256) softmax_k(const float* __restrict__ x,
    bf* __restrict__ pH, bf* __restrict__ pL)
{
    long row=blockIdx.x; const float* p=x+row*N1_; int t=threadIdx.x;
    float v[4], mx=-1e30f;
#pragma unroll
    for(int i=0;i<4;i++){ v[i]=p[t+i*256]; mx=fmaxf(mx,v[i]); }
    __shared__ float red[256];
    red[t]=mx; __syncthreads();
    for(int o=128;o>0;o>>=1){ if(t<o) red[t]=fmaxf(red[t],red[t+o]); __syncthreads(); }
    mx=red[0]; __syncthreads();
    float s=0.f;
#pragma unroll
    for(int i=0;i<4;i++){ v[i]=expf(v[i]-mx); s+=v[i]; }
    red[t]=s; __syncthreads();
    for(int o=128;o>0;o>>=1){ if(t<o) red[t]+=red[t+o]; __syncthreads(); }
    float inv=1.f/red[0];
#pragma unroll
    for(int i=0;i<4;i++){
        int c=t+i*256; bf h,l; sp2(v[i]*inv,h,l);
        pH[row*N1_+c]=h; pL[row*N1_+c]=l;
    }
}

// ---- split / gelu-split ----
__global__ void split_k(const float* __restrict__ s, bf* __restrict__ h, bf* __restrict__ l, int n)
{
    int i=blockIdx.x*blockDim.x+threadIdx.x;
    if(i>=n) return;
    bf hh,ll; sp2(s[i],hh,ll); h[i]=hh; l[i]=ll;
}
__global__ void gsplit_k(const float* __restrict__ s, bf* __restrict__ h, bf* __restrict__ l, int n)
{
    int i=blockIdx.x*blockDim.x+threadIdx.x;
    if(i>=n) return;
    float v=s[i];
    v = 0.5f*v*(1.f+erff(v*0.70710678118654752f));
    bf hh,ll; sp2(v,hh,ll); h[i]=hh; l[i]=ll;
}

// ---- transpose bf16 pairs ----
__global__ void btransp(const bf* __restrict__ ih,const bf* __restrict__ il,
                        bf* __restrict__ oh, bf* __restrict__ ol,int R,int C)
{
    __shared__ bf th[32][33], tl[32][33];
    long zo=(long)blockIdx.z*R*C;
    int c0=blockIdx.x*32, r0=blockIdx.y*32;
    int tx=threadIdx.x, ty=threadIdx.y;
#pragma unroll
    for(int j=0;j<4;j++){
        int r=r0+ty+j*8;
        th[ty+j*8][tx]=ih[zo+(long)r*C+c0+tx];
        tl[ty+j*8][tx]=il[zo+(long)r*C+c0+tx];
    }
    __syncthreads();
#pragma unroll
    for(int j=0;j<4;j++){
        int c=c0+ty+j*8, r=r0+tx;
        oh[zo+(long)c*R+r]=th[tx][ty+j*8];
        ol[zo+(long)c*R+r]=tl[tx][ty+j*8];
    }
}

// ---- misc ----
__global__ void timestep_k(const float* __restrict__ ts, float* __restrict__ out){
    int b=blockIdx.x,i=threadIdx.x;
    int j=(i<160)?i:(i-160);
    float f=expf(-logf(10000.f)*(float)j/160.f);
    double a=(double)(ts[b]*f);
    out[b*TD_+i]=(i<160)?(float)cos(a):(float)sin(a);
}
__global__ void silu_split_k(const float* __restrict__ x,float* __restrict__ y,
                             bf* __restrict__ yH,bf* __restrict__ yL,int n){
    int i=blockIdx.x*blockDim.x+threadIdx.x;
    if(i<n){ float v=x[i]; v=v/(1.f+expf(-v)); y[i]=v;
        bf h,l; sp2(v,h,l); yH[i]=h; yL[i]=l; }
}
__global__ void bcast_k(const float* __restrict__ s,float* __restrict__ d,int n,int per){
    int i=blockIdx.x*blockDim.x+threadIdx.x;
    if(i<n) d[i]=s[i%per];
}
__global__ void modulate_k(const float* __restrict__ q,const float* __restrict__ ada,int loff,
                           bf* __restrict__ qH,bf* __restrict__ qL){
    int i=blockIdx.x*blockDim.x+threadIdx.x;
    if(i>=BS_*NQ_*D_) return;
    int b=i/(NQ_*D_), c=i&(D_-1);
    const float* ap=ada+(long)b*ADAW+loff;
    float v=q[i]*(1.f+ap[2*D_+c])+ap[c];
    bf h,l; sp2(v,h,l); qH[i]=h; qL[i]=l;
}

// ---- host ----
#define GSA(p,s) cudaGetSymbolAddress((void**)&p,s)
static inline dim3 tg(int M,int N,int z){ return dim3((unsigned)((N+127)/128),(unsigned)((M+127)/128),(unsigned)z); }
static bf* NB_=nullptr;

extern "C" void kernel_launch(void* const* d_in, const int* in_sizes, int n_in,
                              void* d_out, int out_size)
{
    const float *in_x=(const float*)d_in[0], *in_ts=(const float*)d_in[1], *in_lat=(const float*)d_in[2];
    const float *te_w1=(const float*)d_in[3], *te_b1=(const float*)d_in[4];
    const float *te_w2=(const float*)d_in[5], *te_b2=(const float*)d_in[6];
    const float *pin_w=(const float*)d_in[7], *pin_b=(const float*)d_in[8];
    const float *ln1_g=(const float*)d_in[9], *ln1_b=(const float*)d_in[10];
    const float *ln2_g=(const float*)d_in[11], *ln2_b=(const float*)d_in[12];
    const float *wq=(const float*)d_in[13], *wkv=(const float*)d_in[14], *wo=(const float*)d_in[15];
    const float *flg=(const float*)d_in[16], *flb=(const float*)d_in[17];
    const float *fw1=(const float*)d_in[18], *fw2=(const float*)d_in[19];
    const float *aw=(const float*)d_in[20], *ab=(const float*)d_in[21];
    const float *pout_w=(const float*)d_in[22], *pout_b=(const float*)d_in[23];
    const float *ng=(const float*)d_in[24], *nb=(const float*)d_in[25];
    float* out=(float*)d_out;

    cudaFuncSetAttribute(mgemm<CM_STORE,3>,cudaFuncAttributeMaxDynamicSharedMemorySize,SMB);
    cudaFuncSetAttribute(mgemm<CM_ATOM,3>, cudaFuncAttributeMaxDynamicSharedMemorySize,SMB);
    cudaFuncSetAttribute(mgemm<CM_SPLIT,3>,cudaFuncAttributeMaxDynamicSharedMemorySize,SMB);
    cudaFuncSetAttribute(mgemm64<CM_STORE>,cudaFuncAttributeMaxDynamicSharedMemorySize,SMB64);
    cudaFuncSetAttribute(mgemm64<CM_SPLIT>,cudaFuncAttributeMaxDynamicSharedMemorySize,SMB64);
    cudaFuncSetAttribute(mgemmV,cudaFuncAttributeMaxDynamicSharedMemorySize,SMBV);
    cudaFuncSetAttribute(mgemm32,cudaFuncAttributeMaxDynamicSharedMemorySize,2*SM32S);

    float *xp,*temb0,*temb1,*temb,*stemb,*ada,*lat,*att,*hff,*zacc;
    GSA(xp,g_xp); GSA(temb0,g_temb0); GSA(temb1,g_temb1); GSA(temb,g_temb);
    GSA(stemb,g_stemb); GSA(ada,g_ada); GSA(lat,g_lat);
    GSA(att,g_att); GSA(hff,g_hff); GSA(zacc,g_zacc);
    float* q    = zacc;
    float* vout = zacc + (long)BS_*NQ_*D_;
    float* h1   = zacc + (long)2*BS_*NQ_*D_;
    bf *inxH,*inxL,*pinH,*pinL,*xnH,*xnL,*xnTH,*xnTL,*latnH,*latnL,*qH,*qL,*qpH,*qpL;
    bf *attH,*attL,*ovH,*ovL,*voH,*voL,*hffH,*hffL,*h1H,*h1L,*latH,*latL,*stH,*stL;
    bf *wqH,*wqL,*kvH,*kvL,*kvTH,*kvTL,*woH,*woL,*f1H,*f1L,*f2H,*f2L,*awH,*awL,*poH,*poL;
    GSA(inxH,s_inxH); GSA(inxL,s_inxL); GSA(pinH,s_pinH); GSA(pinL,s_pinL);
    GSA(xnH,s_xnH); GSA(xnL,s_xnL); GSA(xnTH,s_xnTH); GSA(xnTL,s_xnTL);
    GSA(latnH,s_latnH); GSA(latnL,s_latnL); GSA(qH,s_qH); GSA(qL,s_qL);
    GSA(qpH,s_qpH); GSA(qpL,s_qpL); GSA(attH,s_attH); GSA(attL,s_attL);
    GSA(ovH,s_ovH); GSA(ovL,s_ovL); GSA(voH,s_voH); GSA(voL,s_voL);
    GSA(hffH,s_hffH); GSA(hffL,s_hffL); GSA(h1H,s_h1H); GSA(h1L,s_h1L);
    GSA(latH,s_latH); GSA(latL,s_latL); GSA(stH,s_stH); GSA(stL,s_stL);
    GSA(wqH,s_wqH); GSA(wqL,s_wqL); GSA(kvH,s_kvH); GSA(kvL,s_kvL);
    GSA(kvTH,s_kvTH); GSA(kvTL,s_kvTL); GSA(woH,s_woH); GSA(woL,s_woL);
    GSA(f1H,s_f1H); GSA(f1L,s_f1L); GSA(f2H,s_f2H); GSA(f2L,s_f2L);
    GSA(awH,s_awH); GSA(awL,s_awL); GSA(poH,s_poH); GSA(poL,s_poL);

    // launch 0: ALL prep in one kernel
    Segs S; int nbk=0; int si=0;
    auto addT=[&](const float* s, bf* h, bf* l, int K,int N,int z){
        S.src[si]=s;S.dh[si]=h;S.dl[si]=l;S.K[si]=K;S.N[si]=N;S.mode[si]=0;
        S.bstart[si]=nbk; nbk+=(N/32)*(K/32)*z; si++;
    };
    auto addS2=[&](const float* s, bf* h, bf* l, long n){
        S.src[si]=s;S.dh[si]=h;S.dl[si]=l;S.K[si]=(int)(n/2048);S.N[si]=1;S.mode[si]=1;
        S.bstart[si]=nbk; nbk+=(int)(n/2048); si++;
    };
    addT(pin_w,pinH,pinL,ED_,D_,1);
    addT(wq,wqH,wqL,D_,INNER,DEPTH);
    addT(wkv,kvTH,kvTL,D_,2*INNER,DEPTH);
    addT(wo,woH,woL,INNER,D_,DEPTH);
    addT(fw1,f1H,f1L,D_,FF_,DEPTH);
    addT(fw2,f2H,f2L,FF_,D_,DEPTH);
    addT(aw,awH,awL,D_,4*D_,DEPTH);
    addT(pout_w,poH,poL,D_,D_,1);
    addS2(wkv,kvH,kvL,(long)DEPTH*D_*2*INNER);
    addS2(in_x,inxH,inxL,(long)BS_*N1_*ED_);
    S.nseg=si; S.bstart[si]=nbk;
    prep_all<<<nbk,dim3(32,8)>>>(S);

    // launches 1,2
    timestep_k<<<BS_,TD_>>>(in_ts,temb0);
    gemm_s<ACT_SILU><<<dim3(16,1),256>>>(BS_,D_,TD_,temb0,TD_,te_w1,D_,temb1,D_,te_b1);

    // launch 3: proj_in (profiled at idx 5)
    mgemm<CM_STORE,3><<<tg(BS_*N1_,D_,1),256,SMB>>>(
        BS_*N1_,D_,ED_,1, inxH,inxL,ED_,0, pinH,pinL,ED_,0,
        xp,NB_,NB_,D_,0, pin_b,nullptr,1.f);

    gemm_s<ACT_NONE><<<dim3(16,1),256>>>(BS_,D_,D_,temb1,D_,te_w2,D_,temb,D_,te_b2);
    silu_split_k<<<(BS_*D_+255)/256,256>>>(temb,stemb,stH,stL,BS_*D_);

    // batched adaLN for ALL layers (BM=32)
    mgemm32<<<ADAW/128,256,2*SM32S>>>(ADAW,D_, stH,stL,D_, awH,awL,D_, ada,ADAW, ab);

    ln_k<false,true><<<BS_*N1_,256>>>(xp,nullptr,xnH,xnL,nullptr,nullptr);
    btransp<<<dim3(D_/32,N1_/32,BS_),dim3(32,8)>>>(xnH,xnL,xnTH,xnTL,N1_,D_);
    bcast_k<<<(BS_*NQ_*D_+255)/256,256>>>(in_lat,lat,BS_*NQ_*D_,NQ_*D_);

    for(int l=0;l<DEPTH;l++){
        const float *g1=ln1_g+l*D_, *b1=ln1_b+l*D_, *g2=ln2_g+l*D_, *b2=ln2_b+l*D_;
        const float *fg=flg+l*D_, *fb=flb+l*D_;
        const bf *wqh=wqH+(long)l*INNER*D_, *wql=wqL+(long)l*INNER*D_;
        const bf *kvh=kvH+(long)l*D_*2*INNER, *kvl=kvL+(long)l*D_*2*INNER;
        const bf *kvth=kvTH+(long)l*2*INNER*D_, *kvtl=kvTL+(long)l*2*INNER*D_;
        const bf *woh=woH+(long)l*D_*INNER, *wol=woL+(long)l*D_*INNER;
        const bf *f1h=f1H+(long)l*FF_*D_, *f1l=f1L+(long)l*FF_*D_;
        const bf *f2h=f2H+(long)l*D_*FF_, *f2l=f2L+(long)l*D_*FF_;

        cudaMemsetAsync(zacc,0,(size_t)BS_*NQ_*(2*D_+FF_)*sizeof(float),0);

        // latn -> q (split-K=16) -> modulate+split
        ln_k<true,true><<<BS_*NQ_,256>>>(lat,nullptr,latnH,latnL,g2,b2);
        mgemm<CM_ATOM,3><<<tg(BS_*NQ_,INNER,16),256,SMB>>>(
            BS_*NQ_,INNER,D_,16, latnH,latnL,D_,0, wqh,wql,D_,0,
            q,NB_,NB_,INNER,0, nullptr,nullptr,1.f);
        modulate_k<<<(BS_*NQ_*D_+255)/256,256>>>(q,ada,l*4*D_,qH,qL);

        // qp(split out, ⊙g1) = SCALE * qmod_h @ wk_h^T (z=heads)
        mgemm<CM_SPLIT,3><<<tg(BS_*NQ_,D_,H_),256,SMB>>>(
            BS_*NQ_,D_,DH_,1, qH,qL,INNER,64, kvh,kvl,2*INNER,64,
            nullptr,qpH,qpL,H_*D_,(long)D_, nullptr,g1,SCALE_);

        // logits = qp' @ xn^T (2-pass, BK=64)
        mgemm64<CM_STORE><<<dim3(N1_/128,1,BS_),256,SMB64>>>(
            D_, qpH,qpL,D_,(long)NQ_*H_*D_, xnH,D_,(long)N1_*D_,
            att,NB_,NB_,N1_,(long)NQ_*H_*N1_, nullptr,nullptr,1.f);
        softmax_k<<<BS_*NQ_*H_,256>>>(att,attH,attL);

        // ov(split out, g1*x+b1) = attn @ xn (2-pass, BK=64, via xnT)
        mgemm64<CM_SPLIT><<<dim3(D_/128,1,BS_),256,SMB64>>>(
            N1_, attH,attL,N1_,(long)NQ_*H_*N1_, xnTH,N1_,(long)D_*N1_,
            nullptr,ovH,ovL,D_,(long)NQ_*H_*D_, b1,g1,1.f);

        // vout = ovm_h @ wv_h (z=heads, split-K=8, BN=64 tile)
        mgemmV<<<dim3(1,(BS_*NQ_)/128,H_*8),256,SMBV>>>(
            D_,8, ovH,ovL,H_*D_,(long)D_, kvth+(long)INNER*D_,kvtl+(long)INNER*D_,D_,(long)64*D_,
            vout,D_,64);
        split_k<<<(BS_*NQ_*D_+255)/256,256>>>(vout,voH,voL,BS_*NQ_*D_);

        // lat += vout @ wo (split-K=16)
        mgemm<CM_ATOM,3><<<tg(BS_*NQ_,D_,16),256,SMB>>>(
            BS_*NQ_,D_,INNER,16, voH,voL,INNER,0, woh,wol,INNER,0,
            lat,NB_,NB_,D_,0, nullptr,nullptr,1.f);

        // FF: h1 raw (split-K=4) -> GELU+split -> ff2 (split-K=16)
        ln_k<true,true><<<BS_*NQ_,256>>>(lat,nullptr,hffH,hffL,fg,fb);
        mgemm<CM_ATOM,3><<<tg(BS_*NQ_,FF_,4),256,SMB>>>(
            BS_*NQ_,FF_,D_,4, hffH,hffL,D_,0, f1h,f1l,D_,0,
            h1,NB_,NB_,FF_,0, nullptr,nullptr,1.f);
        gsplit_k<<<(BS_*NQ_*FF_+255)/256,256>>>(h1,h1H,h1L,BS_*NQ_*FF_);
        mgemm<CM_ATOM,3><<<tg(BS_*NQ_,D_,16),256,SMB>>>(
            BS_*NQ_,D_,FF_,16, h1H,h1L,FF_,0, f2h,f2l,FF_,0,
            lat,NB_,NB_,D_,0, nullptr,nullptr,1.f);
    }

    // ---- proj_out (split-K=16) + final LN ----
    split_k<<<(BS_*NQ_*D_+255)/256,256>>>(lat,latH,latL,BS_*NQ_*D_);
    cudaMemsetAsync(hff,0,(size_t)BS_*NQ_*D_*sizeof(float),0);
    mgemm<CM_ATOM,3><<<tg(BS_*NQ_,D_,16),256,SMB>>>(
        BS_*NQ_,D_,D_,16, latH,latL,D_,0, poH,poL,D_,0,
        hff,NB_,NB_,D_,0, pout_b,nullptr,1.f);
    ln_k<true,false><<<BS_*NQ_,256>>>(hff,out,nullptr,nullptr,ng,nb);
}

// round 17
// speedup vs baseline: 1.1924x; 1.0142x over previous
#include <cuda_runtime.h>
#include <cuda_bf16.h>
#include <math.h>
#include <stdint.h>

#define D_    1024
#define DEPTH 8
#define H_    16
#define DH_   64
#define INNER 1024
#define NQ_   8
#define ED_   768
#define FF_   4096
#define TD_   320
#define BS_   32
#define N1_   1024
#define SCALE_ 0.125f
#define ADAW  32768

#define ACT_NONE 0
#define ACT_SILU 1
#define CM_STORE 0
#define CM_ATOM  1
#define CM_SPLIT 2
#define OM_F32   0
#define OM_SPLIT 1

typedef __nv_bfloat16 bf;

// ---- fp32 scratch ----
__device__ float g_xp[BS_*N1_*D_];
__device__ float g_ada[BS_*ADAW];
__device__ float g_lat[BS_*NQ_*D_];
__device__ float g_att[BS_*NQ_*H_*N1_];
__device__ float g_hff[BS_*NQ_*D_];
__device__ float g_zacc[BS_*NQ_*(2*D_+FF_)];

// ---- bf16 hi/lo pairs ----
__device__ bf s_inxH[BS_*N1_*ED_],  s_inxL[BS_*N1_*ED_];
__device__ bf s_pinH[D_*ED_],       s_pinL[D_*ED_];
__device__ bf s_xnH[BS_*N1_*D_],    s_xnL[BS_*N1_*D_];
__device__ bf s_xnTH[BS_*D_*N1_],   s_xnTL[BS_*D_*N1_];
__device__ bf s_latnH[BS_*NQ_*D_],  s_latnL[BS_*NQ_*D_];
__device__ bf s_qH[BS_*NQ_*D_],     s_qL[BS_*NQ_*D_];
__device__ bf s_qpH[BS_*NQ_*H_*D_], s_qpL[BS_*NQ_*H_*D_];
__device__ bf s_attH[BS_*NQ_*H_*N1_], s_attL[BS_*NQ_*H_*N1_];
__device__ bf s_ovH[BS_*NQ_*H_*D_], s_ovL[BS_*NQ_*H_*D_];
__device__ bf s_voH[BS_*NQ_*D_],    s_voL[BS_*NQ_*D_];
__device__ bf s_hffH[BS_*NQ_*D_],   s_hffL[BS_*NQ_*D_];
__device__ bf s_h1H[BS_*NQ_*FF_],   s_h1L[BS_*NQ_*FF_];
__device__ bf s_latH[BS_*NQ_*D_],   s_latL[BS_*NQ_*D_];
__device__ bf s_t0H[BS_*TD_],       s_t0L[BS_*TD_];
__device__ bf s_t1H[BS_*D_],        s_t1L[BS_*D_];
__device__ bf s_stH[BS_*D_],        s_stL[BS_*D_];
__device__ bf s_tw1H[TD_*D_],       s_tw1L[TD_*D_];
__device__ bf s_tw2H[D_*D_],        s_tw2L[D_*D_];
__device__ bf s_wqH[DEPTH*INNER*D_],  s_wqL[DEPTH*INNER*D_];
__device__ bf s_kvH[DEPTH*D_*2*INNER],s_kvL[DEPTH*D_*2*INNER];
__device__ bf s_kvTH[DEPTH*2*INNER*D_],s_kvTL[DEPTH*2*INNER*D_];
__device__ bf s_woH[DEPTH*D_*INNER],  s_woL[DEPTH*D_*INNER];
__device__ bf s_f1H[DEPTH*FF_*D_],    s_f1L[DEPTH*FF_*D_];
__device__ bf s_f2H[DEPTH*D_*FF_],    s_f2L[DEPTH*D_*FF_];
__device__ bf s_awH[DEPTH*4*D_*D_],   s_awL[DEPTH*4*D_*D_];
__device__ bf s_poH[D_*D_],           s_poL[D_*D_];

// ---- helpers ----
__device__ __forceinline__ uint32_t smem_u32(const void* p){
    uint32_t a;
    asm("{ .reg .u64 t; cvta.to.shared.u64 t, %1; cvt.u32.u64 %0, t; }":"=r"(a):"l"(p));
    return a;
}
__device__ __forceinline__ void sp2(float v, bf& h, bf& l){
    h = __float2bfloat16_rn(v);
    l = __float2bfloat16_rn(v - __bfloat162float(h));
}
#define CPA(d,s) asm volatile("cp.async.cg.shared.global [%0],[%1],16;"::"r"(d),"l"(s):"memory")
#define CPC()    asm volatile("cp.async.commit_group;":::"memory")
#define CPW(n)   asm volatile("cp.async.wait_group %0;"::"n"(n):"memory")
#define LDSM4(r,a) asm volatile("ldmatrix.sync.aligned.m8n8.x4.shared.b16 {%0,%1,%2,%3},[%4];" \
    :"=r"((r)[0]),"=r"((r)[1]),"=r"((r)[2]),"=r"((r)[3]):"r"(a))
#define MMA(d,a,b) asm volatile("mma.sync.aligned.m16n8k16.row.col.f32.bf16.bf16.f32 " \
    "{%0,%1,%2,%3},{%4,%5,%6,%7},{%8,%9},{%0,%1,%2,%3};" \
    :"+f"((d)[0]),"+f"((d)[1]),"+f"((d)[2]),"+f"((d)[3]) \
    :"r"((a)[0]),"r"((a)[1]),"r"((a)[2]),"r"((a)[3]),"r"((b)[0]),"r"((b)[1]))

// ---- bf16 tensor GEMM: BK=32; NPASS=3: AhBh+AhBl+AlBh, NPASS=2: AhBh+AlBh ----
#define SMB 81920
template<int CMODE,int NPASS>
__global__ void __launch_bounds__(256,2) mgemm(
    int M,int N,int K,int ksplit,
    const bf* __restrict__ Ah,const bf* __restrict__ Al,int lda,long sAz,
    const bf* __restrict__ Bh,const bf* __restrict__ Bl,int ldb,long sBz,
    float* __restrict__ C, bf* __restrict__ CH, bf* __restrict__ CL, int ldc, long sCz,
    const float* __restrict__ bias, const float* __restrict__ cscale, float alpha)
{
    extern __shared__ bf sh[];
    const int t=threadIdx.x, lane=t&31, wid=t>>5;
    const int zz=blockIdx.z, batch=zz/ksplit, kp=zz-batch*ksplit;
    const int Kl=K/ksplit, koff=kp*Kl, NC=Kl>>5;
    const int bm=blockIdx.y*128, bn=blockIdx.x*128;
    const uint32_t sb = smem_u32(sh);
    const int mw=(wid>>2)*64, nw=(wid&3)*32;

    const bf* pAh[2]; const bf* pAl[2]; const bf* pBh[2]; const bf* pBl[2];
    uint32_t dst[2];
#pragma unroll
    for(int i=0;i<2;i++){
        int f=t+i*256, row=f>>2, ch=(f&3)*8;
        long ao=(long)batch*sAz + (long)(bm+row)*lda + koff + ch;
        pAh[i]=Ah+ao; pAl[i]=Al+ao;
        int rn=bn+row; if(rn>=N) rn=N-1;
        long bo=(long)batch*sBz + (long)rn*ldb + koff + ch;
        pBh[i]=Bh+bo; pBl[i]=Bl+bo;
        dst[i]=sb+(uint32_t)(row*40+ch)*2u;
    }

    float acc[4][4][4];
#pragma unroll
    for(int a=0;a<4;a++)
#pragma unroll
    for(int b=0;b<4;b++)
#pragma unroll
    for(int c=0;c<4;c++) acc[a][b][c]=0.f;

    auto fill=[&](int st){
        uint32_t so=(uint32_t)st*40960u;
#pragma unroll
        for(int i=0;i<2;i++){
            uint32_t d0=dst[i]+so;
            CPA(d0,       pAh[i]);
            CPA(d0+10240, pAl[i]);
            CPA(d0+20480, pBh[i]);
            if(NPASS==3) CPA(d0+30720, pBl[i]);
            pAh[i]+=32; pAl[i]+=32; pBh[i]+=32;
            if(NPASS==3) pBl[i]+=32;
        }
        CPC();
    };

    fill(0);
    for(int c=0;c<NC;c++){
        int st=c&1;
        CPW(0);
        __syncthreads();
        if(c+1<NC) fill(st^1);
        uint32_t base = sb + st*40960u;
#pragma unroll
        for(int ks=0;ks<2;ks++){
            uint32_t kadd = (uint32_t)(ks*32 + (lane>>4)*16);
            uint32_t Af[4][4], Bh2[4][2];
#pragma unroll
            for(int mt=0;mt<4;mt++)
                LDSM4(Af[mt], base + (uint32_t)(mw+mt*16+(lane&15))*80u + kadd);
#pragma unroll
            for(int np=0;np<2;np++){
                uint32_t qq[4];
                LDSM4(qq, base+20480u + (uint32_t)(nw+np*16+(lane&15))*80u + kadd);
                Bh2[np*2][0]=qq[0]; Bh2[np*2][1]=qq[2];
                Bh2[np*2+1][0]=qq[1]; Bh2[np*2+1][1]=qq[3];
            }
#pragma unroll
            for(int mt=0;mt<4;mt++)
#pragma unroll
            for(int nt=0;nt<4;nt++) MMA(acc[mt][nt],Af[mt],Bh2[nt]);
            if(NPASS==3){
                uint32_t Bl2[4][2];
#pragma unroll
                for(int np=0;np<2;np++){
                    uint32_t qq[4];
                    LDSM4(qq, base+30720u + (uint32_t)(nw+np*16+(lane&15))*80u + kadd);
                    Bl2[np*2][0]=qq[0]; Bl2[np*2][1]=qq[2];
                    Bl2[np*2+1][0]=qq[1]; Bl2[np*2+1][1]=qq[3];
                }
#pragma unroll
                for(int mt=0;mt<4;mt++)
#pragma unroll
                for(int nt=0;nt<4;nt++) MMA(acc[mt][nt],Af[mt],Bl2[nt]);
            }
#pragma unroll
            for(int mt=0;mt<4;mt++)
                LDSM4(Af[mt], base+10240u + (uint32_t)(mw+mt*16+(lane&15))*80u + kadd);
#pragma unroll
            for(int mt=0;mt<4;mt++)
#pragma unroll
            for(int nt=0;nt<4;nt++) MMA(acc[mt][nt],Af[mt],Bh2[nt]);
        }
    }

    const bool dob = bias && (CMODE!=CM_ATOM || kp==0);
#pragma unroll
    for(int mt=0;mt<4;mt++)
#pragma unroll
    for(int nt=0;nt<4;nt++){
        int gc = bn+nw+nt*8+(lane&3)*2;
#pragma unroll
        for(int rr=0;rr<2;rr++){
            int gr = bm+mw+mt*16+(lane>>2)+rr*8;
            if(gr>=M) continue;
#pragma unroll
            for(int cc=0;cc<2;cc++){
                int c2=gc+cc;
                if(c2>=N) continue;
                float v = acc[mt][nt][rr*2+cc]*alpha;
                if(cscale) v *= cscale[c2];
                if(dob) v += bias[c2];
                long off=(long)batch*sCz + (long)gr*ldc + c2;
                if(CMODE==CM_ATOM) atomicAdd(&C[off],v);
                else if(CMODE==CM_STORE) C[off]=v;
                else { bf h,l; sp2(v,h,l); CH[off]=h; CL[off]=l; }
            }
        }
    }
}

// ---- BK=64 2-pass GEMM (logits/ov) ----
#define S64  55296
#define SMB64 (2*S64)
template<int CMODE>
__global__ void __launch_bounds__(256,2) mgemm64(
    int K,
    const bf* __restrict__ Ah,const bf* __restrict__ Al,int lda,long sAz,
    const bf* __restrict__ Bh,int ldb,long sBz,
    float* __restrict__ C, bf* __restrict__ CH, bf* __restrict__ CL, int ldc, long sCz,
    const float* __restrict__ bias, const float* __restrict__ cscale, float alpha)
{
    extern __shared__ bf sh[];
    const int t=threadIdx.x, lane=t&31, wid=t>>5;
    const int batch=blockIdx.z;
    const int bm=blockIdx.y*128, bn=blockIdx.x*128;
    const uint32_t sb = smem_u32(sh);
    const int mw=(wid>>2)*64, nw=(wid&3)*32;
    const int NC=K>>6;

    const bf* pAh[4]; const bf* pAl[4]; const bf* pBh[4];
    uint32_t dst[4];
#pragma unroll
    for(int i=0;i<4;i++){
        int f=t+i*256, row=f>>3, ch=(f&7)*8;
        long ao=(long)batch*sAz + (long)(bm+row)*lda + ch;
        pAh[i]=Ah+ao; pAl[i]=Al+ao;
        long bo=(long)batch*sBz + (long)(bn+row)*ldb + ch;
        pBh[i]=Bh+bo;
        dst[i]=sb+(uint32_t)(row*144+ch*2);
    }

    float acc[4][4][4];
#pragma unroll
    for(int a=0;a<4;a++)
#pragma unroll
    for(int b=0;b<4;b++)
#pragma unroll
    for(int c=0;c<4;c++) acc[a][b][c]=0.f;

    auto fill=[&](int st){
        uint32_t so=(uint32_t)st*(uint32_t)S64;
#pragma unroll
        for(int i=0;i<4;i++){
            uint32_t d0=dst[i]+so;
            CPA(d0,        pAh[i]);
            CPA(d0+18432u, pAl[i]);
            CPA(d0+36864u, pBh[i]);
            pAh[i]+=64; pAl[i]+=64; pBh[i]+=64;
        }
        CPC();
    };

    fill(0);
    for(int c=0;c<NC;c++){
        int st=c&1;
        CPW(0);
        __syncthreads();
        if(c+1<NC) fill(st^1);
        uint32_t base = sb + st*(uint32_t)S64;
#pragma unroll
        for(int ks=0;ks<4;ks++){
            uint32_t kadd = (uint32_t)(ks*32 + (lane>>4)*16);
            uint32_t Af[4][4], Bh2[4][2];
#pragma unroll
            for(int mt=0;mt<4;mt++)
                LDSM4(Af[mt], base + (uint32_t)(mw+mt*16+(lane&15))*144u + kadd);
#pragma unroll
            for(int np=0;np<2;np++){
                uint32_t qq[4];
                LDSM4(qq, base+36864u + (uint32_t)(nw+np*16+(lane&15))*144u + kadd);
                Bh2[np*2][0]=qq[0]; Bh2[np*2][1]=qq[2];
                Bh2[np*2+1][0]=qq[1]; Bh2[np*2+1][1]=qq[3];
            }
#pragma unroll
            for(int mt=0;mt<4;mt++)
#pragma unroll
            for(int nt=0;nt<4;nt++) MMA(acc[mt][nt],Af[mt],Bh2[nt]);
#pragma unroll
            for(int mt=0;mt<4;mt++)
                LDSM4(Af[mt], base+18432u + (uint32_t)(mw+mt*16+(lane&15))*144u + kadd);
#pragma unroll
            for(int mt=0;mt<4;mt++)
#pragma unroll
            for(int nt=0;nt<4;nt++) MMA(acc[mt][nt],Af[mt],Bh2[nt]);
        }
    }

#pragma unroll
    for(int mt=0;mt<4;mt++)
#pragma unroll
    for(int nt=0;nt<4;nt++){
        int gc = bn+nw+nt*8+(lane&3)*2;
#pragma unroll
        for(int rr=0;rr<2;rr++){
            int gr = bm+mw+mt*16+(lane>>2)+rr*8;
#pragma unroll
            for(int cc=0;cc<2;cc++){
                int c2=gc+cc;
                float v = acc[mt][nt][rr*2+cc]*alpha;
                if(cscale) v *= cscale[c2];
                if(bias) v += bias[c2];
                long off=(long)batch*sCz + (long)gr*ldc + c2;
                if(CMODE==CM_STORE) C[off]=v;
                else { bf h,l; sp2(v,h,l); CH[off]=h; CL[off]=l; }
            }
        }
    }
}

// ---- BN=64 3-pass GEMM (vout): BM=128, N==64, split-K atomic ----
#define SV 30720
#define SMBV (2*SV)
__global__ void __launch_bounds__(256,2) mgemmV(
    int K,int ksplit,
    const bf* __restrict__ Ah,const bf* __restrict__ Al,int lda,long sAz,
    const bf* __restrict__ Bh,const bf* __restrict__ Bl,int ldb,long sBz,
    float* __restrict__ C,int ldc,long sCz)
{
    extern __shared__ bf sh[];
    const int t=threadIdx.x, lane=t&31, wid=t>>5;
    const int zz=blockIdx.z, batch=zz/ksplit, kp=zz-batch*ksplit;
    const int Kl=K/ksplit, koff=kp*Kl, NC=Kl>>5;
    const int bm=blockIdx.y*128;
    const uint32_t sb=smem_u32(sh);
    const int mw=(wid&3)*32, nw=(wid>>2)*32;

    const bf* pAh[2]; const bf* pAl[2]; const bf* pBh; const bf* pBl;
    uint32_t dstA[2], dstB;
#pragma unroll
    for(int i=0;i<2;i++){
        int f=t+i*256, row=f>>2, ch=(f&3)*8;
        long ao=(long)batch*sAz + (long)(bm+row)*lda + koff + ch;
        pAh[i]=Ah+ao; pAl[i]=Al+ao;
        dstA[i]=sb+(uint32_t)(row*40+ch)*2u;
    }
    {
        int row=t>>2, ch=(t&3)*8;
        long bo=(long)batch*sBz + (long)row*ldb + koff + ch;
        pBh=Bh+bo; pBl=Bl+bo;
        dstB=sb+(uint32_t)(row*40+ch)*2u;
    }

    float acc[2][4][4];
#pragma unroll
    for(int a=0;a<2;a++)
#pragma unroll
    for(int b=0;b<4;b++)
#pragma unroll
    for(int c=0;c<4;c++) acc[a][b][c]=0.f;

    auto fill=[&](int st){
        uint32_t so=(uint32_t)st*(uint32_t)SV;
#pragma unroll
        for(int i=0;i<2;i++){
            uint32_t d0=dstA[i]+so;
            CPA(d0,       pAh[i]);
            CPA(d0+10240, pAl[i]);
            pAh[i]+=32; pAl[i]+=32;
        }
        CPA(dstB+so+20480u, pBh);
        CPA(dstB+so+25600u, pBl);
        pBh+=32; pBl+=32;
        CPC();
    };

    fill(0);
    for(int c=0;c<NC;c++){
        int st=c&1;
        CPW(0);
        __syncthreads();
        if(c+1<NC) fill(st^1);
        uint32_t base=sb+(uint32_t)st*(uint32_t)SV;
#pragma unroll
        for(int ks=0;ks<2;ks++){
            uint32_t kadd=(uint32_t)(ks*32+(lane>>4)*16);
            uint32_t Af[2][4], Bh2[4][2];
#pragma unroll
            for(int mt=0;mt<2;mt++)
                LDSM4(Af[mt], base + (uint32_t)(mw+mt*16+(lane&15))*80u + kadd);
#pragma unroll
            for(int np=0;np<2;np++){
                uint32_t qq[4];
                LDSM4(qq, base+20480u + (uint32_t)(nw+np*16+(lane&15))*80u + kadd);
                Bh2[np*2][0]=qq[0]; Bh2[np*2][1]=qq[2];
                Bh2[np*2+1][0]=qq[1]; Bh2[np*2+1][1]=qq[3];
            }
#pragma unroll
            for(int mt=0;mt<2;mt++)
#pragma unroll
            for(int nt=0;nt<4;nt++) MMA(acc[mt][nt],Af[mt],Bh2[nt]);
            {
                uint32_t Bl2[4][2];
#pragma unroll
                for(int np=0;np<2;np++){
                    uint32_t qq[4];
                    LDSM4(qq, base+25600u + (uint32_t)(nw+np*16+(lane&15))*80u + kadd);
                    Bl2[np*2][0]=qq[0]; Bl2[np*2][1]=qq[2];
                    Bl2[np*2+1][0]=qq[1]; Bl2[np*2+1][1]=qq[3];
                }
#pragma unroll
                for(int mt=0;mt<2;mt++)
#pragma unroll
                for(int nt=0;nt<4;nt++) MMA(acc[mt][nt],Af[mt],Bl2[nt]);
            }
#pragma unroll
            for(int mt=0;mt<2;mt++)
                LDSM4(Af[mt], base+10240u + (uint32_t)(mw+mt*16+(lane&15))*80u + kadd);
#pragma unroll
            for(int mt=0;mt<2;mt++)
#pragma unroll
            for(int nt=0;nt<4;nt++) MMA(acc[mt][nt],Af[mt],Bh2[nt]);
        }
    }

#pragma unroll
    for(int mt=0;mt<2;mt++)
#pragma unroll
    for(int nt=0;nt<4;nt++){
        int gc = nw+nt*8+(lane&3)*2;
#pragma unroll
        for(int rr=0;rr<2;rr++){
            int gr = bm+mw+mt*16+(lane>>2)+rr*8;
#pragma unroll
            for(int cc=0;cc<2;cc++){
                long off=(long)batch*sCz + (long)gr*ldc + gc+cc;
                atomicAdd(&C[off], acc[mt][nt][rr*2+cc]);
            }
        }
    }
}

// ---- BM=32 bf16 GEMM (M==32): ACT + output-mode templated ----
#define SM32S 25600
template<int ACT,int OM>
__global__ void __launch_bounds__(256,2) mgemm32(
    int N,int K,
    const bf* __restrict__ Ah,const bf* __restrict__ Al,int lda,
    const bf* __restrict__ Bh,const bf* __restrict__ Bl,int ldb,
    float* __restrict__ C, bf* __restrict__ CH, bf* __restrict__ CL,
    int ldc,const float* __restrict__ bias)
{
    extern __shared__ bf sh[];
    const int t=threadIdx.x, lane=t&31, wid=t>>5;
    const int bn=blockIdx.x*128;
    const uint32_t sb=smem_u32(sh);
    const int NC=K>>5;
    float acc[2][2][4];
#pragma unroll
    for(int a=0;a<2;a++)
#pragma unroll
    for(int b=0;b<2;b++)
#pragma unroll
    for(int c=0;c<4;c++) acc[a][b][c]=0.f;

    auto fill=[&](int st,int c){
        uint32_t bs=sb+(uint32_t)st*SM32S;
        {
            int row=(t&127)>>2, ch=(t&3)*8;
            const bf* Ap=(t<128)?Ah:Al;
            uint32_t off=(t<128)?0u:2560u;
            CPA(bs+off+(uint32_t)(row*80+ch*2), Ap+(long)row*lda+c*32+ch);
        }
#pragma unroll
        for(int i=0;i<2;i++){
            int f=t+i*256, row=f>>2, ch=(f&3)*8;
            int rn=bn+row; if(rn>=N) rn=N-1;
            long bo=(long)rn*ldb+c*32+ch;
            CPA(bs+5120u+(uint32_t)(row*80+ch*2), Bh+bo);
            CPA(bs+15360u+(uint32_t)(row*80+ch*2), Bl+bo);
        }
        CPC();
    };

    fill(0,0);
    for(int c=0;c<NC;c++){
        int st=c&1;
        CPW(0);
        __syncthreads();
        if(c+1<NC) fill(st^1,c+1);
        uint32_t base=sb+(uint32_t)st*SM32S;
#pragma unroll
        for(int ks=0;ks<2;ks++){
            uint32_t kadd=(uint32_t)(ks*32+(lane>>4)*16);
            uint32_t Af[2][4], Bf[2][2], Bl2[2][2];
#pragma unroll
            for(int mt=0;mt<2;mt++)
                LDSM4(Af[mt], base + (uint32_t)((mt*16+(lane&15))*80) + kadd);
            {
                uint32_t qq[4];
                LDSM4(qq, base+5120u + (uint32_t)((wid*16+(lane&15))*80) + kadd);
                Bf[0][0]=qq[0];Bf[0][1]=qq[2];Bf[1][0]=qq[1];Bf[1][1]=qq[3];
            }
#pragma unroll
            for(int mt=0;mt<2;mt++)
#pragma unroll
            for(int nt=0;nt<2;nt++) MMA(acc[mt][nt],Af[mt],Bf[nt]);
            {
                uint32_t qq[4];
                LDSM4(qq, base+15360u + (uint32_t)((wid*16+(lane&15))*80) + kadd);
                Bl2[0][0]=qq[0];Bl2[0][1]=qq[2];Bl2[1][0]=qq[1];Bl2[1][1]=qq[3];
            }
#pragma unroll
            for(int mt=0;mt<2;mt++)
#pragma unroll
            for(int nt=0;nt<2;nt++) MMA(acc[mt][nt],Af[mt],Bl2[nt]);
#pragma unroll
            for(int mt=0;mt<2;mt++)
                LDSM4(Af[mt], base+2560u + (uint32_t)((mt*16+(lane&15))*80) + kadd);
#pragma unroll
            for(int mt=0;mt<2;mt++)
#pragma unroll
            for(int nt=0;nt<2;nt++) MMA(acc[mt][nt],Af[mt],Bf[nt]);
        }
    }
#pragma unroll
    for(int mt=0;mt<2;mt++)
#pragma unroll
    for(int nt=0;nt<2;nt++){
        int gc=bn+wid*16+nt*8+(lane&3)*2;
#pragma unroll
        for(int rr=0;rr<2;rr++){
            int gr=mt*16+(lane>>2)+rr*8;
#pragma unroll
            for(int cc=0;cc<2;cc++){
                int c2=gc+cc;
                if(c2>=N) continue;
                float v=acc[mt][nt][rr*2+cc];
                if(bias) v+=bias[c2];
                if(ACT==ACT_SILU) v=v/(1.f+expf(-v));
                long off=(long)gr*ldc+c2;
                if(OM==OM_F32) C[off]=v;
                else { bf h,l; sp2(v,h,l); CH[off]=h; CL[off]=l; }
            }
        }
    }
}

// ---- unified prep ----
#define NSEG 12
struct Segs {
    const float* src[NSEG]; bf* dh[NSEG]; bf* dl[NSEG];
    int K[NSEG], N[NSEG], mode[NSEG];
    int bstart[NSEG+1]; int nseg;
};
__global__ void prep_all(Segs S)
{
    __shared__ float tile[32][33];
    int b=blockIdx.x;
    int si=0;
    while(si+1<S.nseg && b>=S.bstart[si+1]) si++;
    int lb=b-S.bstart[si];
    int tx=threadIdx.x, ty=threadIdx.y;
    if(S.mode[si]==0){
        int K=S.K[si], N=S.N[si];
        int tpz=(N/32)*(K/32);
        int z=lb/tpz, rem=lb-z*tpz;
        int n0=(rem%(N/32))*32, k0=(rem/(N/32))*32;
        long zo=(long)z*K*N;
        const float* Sp=S.src[si]+zo; bf* TH=S.dh[si]+zo; bf* TL=S.dl[si]+zo;
#pragma unroll
        for(int j=0;j<4;j++)
            tile[ty+j*8][tx]=Sp[(long)(k0+ty+j*8)*N+n0+tx];
        __syncthreads();
#pragma unroll
        for(int j=0;j<4;j++){
            int n=n0+ty+j*8, k=k0+tx;
            bf h,l; sp2(tile[tx][ty+j*8],h,l);
            TH[(long)n*K+k]=h; TL[(long)n*K+k]=l;
        }
    } else {
        long n=(long)S.K[si]*2048;
        long i0=(long)lb*2048 + ty*32+tx;
#pragma unroll
        for(int j=0;j<8;j++){
            long i=i0+j*256;
            if(i<n){ bf h,l; sp2(S.src[si][i],h,l); S.dh[si][i]=h; S.dl[si][i]=l; }
        }
    }
}

// ---- LayerNorm D=1024 -> split or fp32 ----
template<bool AFFINE,bool SPLIT>
__global__ void __launch_bounds__(256) ln_k(const float* __restrict__ x,
    float* __restrict__ y, bf* __restrict__ yH, bf* __restrict__ yL,
    const float* __restrict__ g, const float* __restrict__ b)
{
    long row=blockIdx.x; const float* xr=x+row*D_; int t=threadIdx.x;
    float v[4], s=0.f;
#pragma unroll
    for(int i=0;i<4;i++){ v[i]=xr[t+i*256]; s+=v[i]; }
    __shared__ float red[256];
    red[t]=s; __syncthreads();
    for(int o=128;o>0;o>>=1){ if(t<o) red[t]+=red[t+o]; __syncthreads(); }
    float m=red[0]*(1.f/D_); __syncthreads();
    float vs=0.f;
#pragma unroll
    for(int i=0;i<4;i++){ float d=v[i]-m; vs+=d*d; }
    red[t]=vs; __syncthreads();
    for(int o=128;o>0;o>>=1){ if(t<o) red[t]+=red[t+o]; __syncthreads(); }
    float rs=1.f/sqrtf(red[0]*(1.f/D_)+1e-5f);
#pragma unroll
    for(int i=0;i<4;i++){
        int c=t+i*256; float o=(v[i]-m)*rs;
        if(AFFINE) o=o*g[c]+b[c];
        if(SPLIT){ bf h,l; sp2(o,h,l); yH[row*D_+c]=h; yL[row*D_+c]=l; }
        else y[row*D_+c]=o;
    }
}

// ---- softmax 1024 -> split ----
__global__ void __launch_bounds__(256) softmax_k(const float* __restrict__ x,
    bf* __restrict__ pH, bf* __restrict__ pL)
{
    long row=blockIdx.x; const float* p=x+row*N1_; int t=threadIdx.x;
    float v[4], mx=-1e30f;
#pragma unroll
    for(int i=0;i<4;i++){ v[i]=p[t+i*256]; mx=fmaxf(mx,v[i]); }
    __shared__ float red[256];
    red[t]=mx; __syncthreads();
    for(int o=128;o>0;o>>=1){ if(t<o) red[t]=fmaxf(red[t],red[t+o]); __syncthreads(); }
    mx=red[0]; __syncthreads();
    float s=0.f;
#pragma unroll
    for(int i=0;i<4;i++){ v[i]=expf(v[i]-mx); s+=v[i]; }
    red[t]=s; __syncthreads();
    for(int o=128;o>0;o>>=1){ if(t<o) red[t]+=red[t+o]; __syncthreads(); }
    float inv=1.f/red[0];
#pragma unroll
    for(int i=0;i<4;i++){
        int c=t+i*256; bf h,l; sp2(v[i]*inv,h,l);
        pH[row*N1_+c]=h; pL[row*N1_+c]=l;
    }
}

// ---- split / gelu-split ----
__global__ void split_k(const float* __restrict__ s, bf* __restrict__ h, bf* __restrict__ l, int n)
{
    int i=blockIdx.x*blockDim.x+threadIdx.x;
    if(i>=n) return;
    bf hh,ll; sp2(s[i],hh,ll); h[i]=hh; l[i]=ll;
}
__global__ void gsplit_k(const float* __restrict__ s, bf* __restrict__ h, bf* __restrict__ l, int n)
{
    int i=blockIdx.x*blockDim.x+threadIdx.x;
    if(i>=n) return;
    float v=s[i];
    v = 0.5f*v*(1.f+erff(v*0.70710678118654752f));
    bf hh,ll; sp2(v,hh,ll); h[i]=hh; l[i]=ll;
}

// ---- transpose bf16 pairs ----
__global__ void btransp(const bf* __restrict__ ih,const bf* __restrict__ il,
                        bf* __restrict__ oh, bf* __restrict__ ol,int R,int C)
{
    __shared__ bf th[32][33], tl[32][33];
    long zo=(long)blockIdx.z*R*C;
    int c0=blockIdx.x*32, r0=blockIdx.y*32;
    int tx=threadIdx.x, ty=threadIdx.y;
#pragma unroll
    for(int j=0;j<4;j++){
        int r=r0+ty+j*8;
        th[ty+j*8][tx]=ih[zo+(long)r*C+c0+tx];
        tl[ty+j*8][tx]=il[zo+(long)r*C+c0+tx];
    }
    __syncthreads();
#pragma unroll
    for(int j=0;j<4;j++){
        int c=c0+ty+j*8, r=r0+tx;
        oh[zo+(long)c*R+r]=th[tx][ty+j*8];
        ol[zo+(long)c*R+r]=tl[tx][ty+j*8];
    }
}

// ---- misc ----
__global__ void timestep_k(const float* __restrict__ ts, bf* __restrict__ oH, bf* __restrict__ oL){
    int b=blockIdx.x,i=threadIdx.x;
    int j=(i<160)?i:(i-160);
    float f=expf(-logf(10000.f)*(float)j/160.f);
    double a=(double)(ts[b]*f);
    float v=(i<160)?(float)cos(a):(float)sin(a);
    bf h,l; sp2(v,h,l);
    oH[b*TD_+i]=h; oL[b*TD_+i]=l;
}
__global__ void bcast_k(const float* __restrict__ s,float* __restrict__ d,int n,int per){
    int i=blockIdx.x*blockDim.x+threadIdx.x;
    if(i<n) d[i]=s[i%per];
}
__global__ void modulate_k(const float* __restrict__ q,const float* __restrict__ ada,int loff,
                           bf* __restrict__ qH,bf* __restrict__ qL){
    int i=blockIdx.x*blockDim.x+threadIdx.x;
    if(i>=BS_*NQ_*D_) return;
    int b=i/(NQ_*D_), c=i&(D_-1);
    const float* ap=ada+(long)b*ADAW+loff;
    float v=q[i]*(1.f+ap[2*D_+c])+ap[c];
    bf h,l; sp2(v,h,l); qH[i]=h; qL[i]=l;
}

// ---- host ----
#define GSA(p,s) cudaGetSymbolAddress((void**)&p,s)
static inline dim3 tg(int M,int N,int z){ return dim3((unsigned)((N+127)/128),(unsigned)((M+127)/128),(unsigned)z); }
static bf* NB_=nullptr;
static float* NF_=nullptr;

extern "C" void kernel_launch(void* const* d_in, const int* in_sizes, int n_in,
                              void* d_out, int out_size)
{
    const float *in_x=(const float*)d_in[0], *in_ts=(const float*)d_in[1], *in_lat=(const float*)d_in[2];
    const float *te_w1=(const float*)d_in[3], *te_b1=(const float*)d_in[4];
    const float *te_w2=(const float*)d_in[5], *te_b2=(const float*)d_in[6];
    const float *pin_w=(const float*)d_in[7], *pin_b=(const float*)d_in[8];
    const float *ln1_g=(const float*)d_in[9], *ln1_b=(const float*)d_in[10];
    const float *ln2_g=(const float*)d_in[11], *ln2_b=(const float*)d_in[12];
    const float *wq=(const float*)d_in[13], *wkv=(const float*)d_in[14], *wo=(const float*)d_in[15];
    const float *flg=(const float*)d_in[16], *flb=(const float*)d_in[17];
    const float *fw1=(const float*)d_in[18], *fw2=(const float*)d_in[19];
    const float *aw=(const float*)d_in[20], *ab=(const float*)d_in[21];
    const float *pout_w=(const float*)d_in[22], *pout_b=(const float*)d_in[23];
    const float *ng=(const float*)d_in[24], *nb=(const float*)d_in[25];
    float* out=(float*)d_out;

    cudaFuncSetAttribute(mgemm<CM_STORE,3>,cudaFuncAttributeMaxDynamicSharedMemorySize,SMB);
    cudaFuncSetAttribute(mgemm<CM_ATOM,3>, cudaFuncAttributeMaxDynamicSharedMemorySize,SMB);
    cudaFuncSetAttribute(mgemm<CM_SPLIT,3>,cudaFuncAttributeMaxDynamicSharedMemorySize,SMB);
    cudaFuncSetAttribute(mgemm64<CM_STORE>,cudaFuncAttributeMaxDynamicSharedMemorySize,SMB64);
    cudaFuncSetAttribute(mgemm64<CM_SPLIT>,cudaFuncAttributeMaxDynamicSharedMemorySize,SMB64);
    cudaFuncSetAttribute(mgemmV,cudaFuncAttributeMaxDynamicSharedMemorySize,SMBV);
    cudaFuncSetAttribute(mgemm32<ACT_NONE,OM_F32>,cudaFuncAttributeMaxDynamicSharedMemorySize,2*SM32S);
    cudaFuncSetAttribute(mgemm32<ACT_SILU,OM_SPLIT>,cudaFuncAttributeMaxDynamicSharedMemorySize,2*SM32S);

    float *xp,*ada,*lat,*att,*hff,*zacc;
    GSA(xp,g_xp); GSA(ada,g_ada); GSA(lat,g_lat);
    GSA(att,g_att); GSA(hff,g_hff); GSA(zacc,g_zacc);
    float* q    = zacc;
    float* vout = zacc + (long)BS_*NQ_*D_;
    float* h1   = zacc + (long)2*BS_*NQ_*D_;
    bf *inxH,*inxL,*pinH,*pinL,*xnH,*xnL,*xnTH,*xnTL,*latnH,*latnL,*qH,*qL,*qpH,*qpL;
    bf *attH,*attL,*ovH,*ovL,*voH,*voL,*hffH,*hffL,*h1H,*h1L,*latH,*latL;
    bf *t0H,*t0L,*t1H,*t1L,*stH,*stL,*tw1H,*tw1L,*tw2H,*tw2L;
    bf *wqH,*wqL,*kvH,*kvL,*kvTH,*kvTL,*woH,*woL,*f1H,*f1L,*f2H,*f2L,*awH,*awL,*poH,*poL;
    GSA(inxH,s_inxH); GSA(inxL,s_inxL); GSA(pinH,s_pinH); GSA(pinL,s_pinL);
    GSA(xnH,s_xnH); GSA(xnL,s_xnL); GSA(xnTH,s_xnTH); GSA(xnTL,s_xnTL);
    GSA(latnH,s_latnH); GSA(latnL,s_latnL); GSA(qH,s_qH); GSA(qL,s_qL);
    GSA(qpH,s_qpH); GSA(qpL,s_qpL); GSA(attH,s_attH); GSA(attL,s_attL);
    GSA(ovH,s_ovH); GSA(ovL,s_ovL); GSA(voH,s_voH); GSA(voL,s_voL);
    GSA(hffH,s_hffH); GSA(hffL,s_hffL); GSA(h1H,s_h1H); GSA(h1L,s_h1L);
    GSA(latH,s_latH); GSA(latL,s_latL);
    GSA(t0H,s_t0H); GSA(t0L,s_t0L); GSA(t1H,s_t1H); GSA(t1L,s_t1L);
    GSA(stH,s_stH); GSA(stL,s_stL);
    GSA(tw1H,s_tw1H); GSA(tw1L,s_tw1L); GSA(tw2H,s_tw2H); GSA(tw2L,s_tw2L);
    GSA(wqH,s_wqH); GSA(wqL,s_wqL); GSA(kvH,s_kvH); GSA(kvL,s_kvL);
    GSA(kvTH,s_kvTH); GSA(kvTL,s_kvTL); GSA(woH,s_woH); GSA(woL,s_woL);
    GSA(f1H,s_f1H); GSA(f1L,s_f1L); GSA(f2H,s_f2H); GSA(f2L,s_f2L);
    GSA(awH,s_awH); GSA(awL,s_awL); GSA(poH,s_poH); GSA(poL,s_poL);

    // launch 0: ALL prep in one kernel (incl. te weights)
    Segs S; int nbk=0; int si=0;
    auto addT=[&](const float* s, bf* h, bf* l, int K,int N,int z){
        S.src[si]=s;S.dh[si]=h;S.dl[si]=l;S.K[si]=K;S.N[si]=N;S.mode[si]=0;
        S.bstart[si]=nbk; nbk+=(N/32)*(K/32)*z; si++;
    };
    auto addS2=[&](const float* s, bf* h, bf* l, long n){
        S.src[si]=s;S.dh[si]=h;S.dl[si]=l;S.K[si]=(int)(n/2048);S.N[si]=1;S.mode[si]=1;
        S.bstart[si]=nbk; nbk+=(int)(n/2048); si++;
    };
    addT(pin_w,pinH,pinL,ED_,D_,1);
    addT(wq,wqH,wqL,D_,INNER,DEPTH);
    addT(wkv,kvTH,kvTL,D_,2*INNER,DEPTH);
    addT(wo,woH,woL,INNER,D_,DEPTH);
    addT(fw1,f1H,f1L,D_,FF_,DEPTH);
    addT(fw2,f2H,f2L,FF_,D_,DEPTH);
    addT(aw,awH,awL,D_,4*D_,DEPTH);
    addT(pout_w,poH,poL,D_,D_,1);
    addT(te_w1,tw1H,tw1L,TD_,D_,1);
    addT(te_w2,tw2H,tw2L,D_,D_,1);
    addS2(wkv,kvH,kvL,(long)DEPTH*D_*2*INNER);
    addS2(in_x,inxH,inxL,(long)BS_*N1_*ED_);
    S.nseg=si; S.bstart[si]=nbk;
    prep_all<<<nbk,dim3(32,8)>>>(S);

    // launches 1,2
    timestep_k<<<BS_,TD_>>>(in_ts,t0H,t0L);
    mgemm32<ACT_SILU,OM_SPLIT><<<D_/128,256,2*SM32S>>>(
        D_,TD_, t0H,t0L,TD_, tw1H,tw1L,TD_, NF_,t1H,t1L, D_, te_b1);

    // launch 3: proj_in (profiled at idx 5)
    mgemm<CM_STORE,3><<<tg(BS_*N1_,D_,1),256,SMB>>>(
        BS_*N1_,D_,ED_,1, inxH,inxL,ED_,0, pinH,pinL,ED_,0,
        xp,NB_,NB_,D_,0, pin_b,nullptr,1.f);

    // stemb = silu(temb1 @ te_w2 + te_b2) directly as split pair
    mgemm32<ACT_SILU,OM_SPLIT><<<D_/128,256,2*SM32S>>>(
        D_,D_, t1H,t1L,D_, tw2H,tw2L,D_, NF_,stH,stL, D_, te_b2);

    // batched adaLN for ALL layers
    mgemm32<ACT_NONE,OM_F32><<<ADAW/128,256,2*SM32S>>>(
        ADAW,D_, stH,stL,D_, awH,awL,D_, ada,NB_,NB_, ADAW, ab);

    ln_k<false,true><<<BS_*N1_,256>>>(xp,nullptr,xnH,xnL,nullptr,nullptr);
    btransp<<<dim3(D_/32,N1_/32,BS_),dim3(32,8)>>>(xnH,xnL,xnTH,xnTL,N1_,D_);
    bcast_k<<<(BS_*NQ_*D_+255)/256,256>>>(in_lat,lat,BS_*NQ_*D_,NQ_*D_);

    for(int l=0;l<DEPTH;l++){
        const float *g1=ln1_g+l*D_, *b1=ln1_b+l*D_, *g2=ln2_g+l*D_, *b2=ln2_b+l*D_;
        const float *fg=flg+l*D_, *fb=flb+l*D_;
        const bf *wqh=wqH+(long)l*INNER*D_, *wql=wqL+(long)l*INNER*D_;
        const bf *kvh=kvH+(long)l*D_*2*INNER, *kvl=kvL+(long)l*D_*2*INNER;
        const bf *kvth=kvTH+(long)l*2*INNER*D_, *kvtl=kvTL+(long)l*2*INNER*D_;
        const bf *woh=woH+(long)l*D_*INNER, *wol=woL+(long)l*D_*INNER;
        const bf *f1h=f1H+(long)l*FF_*D_, *f1l=f1L+(long)l*FF_*D_;
        const bf *f2h=f2H+(long)l*D_*FF_, *f2l=f2L+(long)l*D_*FF_;

        cudaMemsetAsync(zacc,0,(size_t)BS_*NQ_*(2*D_+FF_)*sizeof(float),0);

        // latn -> q (split-K=16) -> modulate+split
        ln_k<true,true><<<BS_*NQ_,256>>>(lat,nullptr,latnH,latnL,g2,b2);
        mgemm<CM_ATOM,3><<<tg(BS_*NQ_,INNER,16),256,SMB>>>(
            BS_*NQ_,INNER,D_,16, latnH,latnL,D_,0, wqh,wql,D_,0,
            q,NB_,NB_,INNER,0, nullptr,nullptr,1.f);
        modulate_k<<<(BS_*NQ_*D_+255)/256,256>>>(q,ada,l*4*D_,qH,qL);

        // qp(split out, ⊙g1) = SCALE * qmod_h @ wk_h^T (z=heads)
        mgemm<CM_SPLIT,3><<<tg(BS_*NQ_,D_,H_),256,SMB>>>(
            BS_*NQ_,D_,DH_,1, qH,qL,INNER,64, kvh,kvl,2*INNER,64,
            nullptr,qpH,qpL,H_*D_,(long)D_, nullptr,g1,SCALE_);

        // logits = qp' @ xn^T (2-pass, BK=64)
        mgemm64<CM_STORE><<<dim3(N1_/128,1,BS_),256,SMB64>>>(
            D_, qpH,qpL,D_,(long)NQ_*H_*D_, xnH,D_,(long)N1_*D_,
            att,NB_,NB_,N1_,(long)NQ_*H_*N1_, nullptr,nullptr,1.f);
        softmax_k<<<BS_*NQ_*H_,256>>>(att,attH,attL);

        // ov(split out, g1*x+b1) = attn @ xn (2-pass, BK=64, via xnT)
        mgemm64<CM_SPLIT><<<dim3(D_/128,1,BS_),256,SMB64>>>(
            N1_, attH,attL,N1_,(long)NQ_*H_*N1_, xnTH,N1_,(long)D_*N1_,
            nullptr,ovH,ovL,D_,(long)NQ_*H_*D_, b1,g1,1.f);

        // vout = ovm_h @ wv_h (z=heads, split-K=8, BN=64 tile)
        mgemmV<<<dim3(1,(BS_*NQ_)/128,H_*8),256,SMBV>>>(
            D_,8, ovH,ovL,H_*D_,(long)D_, kvth+(long)INNER*D_,kvtl+(long)INNER*D_,D_,(long)64*D_,
            vout,D_,64);
        split_k<<<(BS_*NQ_*D_+255)/256,256>>>(vout,voH,voL,BS_*NQ_*D_);

        // lat += vout @ wo (split-K=16)
        mgemm<CM_ATOM,3><<<tg(BS_*NQ_,D_,16),256,SMB>>>(
            BS_*NQ_,D_,INNER,16, voH,voL,INNER,0, woh,wol,INNER,0,
            lat,NB_,NB_,D_,0, nullptr,nullptr,1.f);

        // FF: h1 raw (split-K=4) -> GELU+split -> ff2 (split-K=16)
        ln_k<true,true><<<BS_*NQ_,256>>>(lat,nullptr,hffH,hffL,fg,fb);
        mgemm<CM_ATOM,3><<<tg(BS_*NQ_,FF_,4),256,SMB>>>(
            BS_*NQ_,FF_,D_,4, hffH,hffL,D_,0, f1h,f1l,D_,0,
            h1,NB_,NB_,FF_,0, nullptr,nullptr,1.f);
        gsplit_k<<<(BS_*NQ_*FF_+255)/256,256>>>(h1,h1H,h1L,BS_*NQ_*FF_);
        mgemm<CM_ATOM,3><<<tg(BS_*NQ_,D_,16),256,SMB>>>(
            BS_*NQ_,D_,FF_,16, h1H,h1L,FF_,0, f2h,f2l,FF_,0,
            lat,NB_,NB_,D_,0, nullptr,nullptr,1.f);
    }

    // ---- proj_out (split-K=16) + final LN ----
    split_k<<<(BS_*NQ_*D_+255)/256,256>>>(lat,latH,latL,BS_*NQ_*D_);
    cudaMemsetAsync(hff,0,(size_t)BS_*NQ_*D_*sizeof(float),0);
    mgemm<CM_ATOM,3><<<tg(BS_*NQ_,D_,16),256,SMB>>>(
        BS_*NQ_,D_,D_,16, latH,latL,D_,0, poH,poL,D_,0,
        hff,NB_,NB_,D_,0, pout_b,nullptr,1.f);
    ln_k<true,false><<<BS_*NQ_,256>>>(hff,out,nullptr,nullptr,ng,nb);
}